// round 11
// baseline (speedup 1.0000x reference)
#include <cuda_runtime.h>
#include <math.h>

#define Nn 512
#define CSd 384
#define CZd 128
#define Hh 12
#define Cc 16
#define PQd 4
#define PVd 8
#define OUTD 2112
#define PROJD 1152
#define OQ 0
#define OK0 192
#define OV 384
#define OQP 576
#define OKP 720
#define OVP 864

__device__ float g_proj[Nn * PROJD];
__device__ float g_gv[Nn * Hh * PVd * 3];
__device__ float g_B2[Nn * Hh * 48];
__device__ float g_E[Hh * Nn * 32], g_F[Hh * Nn * 32];
__device__ float g_logits[Nn * Hh * Nn];
__device__ float g_opP[8 * Nn * Hh * CZd];
__device__ float g_ms[Nn * Hh * 8 * 2];
__device__ float g_fct[Nn * 96];
__device__ float g_concat[Nn * OUTD];
__device__ float g_opt[Nn * Hh * PVd * 3];
__device__ float g_wop[4 * Nn * CSd];
__device__ float g_s1[Nn * CSd], g_h1[Nn * CSd], g_h2[Nn * CSd], g_h3[Nn * CSd], g_s2[Nn * CSd];
__device__ float g_rotn[Nn * 9], g_trn[Nn * 3];
__device__ float g_partial[Nn];

#define WLc 0.5773502691896258f
#define WCc 0.23570226039551584f

typedef unsigned long long u64;

__device__ __forceinline__ void cp16(void* smem_dst, const void* gmem_src) {
    unsigned s = (unsigned)__cvta_generic_to_shared(smem_dst);
    asm volatile("cp.async.cg.shared.global [%0], [%1], 16;" :: "r"(s), "l"(gmem_src));
}
__device__ __forceinline__ void cp_commit() { asm volatile("cp.async.commit_group;"); }
template<int N> __device__ __forceinline__ void cp_wait() {
    asm volatile("cp.async.wait_group %0;" :: "n"(N));
}
__device__ __forceinline__ void fma2(u64& d, u64 a, u64 b) {
    asm("fma.rn.f32x2 %0, %1, %2, %3;" : "=l"(d) : "l"(a), "l"(b), "l"(d));
}
__device__ __forceinline__ float2 unpk(u64 v) {
    float2 r; asm("mov.b64 {%0, %1}, %2;" : "=f"(r.x), "=f"(r.y) : "l"(v)); return r;
}
__device__ __forceinline__ u64 pkdup(float v) {
    u64 r; asm("mov.b64 %0, {%1, %1};" : "=l"(r) : "f"(v)); return r;
}

// ---------------- generic double-buffered tiled SGEMM ----------------
template<int BM, int BN, int BK, int TM, int TN, bool BIAS, bool RELU, bool SPLITK>
__global__ void sgemm_k(const float* __restrict__ A, const float* __restrict__ B,
                        const float* __restrict__ bias, float* __restrict__ C,
                        int M, int N, int K, int KC) {
    const int THREADS = (BM / TM) * (BN / TN);
    __shared__ float As[2][BK][BM];
    __shared__ float Bs[2][BK][BN + 4];
    int n0 = blockIdx.x * BN, m0 = blockIdx.y * BM;
    int kstart = SPLITK ? blockIdx.z * KC : 0;
    if (SPLITK) C += (size_t)blockIdx.z * M * N;
    int tid = threadIdx.x;
    int tr = tid / (BN / TN), tc = tid % (BN / TN);
    float acc[TM][TN];
    #pragma unroll
    for (int i = 0; i < TM; i++)
        #pragma unroll
        for (int j = 0; j < TN; j++) acc[i][j] = 0.f;
    int nsteps = KC / BK;

    auto loadA = [&](int kt, int buf) {
        #pragma unroll
        for (int r = tid; r < BM * BK / 4; r += THREADS) {
            int arow = r / (BK / 4), aq = r % (BK / 4);
            float4 v = *(const float4*)&A[(size_t)(m0 + arow) * K + kstart + kt * BK + aq * 4];
            As[buf][aq * 4 + 0][arow] = v.x; As[buf][aq * 4 + 1][arow] = v.y;
            As[buf][aq * 4 + 2][arow] = v.z; As[buf][aq * 4 + 3][arow] = v.w;
        }
    };
    auto loadB = [&](int kt, int buf) {
        #pragma unroll
        for (int r = tid; r < BK * BN / 4; r += THREADS) {
            int brow = r / (BN / 4), bq = r % (BN / 4);
            cp16(&Bs[buf][brow][bq * 4], &B[(size_t)(kstart + kt * BK + brow) * N + n0 + bq * 4]);
        }
    };
    loadA(0, 0); loadB(0, 0); cp_commit();
    for (int kt = 0; kt < nsteps; kt++) {
        int buf = kt & 1;
        if (kt + 1 < nsteps) {
            loadA(kt + 1, buf ^ 1); loadB(kt + 1, buf ^ 1); cp_commit();
            cp_wait<1>();
        } else cp_wait<0>();
        __syncthreads();
        #pragma unroll
        for (int k = 0; k < BK; k++) {
            float ra[TM], rb[TN];
            if constexpr (TM % 4 == 0) {
                #pragma unroll
                for (int i = 0; i < TM; i += 4)
                    *(float4*)&ra[i] = *(const float4*)&As[buf][k][tr * TM + i];
            } else {
                #pragma unroll
                for (int i = 0; i < TM; i++) ra[i] = As[buf][k][tr * TM + i];
            }
            #pragma unroll
            for (int j = 0; j < TN; j += 4)
                *(float4*)&rb[j] = *(const float4*)&Bs[buf][k][tc * TN + j];
            #pragma unroll
            for (int i = 0; i < TM; i++)
                #pragma unroll
                for (int j = 0; j < TN; j++) acc[i][j] += ra[i] * rb[j];
        }
        __syncthreads();
    }
    #pragma unroll
    for (int i = 0; i < TM; i++) {
        int m = m0 + tr * TM + i;
        #pragma unroll
        for (int j = 0; j < TN; j++) {
            int n = n0 + tc * TN + j;
            float v = acc[i][j];
            if (BIAS) v += bias[n];
            if (RELU) v = fmaxf(v, 0.f);
            C[(size_t)m * N + n] = v;
        }
    }
}

// ---------------- projection GEMM with fused 6-way weight gather ----------------
__device__ __forceinline__ const float* wf_ptr(
    const float* Wq, const float* Wk, const float* Wv,
    const float* Wqp, const float* Wkp, const float* Wvp, int kk, int n) {
    if (n < 192) return Wq  + kk * 192 + n;
    if (n < 384) return Wk  + kk * 192 + (n - 192);
    if (n < 576) return Wv  + kk * 192 + (n - 384);
    if (n < 720) return Wqp + kk * 144 + (n - 576);
    if (n < 864) return Wkp + kk * 144 + (n - 720);
    return Wvp + kk * 288 + (n - 864);
}

__global__ void proj_gemm_k(const float* __restrict__ A,
                            const float* __restrict__ Wq, const float* __restrict__ Wk,
                            const float* __restrict__ Wv, const float* __restrict__ Wqp,
                            const float* __restrict__ Wkp, const float* __restrict__ Wvp,
                            float* __restrict__ C) {
    const int BM = 64, BN = 64, BK = 16;
    __shared__ float As[2][BK][BM];
    __shared__ float Bs[2][BK][BN + 4];
    int n0 = blockIdx.x * BN, m0 = blockIdx.y * BM;
    int tid = threadIdx.x;
    int tr = tid / 16, tc = tid % 16;
    float acc[4][4];
    #pragma unroll
    for (int i = 0; i < 4; i++)
        #pragma unroll
        for (int j = 0; j < 4; j++) acc[i][j] = 0.f;
    auto loadA = [&](int kt, int buf) {
        for (int r = tid; r < BM * BK / 4; r += 256) {
            int arow = r / 4, aq = r % 4;
            float4 v = *(const float4*)&A[(size_t)(m0 + arow) * CSd + kt * BK + aq * 4];
            As[buf][aq * 4 + 0][arow] = v.x; As[buf][aq * 4 + 1][arow] = v.y;
            As[buf][aq * 4 + 2][arow] = v.z; As[buf][aq * 4 + 3][arow] = v.w;
        }
    };
    auto loadB = [&](int kt, int buf) {
        for (int r = tid; r < BK * BN / 4; r += 256) {
            int brow = r / 16, bq = r % 16;
            cp16(&Bs[buf][brow][bq * 4],
                 wf_ptr(Wq, Wk, Wv, Wqp, Wkp, Wvp, kt * BK + brow, n0 + bq * 4));
        }
    };
    loadA(0, 0); loadB(0, 0); cp_commit();
    const int nsteps = CSd / BK;
    for (int kt = 0; kt < nsteps; kt++) {
        int buf = kt & 1;
        if (kt + 1 < nsteps) {
            loadA(kt + 1, buf ^ 1); loadB(kt + 1, buf ^ 1); cp_commit();
            cp_wait<1>();
        } else cp_wait<0>();
        __syncthreads();
        #pragma unroll
        for (int k = 0; k < BK; k++) {
            float ra[4], rb[4];
            *(float4*)ra = *(const float4*)&As[buf][k][tr * 4];
            *(float4*)rb = *(const float4*)&Bs[buf][k][tc * 4];
            #pragma unroll
            for (int i = 0; i < 4; i++)
                #pragma unroll
                for (int j = 0; j < 4; j++) acc[i][j] += ra[i] * rb[j];
        }
        __syncthreads();
    }
    #pragma unroll
    for (int i = 0; i < 4; i++)
        #pragma unroll
        for (int j = 0; j < 4; j++)
            C[(size_t)(m0 + tr * 4 + i) * PROJD + n0 + tc * 4 + j] = acc[i][j];
}

// ---------------- prep: frames + E/F + packed B2 ----------------
__global__ void prep_k(const float* __restrict__ rot, const float* __restrict__ trans,
                       const float* __restrict__ gamma_raw) {
    __shared__ float R[9], T[3], gqS[144], gkS[144], sqqS[12], sqkS[12], wcgS[12];
    int n = blockIdx.x, tid = threadIdx.x;
    if (tid < 9) R[tid] = rot[n * 9 + tid];
    if (tid < 3) T[tid] = trans[n * 3 + tid];
    if (tid >= 16 && tid < 28) {
        int h = tid - 16;
        float x = gamma_raw[h];
        wcgS[h] = WCc * ((x > 20.f) ? x : log1pf(expf(x)));
    }
    __syncthreads();
    const float* base = &g_proj[(size_t)n * PROJD];
    for (int t = tid; t < 96; t += 128) {
        int which = t / 48, p = t % 48;
        const float* src = base + (which ? OKP : OQP) + p * 3;
        float b0 = src[0], b1 = src[1], b2 = src[2];
        float* dst = (which ? gkS : gqS) + p * 3;
        #pragma unroll
        for (int a = 0; a < 3; a++)
            dst[a] = R[a * 3 + 0] * b0 + R[a * 3 + 1] * b1 + R[a * 3 + 2] * b2 + T[a];
    }
    for (int t = tid; t < 96; t += 128) {
        int h = t >> 3, p = t & 7;
        const float* src = base + OVP + t * 3;
        float b0 = src[0], b1 = src[1], b2 = src[2];
        #pragma unroll
        for (int a = 0; a < 3; a++) {
            float v = R[a * 3 + 0] * b0 + R[a * 3 + 1] * b1 + R[a * 3 + 2] * b2 + T[a];
            g_gv[n * 288 + t * 3 + a] = v;
            g_B2[n * 576 + h * 48 + 16 + p * 3 + a] = v;
        }
    }
    for (int t = tid; t < 192; t += 128) {
        int h = t >> 4, c = t & 15;
        g_B2[n * 576 + h * 48 + c] = base[OV + t];
    }
    for (int t = tid; t < 96; t += 128) {
        int h = t / 8, c = 40 + (t % 8);
        g_B2[n * 576 + h * 48 + c] = 0.f;
    }
    __syncthreads();
    if (tid < 24) {
        int h = tid >> 1, which = tid & 1;
        const float* g = (which ? gkS : gqS) + h * 12;
        float s = 0.f;
        #pragma unroll
        for (int e = 0; e < 12; e++) s += g[e] * g[e];
        (which ? sqkS : sqqS)[h] = s;
    }
    __syncthreads();
    for (int t = tid; t < Hh * 32; t += 128) {
        int h = t >> 5, c = t & 31;
        float wcg = wcgS[h];
        float e, f;
        if (c < 16)      { e = 0.25f * base[OQ + h * 16 + c]; f = base[OK0 + h * 16 + c]; }
        else if (c < 28) { e = wcg * gqS[h * 12 + c - 16];    f = gkS[h * 12 + c - 16]; }
        else if (c == 28){ e = sqqS[h];                        f = -0.5f * wcg; }
        else if (c == 29){ e = 1.f;                            f = -0.5f * wcg * sqkS[h]; }
        else             { e = 0.f;                            f = 0.f; }
        g_E[(size_t)((h << 9) | n) * 32 + c] = e;
        g_F[(size_t)((h << 9) | n) * 32 + c] = f;
    }
}

// ---------------- logit core: 64i x 128j tile, acc 4x8 ----------------
__global__ void core_k() {
    __shared__ float As[32][64], BsT[32][128];
    int h = blockIdx.z, i0 = blockIdx.y * 64, j0 = blockIdx.x * 128;
    int tid = threadIdx.x;
    const float* Eh = &g_E[((size_t)h * Nn + i0) * 32];
    const float* Fh = &g_F[((size_t)h * Nn + j0) * 32];
    for (int t = tid; t < 512; t += 256) {
        int row = t >> 3, d4 = t & 7;
        float4 v = *(const float4*)&Eh[row * 32 + d4 * 4];
        As[d4 * 4 + 0][row] = v.x; As[d4 * 4 + 1][row] = v.y;
        As[d4 * 4 + 2][row] = v.z; As[d4 * 4 + 3][row] = v.w;
    }
    for (int t = tid; t < 1024; t += 256) {
        int row = t >> 3, d4 = t & 7;
        float4 w = *(const float4*)&Fh[row * 32 + d4 * 4];
        BsT[d4 * 4 + 0][row] = w.x; BsT[d4 * 4 + 1][row] = w.y;
        BsT[d4 * 4 + 2][row] = w.z; BsT[d4 * 4 + 3][row] = w.w;
    }
    __syncthreads();
    int tr = tid >> 4, tc = tid & 15;
    float acc[4][8];
    #pragma unroll
    for (int i = 0; i < 4; i++)
        #pragma unroll
        for (int j = 0; j < 8; j++) acc[i][j] = 0.f;
    #pragma unroll
    for (int d = 0; d < 32; d++) {
        float ra[4], rb[8];
        *(float4*)ra = *(const float4*)&As[d][tr * 4];
        *(float4*)&rb[0] = *(const float4*)&BsT[d][tc * 8];
        *(float4*)&rb[4] = *(const float4*)&BsT[d][tc * 8 + 4];
        #pragma unroll
        for (int i = 0; i < 4; i++)
            #pragma unroll
            for (int j = 0; j < 8; j++) acc[i][j] += ra[i] * rb[j];
    }
    #pragma unroll
    for (int i = 0; i < 4; i++) {
        size_t rowb = ((size_t)(i0 + tr * 4 + i) * Hh + h) * Nn + j0 + tc * 8;
        float4 v0 = make_float4(WLc * acc[i][0], WLc * acc[i][1], WLc * acc[i][2], WLc * acc[i][3]);
        float4 v1 = make_float4(WLc * acc[i][4], WLc * acc[i][5], WLc * acc[i][6], WLc * acc[i][7]);
        *(float4*)&g_logits[rowb] = v0;
        *(float4*)&g_logits[rowb + 4] = v1;
    }
}

// ---------------- FLASH2: packed f32x2 bias + softmax + packed o_pair ----------------
// grid (Nn, 8), 256 thr. smem: pairS[64*132] WbT[12*132] lS[12*64] comb[4*32*25]
__global__ void __launch_bounds__(256, 4) flash2_k(const float* __restrict__ pair,
                                                   const float* __restrict__ Wb) {
    extern __shared__ float sm[];
    float* pairS = sm;                  // 8448
    float* WbT   = pairS + 8448;        // 1584
    float* lS    = WbT + 1584;          // 768
    float* comb  = lS + 768;            // 3200
    int i = blockIdx.x, js = blockIdx.y, j0 = js << 6;
    int tid = threadIdx.x;
    int w = tid >> 5, lane = tid & 31;

    for (int r = tid; r < 64 * 32; r += 256) {
        int row = r >> 5, q = r & 31;
        cp16(&pairS[row * 132 + q * 4], &pair[((size_t)i * Nn + j0 + row) * CZd + q * 4]);
    }
    cp_commit();
    for (int t = tid; t < CZd * Hh; t += 256) WbT[(t % Hh) * 132 + (t / Hh)] = Wb[t];
    if (tid < 192) {
        int h = tid >> 4, q = tid & 15;
        *(float4*)&lS[h * 64 + q * 4] =
            *(const float4*)&g_logits[((size_t)i * Hh + h) * Nn + j0 + q * 4];
    }

    // ---- bias: warp w = z-group (16 z), lane = j (2 j), packed f32x2 accumulators ----
    u64 acc0[12], acc1[12];
    #pragma unroll
    for (int h = 0; h < 12; h++) { acc0[h] = 0ull; acc1[h] = 0ull; }

    cp_wait<0>();
    __syncthreads();
    {
        const ulonglong2* ap0 = (const ulonglong2*)&pairS[lane * 132 + w * 16];
        const ulonglong2* ap1 = (const ulonglong2*)&pairS[(lane + 32) * 132 + w * 16];
        #pragma unroll
        for (int z4 = 0; z4 < 4; z4++) {
            ulonglong2 p0 = ap0[z4], p1 = ap1[z4];
            #pragma unroll
            for (int h = 0; h < 12; h++) {
                ulonglong2 wv = *(const ulonglong2*)&WbT[h * 132 + w * 16 + z4 * 4];
                fma2(acc0[h], p0.x, wv.x); fma2(acc0[h], p0.y, wv.y);
                fma2(acc1[h], p1.x, wv.x); fma2(acc1[h], p1.y, wv.y);
            }
        }
    }
    float a0f[12], a1f[12];
    #pragma unroll
    for (int h = 0; h < 12; h++) {
        float2 t0 = unpk(acc0[h]); a0f[h] = t0.x + t0.y;
        float2 t1 = unpk(acc1[h]); a1f[h] = t1.x + t1.y;
    }
    // two-round tree reduction over 8 z-groups (comb rows padded to 25)
    if (w >= 4) {
        float* c = &comb[((w - 4) * 32 + lane) * 25];
        #pragma unroll
        for (int h = 0; h < 12; h++) { c[h] = a0f[h]; c[12 + h] = a1f[h]; }
    }
    __syncthreads();
    if (w < 4) {
        const float* c = &comb[(w * 32 + lane) * 25];
        #pragma unroll
        for (int h = 0; h < 12; h++) { a0f[h] += c[h]; a1f[h] += c[12 + h]; }
    }
    __syncthreads();
    if (w >= 1 && w < 4) {
        float* c = &comb[((w - 1) * 32 + lane) * 25];
        #pragma unroll
        for (int h = 0; h < 12; h++) { c[h] = a0f[h]; c[12 + h] = a1f[h]; }
    }
    __syncthreads();
    if (w == 0) {
        #pragma unroll
        for (int h = 0; h < 12; h++) {
            float s0 = a0f[h], s1 = a1f[h];
            #pragma unroll
            for (int g = 0; g < 3; g++) {
                const float* c = &comb[(g * 32 + lane) * 25];
                s0 += c[h]; s1 += c[12 + h];
            }
            lS[h * 64 + lane] += WLc * s0;
            lS[h * 64 + 32 + lane] += WLc * s1;
        }
    }
    __syncthreads();

    // ---- local softmax: warp w -> head w; warps 0..3 also head 8+w ----
    #pragma unroll
    for (int rep = 0; rep < 2; rep++) {
        int h = w + rep * 8;
        if (h < Hh) {
            float l0 = lS[h * 64 + lane], l1 = lS[h * 64 + 32 + lane];
            float m = fmaxf(l0, l1);
            #pragma unroll
            for (int off = 16; off; off >>= 1) m = fmaxf(m, __shfl_xor_sync(0xffffffffu, m, off));
            float e0 = __expf(l0 - m), e1 = __expf(l1 - m);
            float s = e0 + e1;
            #pragma unroll
            for (int off = 16; off; off >>= 1) s += __shfl_xor_sync(0xffffffffu, s, off);
            lS[h * 64 + lane] = e0;
            lS[h * 64 + 32 + lane] = e1;
            if (lane == 0) {
                int msb = (((i * Hh) + h) * 8 + js) * 2;
                g_ms[msb] = m;
                g_ms[msb + 1] = s;
            }
        }
    }
    __syncthreads();

    // vectorized e writeback for ov_k
    if (tid < 192) {
        int h = tid >> 4, q = tid & 15;
        *(float4*)&g_logits[((size_t)i * Hh + h) * Nn + j0 + q * 4] =
            *(const float4*)&lS[h * 64 + q * 4];
    }

    // ---- o_pair: jh halves of 32 j; thread = (ht 3h) x (zz 4z), packed over z ----
    int jh = tid >> 7, rem = tid & 127, ht = rem >> 5, zz = rem & 31;
    u64 a3[3][2];
    #pragma unroll
    for (int b = 0; b < 3; b++) { a3[b][0] = 0ull; a3[b][1] = 0ull; }
    const float* E0 = &lS[(ht * 3 + 0) * 64 + jh * 32];
    const float* E1 = &lS[(ht * 3 + 1) * 64 + jh * 32];
    const float* E2 = &lS[(ht * 3 + 2) * 64 + jh * 32];
    const float* pb = &pairS[jh * 32 * 132];
    #pragma unroll 8
    for (int j = 0; j < 32; j++) {
        ulonglong2 p = *(const ulonglong2*)&pb[j * 132 + zz * 4];
        u64 v0 = pkdup(E0[j]), v1 = pkdup(E1[j]), v2 = pkdup(E2[j]);
        fma2(a3[0][0], v0, p.x); fma2(a3[0][1], v0, p.y);
        fma2(a3[1][0], v1, p.x); fma2(a3[1][1], v1, p.y);
        fma2(a3[2][0], v2, p.x); fma2(a3[2][1], v2, p.y);
    }
    float af[3][4];
    #pragma unroll
    for (int b = 0; b < 3; b++) {
        float2 x0 = unpk(a3[b][0]), x1 = unpk(a3[b][1]);
        af[b][0] = x0.x; af[b][1] = x0.y; af[b][2] = x1.x; af[b][3] = x1.y;
    }
    if (jh == 1) {
        float* c = &comb[rem * 13];
        #pragma unroll
        for (int b = 0; b < 3; b++)
            #pragma unroll
            for (int a = 0; a < 4; a++) c[b * 4 + a] = af[b][a];
    }
    __syncthreads();
    if (jh == 0) {
        const float* c = &comb[rem * 13];
        float* dst = &g_opP[((size_t)js * Nn + i) * (Hh * CZd)];
        #pragma unroll
        for (int b = 0; b < 3; b++) {
            float4 v;
            v.x = af[b][0] + c[b * 4 + 0];
            v.y = af[b][1] + c[b * 4 + 1];
            v.z = af[b][2] + c[b * 4 + 2];
            v.w = af[b][3] + c[b * 4 + 3];
            *(float4*)&dst[(ht * 3 + b) * CZd + zz * 4] = v;
        }
    }
}

// ---------------- combine: global stats + o_pair; factors -> g_fct ----------------
__global__ void combine_k() {
    __shared__ float fctS[96];
    int i = blockIdx.x, tid = threadIdx.x;
    if (tid < 96) {
        int h = tid >> 3, js = tid & 7;
        float mv[8], sv[8];
        float mg = -1e30f;
        #pragma unroll
        for (int k = 0; k < 8; k++) {
            int b = ((i * Hh + h) * 8 + k) * 2;
            mv[k] = g_ms[b]; sv[k] = g_ms[b + 1];
            mg = fmaxf(mg, mv[k]);
        }
        float sg = 0.f;
        #pragma unroll
        for (int k = 0; k < 8; k++) sg += sv[k] * __expf(mv[k] - mg);
        float f = __expf(mv[js] - mg) / sg;
        fctS[tid] = f;
        g_fct[i * 96 + tid] = f;
    }
    __syncthreads();
    const size_t S = (size_t)Nn * Hh * CZd;
    for (int c = tid; c < Hh * CZd; c += 256) {
        int h = c >> 7;
        float s = 0.f;
        #pragma unroll
        for (int js = 0; js < 8; js++)
            s += fctS[h * 8 + js] * g_opP[js * S + (size_t)i * (Hh * CZd) + c];
        g_concat[(size_t)i * OUTD + 576 + c] = s;
    }
}

// ---------------- o_v & o_pt: unnormalized e x per-chunk factor ----------------
__global__ void ov_k() {
    __shared__ float As[2][32 * 36];
    __shared__ float Bs[2][32 * 48];
    __shared__ float fS[32 * 8];
    int i0 = blockIdx.x * 32, h = blockIdx.y;
    int tid = threadIdx.x;
    int tr = tid / 16, tc = tid % 16;
    if (tid < 256) {
        int row = tid >> 3, js = tid & 7;
        fS[row * 8 + js] = g_fct[(i0 + row) * 96 + h * 8 + js];
    }
    float acc[2][3];
    #pragma unroll
    for (int a = 0; a < 2; a++)
        #pragma unroll
        for (int b = 0; b < 3; b++) acc[a][b] = 0.f;

    auto loadA = [&](int chunk, int buf) {
        int j0 = chunk * 32;
        int row = tid >> 3, q = tid & 7;
        cp16(&As[buf][row * 36 + q * 4],
             &g_logits[((size_t)(i0 + row) * Hh + h) * Nn + j0 + q * 4]);
    };
    auto loadB = [&](int chunk, int buf) {
        int j0 = chunk * 32;
        for (int t = tid; t < 384; t += 256) {
            int row = t / 12, q = t % 12;
            cp16(&Bs[buf][row * 48 + q * 4], &g_B2[(size_t)(j0 + row) * 576 + h * 48 + q * 4]);
        }
    };
    loadA(0, 0); loadB(0, 0); cp_commit();
    for (int chunk = 0; chunk < 16; chunk++) {
        int buf = chunk & 1;
        if (chunk + 1 < 16) {
            loadA(chunk + 1, buf ^ 1); loadB(chunk + 1, buf ^ 1); cp_commit();
            cp_wait<1>();
        } else cp_wait<0>();
        __syncthreads();
        float pacc[2][3];
        #pragma unroll
        for (int a = 0; a < 2; a++)
            #pragma unroll
            for (int b = 0; b < 3; b++) pacc[a][b] = 0.f;
        #pragma unroll 8
        for (int jl = 0; jl < 32; jl++) {
            float ra[2], rb[3];
            #pragma unroll
            for (int a = 0; a < 2; a++) ra[a] = As[buf][(tr * 2 + a) * 36 + jl];
            #pragma unroll
            for (int b = 0; b < 3; b++) rb[b] = Bs[buf][jl * 48 + tc * 3 + b];
            #pragma unroll
            for (int a = 0; a < 2; a++)
                #pragma unroll
                for (int b = 0; b < 3; b++) pacc[a][b] += ra[a] * rb[b];
        }
        int js = chunk >> 1;
        #pragma unroll
        for (int a = 0; a < 2; a++) {
            float f = fS[(tr * 2 + a) * 8 + js];
            #pragma unroll
            for (int b = 0; b < 3; b++) acc[a][b] += f * pacc[a][b];
        }
        __syncthreads();
    }
    #pragma unroll
    for (int a = 0; a < 2; a++) {
        int i = i0 + tr * 2 + a;
        #pragma unroll
        for (int b = 0; b < 3; b++) {
            int c = tc * 3 + b;
            if (c < 16)      g_concat[(size_t)i * OUTD + h * Cc + c] = acc[a][b];
            else if (c < 40) g_opt[i * (Hh * 24) + h * 24 + (c - 16)] = acc[a][b];
        }
    }
}

__global__ void post_pt_k(const float* __restrict__ rot, const float* __restrict__ trans) {
    int idx = blockIdx.x * blockDim.x + threadIdx.x;
    if (idx >= Nn * Hh * PVd) return;
    int i = idx / (Hh * PVd), t = idx % (Hh * PVd);
    float b0 = g_opt[i * (Hh * 24) + t * 3 + 0] - trans[i * 3 + 0];
    float b1 = g_opt[i * (Hh * 24) + t * 3 + 1] - trans[i * 3 + 1];
    float b2 = g_opt[i * (Hh * 24) + t * 3 + 2] - trans[i * 3 + 2];
    float l0 = rot[i * 9 + 0] * b0 + rot[i * 9 + 3] * b1 + rot[i * 9 + 6] * b2;
    float l1 = rot[i * 9 + 1] * b0 + rot[i * 9 + 4] * b1 + rot[i * 9 + 7] * b2;
    float l2 = rot[i * 9 + 2] * b0 + rot[i * 9 + 5] * b1 + rot[i * 9 + 8] * b2;
    float* crow = &g_concat[(size_t)i * OUTD];
    crow[192 + t * 3 + 0] = l0;
    crow[192 + t * 3 + 1] = l1;
    crow[192 + t * 3 + 2] = l2;
    crow[480 + t] = sqrtf(l0 * l0 + l1 * l1 + l2 * l2 + 1e-8f);
}

// ---------------- layer norms ----------------
__device__ __forceinline__ float blockSum384(float v, float* red) {
    int tid = threadIdx.x;
    red[tid] = v;
    if (tid < 128) red[384 + tid] = 0.f;
    __syncthreads();
    for (int s = 256; s > 0; s >>= 1) {
        if (tid < s) red[tid] += red[tid + s];
        __syncthreads();
    }
    float r = red[0];
    __syncthreads();
    return r;
}

__global__ void ln1_k(const float* __restrict__ single_in, const float* __restrict__ bo,
                      const float* __restrict__ g, const float* __restrict__ b) {
    __shared__ float red[512];
    int row = blockIdx.x, tid = threadIdx.x;
    float x = single_in[row * CSd + tid] + bo[tid];
    #pragma unroll
    for (int z = 0; z < 4; z++) x += g_wop[(size_t)z * Nn * CSd + row * CSd + tid];
    float mean = blockSum384(x, red) * (1.f / CSd);
    float dx = x - mean;
    float var = blockSum384(dx * dx, red) * (1.f / CSd);
    g_s1[row * CSd + tid] = dx * rsqrtf(var + 1e-5f) * g[tid] + b[tid];
}

__global__ void ln2_k(const float* __restrict__ g, const float* __restrict__ b,
                      float* __restrict__ out) {
    __shared__ float red[512];
    int row = blockIdx.x, tid = threadIdx.x;
    float x = g_s1[row * CSd + tid] + g_h3[row * CSd + tid];
    float mean = blockSum384(x, red) * (1.f / CSd);
    float dx = x - mean;
    float var = blockSum384(dx * dx, red) * (1.f / CSd);
    float y = dx * rsqrtf(var + 1e-5f) * g[tid] + b[tid];
    out[row * CSd + tid] = y;
    g_s2[row * CSd + tid] = y;
}

// ---------------- backbone update ----------------
__global__ void update_k(const float* __restrict__ rot, const float* __restrict__ trans,
                         const float* __restrict__ Wbu, const float* __restrict__ bbu,
                         float* __restrict__ out) {
    int gtid = blockIdx.x * blockDim.x + threadIdx.x;
    int n = gtid >> 5, lane = gtid & 31;
    if (n >= Nn) return;
    float u[6] = {0, 0, 0, 0, 0, 0};
    for (int s = lane; s < CSd; s += 32) {
        float x = g_s2[n * CSd + s];
        #pragma unroll
        for (int j = 0; j < 6; j++) u[j] += x * Wbu[s * 6 + j];
    }
    #pragma unroll
    for (int j = 0; j < 6; j++)
        #pragma unroll
        for (int off = 16; off; off >>= 1) u[j] += __shfl_xor_sync(0xffffffffu, u[j], off);
    if (lane != 0) return;
    #pragma unroll
    for (int j = 0; j < 6; j++) u[j] += bbu[j];
    float b = u[0], c = u[1], d = u[2];
    float inq = rsqrtf(1.f + b * b + c * c + d * d);
    float a = inq; b *= inq; c *= inq; d *= inq;
    float R[9] = {
        a*a + b*b - c*c - d*d, 2.f*(b*c - a*d),       2.f*(b*d + a*c),
        2.f*(b*c + a*d),       a*a - b*b + c*c - d*d, 2.f*(c*d - a*b),
        2.f*(b*d - a*c),       2.f*(c*d + a*b),       a*a - b*b - c*c + d*d };
    float rn[9];
    #pragma unroll
    for (int aa = 0; aa < 3; aa++)
        #pragma unroll
        for (int cc = 0; cc < 3; cc++) {
            float s2 = 0.f;
            #pragma unroll
            for (int bx = 0; bx < 3; bx++) s2 += rot[n * 9 + aa * 3 + bx] * R[bx * 3 + cc];
            rn[aa * 3 + cc] = s2;
        }
    float t0 = u[3], t1 = u[4], t2 = u[5];
    float tn[3];
    #pragma unroll
    for (int aa = 0; aa < 3; aa++)
        tn[aa] = rot[n * 9 + aa * 3 + 0] * t0 + rot[n * 9 + aa * 3 + 1] * t1 +
                 rot[n * 9 + aa * 3 + 2] * t2 + trans[n * 3 + aa];
    #pragma unroll
    for (int e = 0; e < 9; e++) { g_rotn[n * 9 + e] = rn[e]; out[Nn * CSd + n * 9 + e] = rn[e]; }
    #pragma unroll
    for (int e = 0; e < 3; e++) { g_trn[n * 3 + e] = tn[e]; out[Nn * CSd + Nn * 9 + n * 3 + e] = tn[e]; }
}

// ---------------- loss ----------------
__global__ void loss_part_k(const float* __restrict__ rt, const float* __restrict__ tt) {
    int i = blockIdx.x, tid = threadIdx.x;
    __shared__ float red[256];
    float rn[9], rte[9], tni[3], tti[3];
    #pragma unroll
    for (int e = 0; e < 9; e++) { rn[e] = g_rotn[i * 9 + e]; rte[e] = rt[i * 9 + e]; }
    #pragma unroll
    for (int e = 0; e < 3; e++) { tni[e] = g_trn[i * 3 + e]; tti[e] = tt[i * 3 + e]; }
    float s = 0.f;
    for (int j = tid; j < Nn; j += 256) {
        float db0 = g_trn[j * 3 + 0] - tni[0];
        float db1 = g_trn[j * 3 + 1] - tni[1];
        float db2 = g_trn[j * 3 + 2] - tni[2];
        float dp0 = rn[0] * db0 + rn[3] * db1 + rn[6] * db2;
        float dp1 = rn[1] * db0 + rn[4] * db1 + rn[7] * db2;
        float dp2 = rn[2] * db0 + rn[5] * db1 + rn[8] * db2;
        float eb0 = tt[j * 3 + 0] - tti[0];
        float eb1 = tt[j * 3 + 1] - tti[1];
        float eb2 = tt[j * 3 + 2] - tti[2];
        float dt0 = rte[0] * eb0 + rte[3] * eb1 + rte[6] * eb2;
        float dt1 = rte[1] * eb0 + rte[4] * eb1 + rte[7] * eb2;
        float dt2 = rte[2] * eb0 + rte[5] * eb1 + rte[8] * eb2;
        float d0 = dp0 - dt0, d1 = dp1 - dt1, d2 = dp2 - dt2;
        float dd = sqrtf(d0 * d0 + d1 * d1 + d2 * d2 + 1e-12f);
        s += fminf(dd, 10.f);
    }
    red[tid] = s; __syncthreads();
    for (int st = 128; st > 0; st >>= 1) {
        if (tid < st) red[tid] += red[tid + st];
        __syncthreads();
    }
    if (tid == 0) g_partial[i] = red[0];
}

__global__ void loss_final_k(float* __restrict__ out) {
    __shared__ float red[512];
    int tid = threadIdx.x;
    red[tid] = g_partial[tid];
    __syncthreads();
    for (int s = 256; s > 0; s >>= 1) {
        if (tid < s) red[tid] += red[tid + s];
        __syncthreads();
    }
    if (tid == 0)
        out[Nn * CSd + Nn * 9 + Nn * 3] = red[0] / ((float)Nn * (float)Nn) * 0.1f;
}

// ---------------- host ----------------
template <typename T>
static float* symaddr(T& sym) {
    void* p = nullptr;
    cudaGetSymbolAddress(&p, sym);
    return (float*)p;
}

extern "C" void kernel_launch(void* const* d_in, const int* in_sizes, int n_in,
                              void* d_out, int out_size) {
    const float* single      = (const float*)d_in[0];
    const float* pair        = (const float*)d_in[1];
    const float* rot         = (const float*)d_in[2];
    const float* trans       = (const float*)d_in[3];
    const float* rot_truth   = (const float*)d_in[4];
    const float* trans_truth = (const float*)d_in[5];
    const float* Wq  = (const float*)d_in[6];
    const float* Wk  = (const float*)d_in[7];
    const float* Wv  = (const float*)d_in[8];
    const float* Wqp = (const float*)d_in[9];
    const float* Wkp = (const float*)d_in[10];
    const float* Wvp = (const float*)d_in[11];
    const float* Wb  = (const float*)d_in[12];
    const float* Wo  = (const float*)d_in[13];
    const float* bo  = (const float*)d_in[14];
    const float* gamma_raw = (const float*)d_in[15];
    const float* ln1_g = (const float*)d_in[16];
    const float* ln1_b = (const float*)d_in[17];
    const float* ln2_g = (const float*)d_in[18];
    const float* ln2_b = (const float*)d_in[19];
    const float* W1 = (const float*)d_in[20];
    const float* b1 = (const float*)d_in[21];
    const float* W2 = (const float*)d_in[22];
    const float* b2 = (const float*)d_in[23];
    const float* W3 = (const float*)d_in[24];
    const float* b3 = (const float*)d_in[25];
    const float* Wbu = (const float*)d_in[26];
    const float* bbu = (const float*)d_in[27];
    float* out = (float*)d_out;

    float* pProj   = symaddr(g_proj);
    float* pConcat = symaddr(g_concat);
    float* pS1     = symaddr(g_s1);
    float* pH1     = symaddr(g_h1);
    float* pH2     = symaddr(g_h2);
    float* pH3     = symaddr(g_h3);

    const int FLASH2_SMEM = (8448 + 1584 + 768 + 3200) * 4;   // 56000
    cudaFuncSetAttribute(flash2_k, cudaFuncAttributeMaxDynamicSharedMemorySize, FLASH2_SMEM);

    proj_gemm_k<<<dim3(PROJD/64, Nn/64), 256>>>(single, Wq, Wk, Wv, Wqp, Wkp, Wvp, pProj);
    prep_k<<<Nn, 128>>>(rot, trans, gamma_raw);
    core_k<<<dim3(Nn/128, Nn/64, Hh), 256>>>();

    flash2_k<<<dim3(Nn, 8), 256, FLASH2_SMEM>>>(pair, Wb);   // profiler slot 4
    combine_k<<<Nn, 256>>>();
    ov_k<<<dim3(Nn/32, Hh), 256>>>();
    post_pt_k<<<(Nn * Hh * PVd + 255) / 256, 256>>>(rot, trans);

    sgemm_k<64,64,16,4,4,false,false,true><<<dim3(CSd/64, Nn/64, 4), 256>>>(
        pConcat, Wo, nullptr, symaddr(g_wop), Nn, CSd, OUTD, OUTD/4);
    ln1_k<<<Nn, CSd>>>(single, bo, ln1_g, ln1_b);

    sgemm_k<32,64,16,2,4,true,true,false><<<dim3(CSd/64, Nn/32, 1), 256>>>(
        pS1, W1, b1, pH1, Nn, CSd, CSd, CSd);
    sgemm_k<32,64,16,2,4,true,true,false><<<dim3(CSd/64, Nn/32, 1), 256>>>(
        pH1, W2, b2, pH2, Nn, CSd, CSd, CSd);
    sgemm_k<32,64,16,2,4,true,false,false><<<dim3(CSd/64, Nn/32, 1), 256>>>(
        pH2, W3, b3, pH3, Nn, CSd, CSd, CSd);
    ln2_k<<<Nn, CSd>>>(ln2_g, ln2_b, out);

    update_k<<<(Nn * 32 + 127) / 128, 128>>>(rot, trans, Wbu, bbu, out);
    loss_part_k<<<Nn, 256>>>(rot_truth, trans_truth);
    loss_final_k<<<1, 512>>>(out);
}

// round 12
// speedup vs baseline: 1.0070x; 1.0070x over previous
#include <cuda_runtime.h>
#include <math.h>

#define Nn 512
#define CSd 384
#define CZd 128
#define Hh 12
#define Cc 16
#define PQd 4
#define PVd 8
#define OUTD 2112
#define PROJD 1152
#define OQ 0
#define OK0 192
#define OV 384
#define OQP 576
#define OKP 720
#define OVP 864

__device__ float g_proj[Nn * PROJD];
__device__ float g_gv[Nn * Hh * PVd * 3];
__device__ float g_B2[Nn * Hh * 48];
__device__ float g_E[Hh * Nn * 32], g_F[Hh * Nn * 32];
__device__ float g_logits[Nn * Hh * Nn];
__device__ float g_opP[8 * Nn * Hh * CZd];
__device__ float g_ovP[4 * Nn * Hh * 48];
__device__ float g_ms[Nn * Hh * 8 * 2];
__device__ float g_fct[Nn * 96];
__device__ float g_concat[Nn * OUTD];
__device__ float g_opt[Nn * Hh * PVd * 3];
__device__ float g_wop[4 * Nn * CSd];
__device__ float g_s1[Nn * CSd], g_h1[Nn * CSd], g_h2[Nn * CSd], g_h3[Nn * CSd], g_s2[Nn * CSd];
__device__ float g_rotn[Nn * 9], g_trn[Nn * 3];
__device__ float g_partial[Nn];

#define WLc 0.5773502691896258f
#define WCc 0.23570226039551584f

__device__ __forceinline__ void cp16(void* smem_dst, const void* gmem_src) {
    unsigned s = (unsigned)__cvta_generic_to_shared(smem_dst);
    asm volatile("cp.async.cg.shared.global [%0], [%1], 16;" :: "r"(s), "l"(gmem_src));
}
__device__ __forceinline__ void cp_commit() { asm volatile("cp.async.commit_group;"); }
template<int N> __device__ __forceinline__ void cp_wait() {
    asm volatile("cp.async.wait_group %0;" :: "n"(N));
}

// ---------------- generic double-buffered tiled SGEMM ----------------
template<int BM, int BN, int BK, int TM, int TN, bool BIAS, bool RELU, bool SPLITK>
__global__ void sgemm_k(const float* __restrict__ A, const float* __restrict__ B,
                        const float* __restrict__ bias, float* __restrict__ C,
                        int M, int N, int K, int KC) {
    const int THREADS = (BM / TM) * (BN / TN);
    __shared__ float As[2][BK][BM];
    __shared__ float Bs[2][BK][BN + 4];
    int n0 = blockIdx.x * BN, m0 = blockIdx.y * BM;
    int kstart = SPLITK ? blockIdx.z * KC : 0;
    if (SPLITK) C += (size_t)blockIdx.z * M * N;
    int tid = threadIdx.x;
    int tr = tid / (BN / TN), tc = tid % (BN / TN);
    float acc[TM][TN];
    #pragma unroll
    for (int i = 0; i < TM; i++)
        #pragma unroll
        for (int j = 0; j < TN; j++) acc[i][j] = 0.f;
    int nsteps = KC / BK;

    auto loadA = [&](int kt, int buf) {
        #pragma unroll
        for (int r = tid; r < BM * BK / 4; r += THREADS) {
            int arow = r / (BK / 4), aq = r % (BK / 4);
            float4 v = *(const float4*)&A[(size_t)(m0 + arow) * K + kstart + kt * BK + aq * 4];
            As[buf][aq * 4 + 0][arow] = v.x; As[buf][aq * 4 + 1][arow] = v.y;
            As[buf][aq * 4 + 2][arow] = v.z; As[buf][aq * 4 + 3][arow] = v.w;
        }
    };
    auto loadB = [&](int kt, int buf) {
        #pragma unroll
        for (int r = tid; r < BK * BN / 4; r += THREADS) {
            int brow = r / (BN / 4), bq = r % (BN / 4);
            cp16(&Bs[buf][brow][bq * 4], &B[(size_t)(kstart + kt * BK + brow) * N + n0 + bq * 4]);
        }
    };
    loadA(0, 0); loadB(0, 0); cp_commit();
    for (int kt = 0; kt < nsteps; kt++) {
        int buf = kt & 1;
        if (kt + 1 < nsteps) {
            loadA(kt + 1, buf ^ 1); loadB(kt + 1, buf ^ 1); cp_commit();
            cp_wait<1>();
        } else cp_wait<0>();
        __syncthreads();
        #pragma unroll
        for (int k = 0; k < BK; k++) {
            float ra[TM], rb[TN];
            if constexpr (TM % 4 == 0) {
                #pragma unroll
                for (int i = 0; i < TM; i += 4)
                    *(float4*)&ra[i] = *(const float4*)&As[buf][k][tr * TM + i];
            } else {
                #pragma unroll
                for (int i = 0; i < TM; i++) ra[i] = As[buf][k][tr * TM + i];
            }
            #pragma unroll
            for (int j = 0; j < TN; j += 4)
                *(float4*)&rb[j] = *(const float4*)&Bs[buf][k][tc * TN + j];
            #pragma unroll
            for (int i = 0; i < TM; i++)
                #pragma unroll
                for (int j = 0; j < TN; j++) acc[i][j] += ra[i] * rb[j];
        }
        __syncthreads();
    }
    #pragma unroll
    for (int i = 0; i < TM; i++) {
        int m = m0 + tr * TM + i;
        #pragma unroll
        for (int j = 0; j < TN; j++) {
            int n = n0 + tc * TN + j;
            float v = acc[i][j];
            if (BIAS) v += bias[n];
            if (RELU) v = fmaxf(v, 0.f);
            C[(size_t)m * N + n] = v;
        }
    }
}

// ---------------- projection GEMM with fused 6-way weight gather ----------------
__device__ __forceinline__ const float* wf_ptr(
    const float* Wq, const float* Wk, const float* Wv,
    const float* Wqp, const float* Wkp, const float* Wvp, int kk, int n) {
    if (n < 192) return Wq  + kk * 192 + n;
    if (n < 384) return Wk  + kk * 192 + (n - 192);
    if (n < 576) return Wv  + kk * 192 + (n - 384);
    if (n < 720) return Wqp + kk * 144 + (n - 576);
    if (n < 864) return Wkp + kk * 144 + (n - 720);
    return Wvp + kk * 288 + (n - 864);
}

__global__ void proj_gemm_k(const float* __restrict__ A,
                            const float* __restrict__ Wq, const float* __restrict__ Wk,
                            const float* __restrict__ Wv, const float* __restrict__ Wqp,
                            const float* __restrict__ Wkp, const float* __restrict__ Wvp,
                            float* __restrict__ C) {
    const int BM = 64, BN = 64, BK = 16;
    __shared__ float As[2][BK][BM];
    __shared__ float Bs[2][BK][BN + 4];
    int n0 = blockIdx.x * BN, m0 = blockIdx.y * BM;
    int tid = threadIdx.x;
    int tr = tid / 16, tc = tid % 16;
    float acc[4][4];
    #pragma unroll
    for (int i = 0; i < 4; i++)
        #pragma unroll
        for (int j = 0; j < 4; j++) acc[i][j] = 0.f;
    auto loadA = [&](int kt, int buf) {
        for (int r = tid; r < BM * BK / 4; r += 256) {
            int arow = r / 4, aq = r % 4;
            float4 v = *(const float4*)&A[(size_t)(m0 + arow) * CSd + kt * BK + aq * 4];
            As[buf][aq * 4 + 0][arow] = v.x; As[buf][aq * 4 + 1][arow] = v.y;
            As[buf][aq * 4 + 2][arow] = v.z; As[buf][aq * 4 + 3][arow] = v.w;
        }
    };
    auto loadB = [&](int kt, int buf) {
        for (int r = tid; r < BK * BN / 4; r += 256) {
            int brow = r / 16, bq = r % 16;
            cp16(&Bs[buf][brow][bq * 4],
                 wf_ptr(Wq, Wk, Wv, Wqp, Wkp, Wvp, kt * BK + brow, n0 + bq * 4));
        }
    };
    loadA(0, 0); loadB(0, 0); cp_commit();
    const int nsteps = CSd / BK;
    for (int kt = 0; kt < nsteps; kt++) {
        int buf = kt & 1;
        if (kt + 1 < nsteps) {
            loadA(kt + 1, buf ^ 1); loadB(kt + 1, buf ^ 1); cp_commit();
            cp_wait<1>();
        } else cp_wait<0>();
        __syncthreads();
        #pragma unroll
        for (int k = 0; k < BK; k++) {
            float ra[4], rb[4];
            *(float4*)ra = *(const float4*)&As[buf][k][tr * 4];
            *(float4*)rb = *(const float4*)&Bs[buf][k][tc * 4];
            #pragma unroll
            for (int i = 0; i < 4; i++)
                #pragma unroll
                for (int j = 0; j < 4; j++) acc[i][j] += ra[i] * rb[j];
        }
        __syncthreads();
    }
    #pragma unroll
    for (int i = 0; i < 4; i++)
        #pragma unroll
        for (int j = 0; j < 4; j++)
            C[(size_t)(m0 + tr * 4 + i) * PROJD + n0 + tc * 4 + j] = acc[i][j];
}

// ---------------- prep: frames + E/F + packed B2 ----------------
__global__ void prep_k(const float* __restrict__ rot, const float* __restrict__ trans,
                       const float* __restrict__ gamma_raw) {
    __shared__ float R[9], T[3], gqS[144], gkS[144], sqqS[12], sqkS[12], wcgS[12];
    int n = blockIdx.x, tid = threadIdx.x;
    if (tid < 9) R[tid] = rot[n * 9 + tid];
    if (tid < 3) T[tid] = trans[n * 3 + tid];
    if (tid >= 16 && tid < 28) {
        int h = tid - 16;
        float x = gamma_raw[h];
        wcgS[h] = WCc * ((x > 20.f) ? x : log1pf(expf(x)));
    }
    __syncthreads();
    const float* base = &g_proj[(size_t)n * PROJD];
    for (int t = tid; t < 96; t += 128) {
        int which = t / 48, p = t % 48;
        const float* src = base + (which ? OKP : OQP) + p * 3;
        float b0 = src[0], b1 = src[1], b2 = src[2];
        float* dst = (which ? gkS : gqS) + p * 3;
        #pragma unroll
        for (int a = 0; a < 3; a++)
            dst[a] = R[a * 3 + 0] * b0 + R[a * 3 + 1] * b1 + R[a * 3 + 2] * b2 + T[a];
    }
    for (int t = tid; t < 96; t += 128) {
        int h = t >> 3, p = t & 7;
        const float* src = base + OVP + t * 3;
        float b0 = src[0], b1 = src[1], b2 = src[2];
        #pragma unroll
        for (int a = 0; a < 3; a++) {
            float v = R[a * 3 + 0] * b0 + R[a * 3 + 1] * b1 + R[a * 3 + 2] * b2 + T[a];
            g_gv[n * 288 + t * 3 + a] = v;
            g_B2[n * 576 + h * 48 + 16 + p * 3 + a] = v;
        }
    }
    for (int t = tid; t < 192; t += 128) {
        int h = t >> 4, c = t & 15;
        g_B2[n * 576 + h * 48 + c] = base[OV + t];
    }
    for (int t = tid; t < 96; t += 128) {
        int h = t / 8, c = 40 + (t % 8);
        g_B2[n * 576 + h * 48 + c] = 0.f;
    }
    __syncthreads();
    if (tid < 24) {
        int h = tid >> 1, which = tid & 1;
        const float* g = (which ? gkS : gqS) + h * 12;
        float s = 0.f;
        #pragma unroll
        for (int e = 0; e < 12; e++) s += g[e] * g[e];
        (which ? sqkS : sqqS)[h] = s;
    }
    __syncthreads();
    for (int t = tid; t < Hh * 32; t += 128) {
        int h = t >> 5, c = t & 31;
        float wcg = wcgS[h];
        float e, f;
        if (c < 16)      { e = 0.25f * base[OQ + h * 16 + c]; f = base[OK0 + h * 16 + c]; }
        else if (c < 28) { e = wcg * gqS[h * 12 + c - 16];    f = gkS[h * 12 + c - 16]; }
        else if (c == 28){ e = sqqS[h];                        f = -0.5f * wcg; }
        else if (c == 29){ e = 1.f;                            f = -0.5f * wcg * sqkS[h]; }
        else             { e = 0.f;                            f = 0.f; }
        g_E[(size_t)((h << 9) | n) * 32 + c] = e;
        g_F[(size_t)((h << 9) | n) * 32 + c] = f;
    }
}

// ---------------- logit core: 64i x 128j tile, acc 4x8 ----------------
__global__ void core_k() {
    __shared__ float As[32][64], BsT[32][128];
    int h = blockIdx.z, i0 = blockIdx.y * 64, j0 = blockIdx.x * 128;
    int tid = threadIdx.x;
    const float* Eh = &g_E[((size_t)h * Nn + i0) * 32];
    const float* Fh = &g_F[((size_t)h * Nn + j0) * 32];
    for (int t = tid; t < 512; t += 256) {
        int row = t >> 3, d4 = t & 7;
        float4 v = *(const float4*)&Eh[row * 32 + d4 * 4];
        As[d4 * 4 + 0][row] = v.x; As[d4 * 4 + 1][row] = v.y;
        As[d4 * 4 + 2][row] = v.z; As[d4 * 4 + 3][row] = v.w;
    }
    for (int t = tid; t < 1024; t += 256) {
        int row = t >> 3, d4 = t & 7;
        float4 w = *(const float4*)&Fh[row * 32 + d4 * 4];
        BsT[d4 * 4 + 0][row] = w.x; BsT[d4 * 4 + 1][row] = w.y;
        BsT[d4 * 4 + 2][row] = w.z; BsT[d4 * 4 + 3][row] = w.w;
    }
    __syncthreads();
    int tr = tid >> 4, tc = tid & 15;
    float acc[4][8];
    #pragma unroll
    for (int i = 0; i < 4; i++)
        #pragma unroll
        for (int j = 0; j < 8; j++) acc[i][j] = 0.f;
    #pragma unroll
    for (int d = 0; d < 32; d++) {
        float ra[4], rb[8];
        *(float4*)ra = *(const float4*)&As[d][tr * 4];
        *(float4*)&rb[0] = *(const float4*)&BsT[d][tc * 8];
        *(float4*)&rb[4] = *(const float4*)&BsT[d][tc * 8 + 4];
        #pragma unroll
        for (int i = 0; i < 4; i++)
            #pragma unroll
            for (int j = 0; j < 8; j++) acc[i][j] += ra[i] * rb[j];
    }
    #pragma unroll
    for (int i = 0; i < 4; i++) {
        size_t rowb = ((size_t)(i0 + tr * 4 + i) * Hh + h) * Nn + j0 + tc * 8;
        float4 v0 = make_float4(WLc * acc[i][0], WLc * acc[i][1], WLc * acc[i][2], WLc * acc[i][3]);
        float4 v1 = make_float4(WLc * acc[i][4], WLc * acc[i][5], WLc * acc[i][6], WLc * acc[i][7]);
        *(float4*)&g_logits[rowb] = v0;
        *(float4*)&g_logits[rowb + 4] = v1;
    }
}

// ---------------- FLASH2 (R10 scalar form): bias + local softmax + o_pair ----------------
// grid (Nn, 8), 256 thr. smem: pairS[64*132] WbT[12*132] lS[12*64] comb[4*32*25]
__global__ void __launch_bounds__(256) flash2_k(const float* __restrict__ pair,
                                                const float* __restrict__ Wb) {
    extern __shared__ float sm[];
    float* pairS = sm;                  // 8448
    float* WbT   = pairS + 8448;        // 1584
    float* lS    = WbT + 1584;          // 768
    float* comb  = lS + 768;            // 3200
    int i = blockIdx.x, js = blockIdx.y, j0 = js << 6;
    int tid = threadIdx.x;
    int w = tid >> 5, lane = tid & 31;

    for (int r = tid; r < 64 * 32; r += 256) {
        int row = r >> 5, q = r & 31;
        cp16(&pairS[row * 132 + q * 4], &pair[((size_t)i * Nn + j0 + row) * CZd + q * 4]);
    }
    cp_commit();
    for (int t = tid; t < CZd * Hh; t += 256) WbT[(t % Hh) * 132 + (t / Hh)] = Wb[t];
    if (tid < 192) {
        int h = tid >> 4, q = tid & 15;
        *(float4*)&lS[h * 64 + q * 4] =
            *(const float4*)&g_logits[((size_t)i * Hh + h) * Nn + j0 + q * 4];
    }

    // ---- bias: warp w = z-group (16 z), lane = j (2 j) ----
    float acc0[12], acc1[12];
    #pragma unroll
    for (int h = 0; h < 12; h++) { acc0[h] = 0.f; acc1[h] = 0.f; }

    cp_wait<0>();
    __syncthreads();
    {
        const float4* ap0 = (const float4*)&pairS[lane * 132 + w * 16];
        const float4* ap1 = (const float4*)&pairS[(lane + 32) * 132 + w * 16];
        #pragma unroll
        for (int z4 = 0; z4 < 4; z4++) {
            float4 p0 = ap0[z4], p1 = ap1[z4];
            #pragma unroll
            for (int h = 0; h < 12; h++) {
                float4 wv = *(const float4*)&WbT[h * 132 + w * 16 + z4 * 4];
                acc0[h] += p0.x * wv.x + p0.y * wv.y + p0.z * wv.z + p0.w * wv.w;
                acc1[h] += p1.x * wv.x + p1.y * wv.y + p1.z * wv.z + p1.w * wv.w;
            }
        }
    }
    if (w >= 4) {
        float* c = &comb[((w - 4) * 32 + lane) * 25];
        #pragma unroll
        for (int h = 0; h < 12; h++) { c[h] = acc0[h]; c[12 + h] = acc1[h]; }
    }
    __syncthreads();
    if (w < 4) {
        const float* c = &comb[(w * 32 + lane) * 25];
        #pragma unroll
        for (int h = 0; h < 12; h++) { acc0[h] += c[h]; acc1[h] += c[12 + h]; }
    }
    __syncthreads();
    if (w >= 1 && w < 4) {
        float* c = &comb[((w - 1) * 32 + lane) * 25];
        #pragma unroll
        for (int h = 0; h < 12; h++) { c[h] = acc0[h]; c[12 + h] = acc1[h]; }
    }
    __syncthreads();
    if (w == 0) {
        #pragma unroll
        for (int h = 0; h < 12; h++) {
            float s0 = acc0[h], s1 = acc1[h];
            #pragma unroll
            for (int g = 0; g < 3; g++) {
                const float* c = &comb[(g * 32 + lane) * 25];
                s0 += c[h]; s1 += c[12 + h];
            }
            lS[h * 64 + lane] += WLc * s0;
            lS[h * 64 + 32 + lane] += WLc * s1;
        }
    }
    __syncthreads();

    // ---- local softmax: warp w -> head w; warps 0..3 also head 8+w ----
    #pragma unroll
    for (int rep = 0; rep < 2; rep++) {
        int h = w + rep * 8;
        if (h < Hh) {
            float l0 = lS[h * 64 + lane], l1 = lS[h * 64 + 32 + lane];
            float m = fmaxf(l0, l1);
            #pragma unroll
            for (int off = 16; off; off >>= 1) m = fmaxf(m, __shfl_xor_sync(0xffffffffu, m, off));
            float e0 = __expf(l0 - m), e1 = __expf(l1 - m);
            float s = e0 + e1;
            #pragma unroll
            for (int off = 16; off; off >>= 1) s += __shfl_xor_sync(0xffffffffu, s, off);
            lS[h * 64 + lane] = e0;
            lS[h * 64 + 32 + lane] = e1;
            if (lane == 0) {
                int msb = (((i * Hh) + h) * 8 + js) * 2;
                g_ms[msb] = m;
                g_ms[msb + 1] = s;
            }
        }
    }
    __syncthreads();

    // vectorized e writeback for ov_k
    if (tid < 192) {
        int h = tid >> 4, q = tid & 15;
        *(float4*)&g_logits[((size_t)i * Hh + h) * Nn + j0 + q * 4] =
            *(const float4*)&lS[h * 64 + q * 4];
    }

    // ---- o_pair: jh halves of 32 j; thread = (ht 3h) x (zz 4z float4) ----
    int jh = tid >> 7, rem = tid & 127, ht = rem >> 5, zz = rem & 31;
    float a3[3][4];
    #pragma unroll
    for (int b = 0; b < 3; b++)
        #pragma unroll
        for (int a = 0; a < 4; a++) a3[b][a] = 0.f;
    const float* E0 = &lS[(ht * 3 + 0) * 64 + jh * 32];
    const float* E1 = &lS[(ht * 3 + 1) * 64 + jh * 32];
    const float* E2 = &lS[(ht * 3 + 2) * 64 + jh * 32];
    const float* pb = &pairS[jh * 32 * 132];
    #pragma unroll 8
    for (int j = 0; j < 32; j++) {
        float4 p = *(const float4*)&pb[j * 132 + zz * 4];
        float v0 = E0[j], v1 = E1[j], v2 = E2[j];
        a3[0][0] += v0 * p.x; a3[0][1] += v0 * p.y; a3[0][2] += v0 * p.z; a3[0][3] += v0 * p.w;
        a3[1][0] += v1 * p.x; a3[1][1] += v1 * p.y; a3[1][2] += v1 * p.z; a3[1][3] += v1 * p.w;
        a3[2][0] += v2 * p.x; a3[2][1] += v2 * p.y; a3[2][2] += v2 * p.z; a3[2][3] += v2 * p.w;
    }
    if (jh == 1) {
        float* c = &comb[rem * 13];
        #pragma unroll
        for (int b = 0; b < 3; b++)
            #pragma unroll
            for (int a = 0; a < 4; a++) c[b * 4 + a] = a3[b][a];
    }
    __syncthreads();
    if (jh == 0) {
        const float* c = &comb[rem * 13];
        float* dst = &g_opP[((size_t)js * Nn + i) * (Hh * CZd)];
        #pragma unroll
        for (int b = 0; b < 3; b++) {
            float4 v;
            v.x = a3[b][0] + c[b * 4 + 0];
            v.y = a3[b][1] + c[b * 4 + 1];
            v.z = a3[b][2] + c[b * 4 + 2];
            v.w = a3[b][3] + c[b * 4 + 3];
            *(float4*)&dst[(ht * 3 + b) * CZd + zz * 4] = v;
        }
    }
}

// ---------------- combine: global stats + o_pair; factors -> g_fct ----------------
__global__ void combine_k() {
    __shared__ float fctS[96];
    int i = blockIdx.x, tid = threadIdx.x;
    if (tid < 96) {
        int h = tid >> 3, js = tid & 7;
        float mv[8], sv[8];
        float mg = -1e30f;
        #pragma unroll
        for (int k = 0; k < 8; k++) {
            int b = ((i * Hh + h) * 8 + k) * 2;
            mv[k] = g_ms[b]; sv[k] = g_ms[b + 1];
            mg = fmaxf(mg, mv[k]);
        }
        float sg = 0.f;
        #pragma unroll
        for (int k = 0; k < 8; k++) sg += sv[k] * __expf(mv[k] - mg);
        float f = __expf(mv[js] - mg) / sg;
        fctS[tid] = f;
        g_fct[i * 96 + tid] = f;
    }
    __syncthreads();
    const size_t S = (size_t)Nn * Hh * CZd;
    for (int c = tid; c < Hh * CZd; c += 256) {
        int h = c >> 7;
        float s = 0.f;
        #pragma unroll
        for (int js = 0; js < 8; js++)
            s += fctS[h * 8 + js] * g_opP[js * S + (size_t)i * (Hh * CZd) + c];
        g_concat[(size_t)i * OUTD + 576 + c] = s;
    }
}

// ---------------- o_v & o_pt: 4-way j-split partials ----------------
__global__ void ov_k() {
    __shared__ float As[2][32 * 36];
    __shared__ float Bs[2][32 * 48];
    __shared__ float fS[32 * 8];
    int i0 = blockIdx.x * 32, h = blockIdx.y, jp = blockIdx.z;
    int tid = threadIdx.x;
    int tr = tid / 16, tc = tid % 16;
    {
        int row = tid >> 3, js = tid & 7;
        fS[row * 8 + js] = g_fct[(i0 + row) * 96 + h * 8 + js];
    }
    float acc[2][3];
    #pragma unroll
    for (int a = 0; a < 2; a++)
        #pragma unroll
        for (int b = 0; b < 3; b++) acc[a][b] = 0.f;

    auto loadA = [&](int c, int buf) {
        int j0 = (jp * 4 + c) * 32;
        int row = tid >> 3, q = tid & 7;
        cp16(&As[buf][row * 36 + q * 4],
             &g_logits[((size_t)(i0 + row) * Hh + h) * Nn + j0 + q * 4]);
    };
    auto loadB = [&](int c, int buf) {
        int j0 = (jp * 4 + c) * 32;
        for (int t = tid; t < 384; t += 256) {
            int row = t / 12, q = t % 12;
            cp16(&Bs[buf][row * 48 + q * 4], &g_B2[(size_t)(j0 + row) * 576 + h * 48 + q * 4]);
        }
    };
    loadA(0, 0); loadB(0, 0); cp_commit();
    for (int c = 0; c < 4; c++) {
        int buf = c & 1;
        if (c + 1 < 4) {
            loadA(c + 1, buf ^ 1); loadB(c + 1, buf ^ 1); cp_commit();
            cp_wait<1>();
        } else cp_wait<0>();
        __syncthreads();
        float pacc[2][3];
        #pragma unroll
        for (int a = 0; a < 2; a++)
            #pragma unroll
            for (int b = 0; b < 3; b++) pacc[a][b] = 0.f;
        #pragma unroll 8
        for (int jl = 0; jl < 32; jl++) {
            float ra[2], rb[3];
            #pragma unroll
            for (int a = 0; a < 2; a++) ra[a] = As[buf][(tr * 2 + a) * 36 + jl];
            #pragma unroll
            for (int b = 0; b < 3; b++) rb[b] = Bs[buf][jl * 48 + tc * 3 + b];
            #pragma unroll
            for (int a = 0; a < 2; a++)
                #pragma unroll
                for (int b = 0; b < 3; b++) pacc[a][b] += ra[a] * rb[b];
        }
        int js = (jp * 4 + c) >> 1;
        #pragma unroll
        for (int a = 0; a < 2; a++) {
            float f = fS[(tr * 2 + a) * 8 + js];
            #pragma unroll
            for (int b = 0; b < 3; b++) acc[a][b] += f * pacc[a][b];
        }
        __syncthreads();
    }
    float* dst = &g_ovP[((size_t)jp * Nn) * (Hh * 48)];
    #pragma unroll
    for (int a = 0; a < 2; a++) {
        int i = i0 + tr * 2 + a;
        #pragma unroll
        for (int b = 0; b < 3; b++) {
            int c = tc * 3 + b;
            dst[(size_t)i * (Hh * 48) + h * 48 + c] = acc[a][b];
        }
    }
}

// ---------------- combine2: sum 4 ov partials, route to concat/opt ----------------
__global__ void combine2_k() {
    int i = blockIdx.x, tid = threadIdx.x;
    const size_t S = (size_t)Nn * Hh * 48;
    for (int t = tid; t < Hh * 48; t += 256) {
        size_t base = (size_t)i * (Hh * 48) + t;
        float s = g_ovP[base] + g_ovP[S + base] + g_ovP[2 * S + base] + g_ovP[3 * S + base];
        int h = t / 48, c = t % 48;
        if (c < 16)      g_concat[(size_t)i * OUTD + h * Cc + c] = s;
        else if (c < 40) g_opt[i * (Hh * 24) + h * 24 + (c - 16)] = s;
    }
}

__global__ void post_pt_k(const float* __restrict__ rot, const float* __restrict__ trans) {
    int idx = blockIdx.x * blockDim.x + threadIdx.x;
    if (idx >= Nn * Hh * PVd) return;
    int i = idx / (Hh * PVd), t = idx % (Hh * PVd);
    float b0 = g_opt[i * (Hh * 24) + t * 3 + 0] - trans[i * 3 + 0];
    float b1 = g_opt[i * (Hh * 24) + t * 3 + 1] - trans[i * 3 + 1];
    float b2 = g_opt[i * (Hh * 24) + t * 3 + 2] - trans[i * 3 + 2];
    float l0 = rot[i * 9 + 0] * b0 + rot[i * 9 + 3] * b1 + rot[i * 9 + 6] * b2;
    float l1 = rot[i * 9 + 1] * b0 + rot[i * 9 + 4] * b1 + rot[i * 9 + 7] * b2;
    float l2 = rot[i * 9 + 2] * b0 + rot[i * 9 + 5] * b1 + rot[i * 9 + 8] * b2;
    float* crow = &g_concat[(size_t)i * OUTD];
    crow[192 + t * 3 + 0] = l0;
    crow[192 + t * 3 + 1] = l1;
    crow[192 + t * 3 + 2] = l2;
    crow[480 + t] = sqrtf(l0 * l0 + l1 * l1 + l2 * l2 + 1e-8f);
}

// ---------------- layer norms ----------------
__device__ __forceinline__ float blockSum384(float v, float* red) {
    int tid = threadIdx.x;
    red[tid] = v;
    if (tid < 128) red[384 + tid] = 0.f;
    __syncthreads();
    for (int s = 256; s > 0; s >>= 1) {
        if (tid < s) red[tid] += red[tid + s];
        __syncthreads();
    }
    float r = red[0];
    __syncthreads();
    return r;
}

__global__ void ln1_k(const float* __restrict__ single_in, const float* __restrict__ bo,
                      const float* __restrict__ g, const float* __restrict__ b) {
    __shared__ float red[512];
    int row = blockIdx.x, tid = threadIdx.x;
    float x = single_in[row * CSd + tid] + bo[tid];
    #pragma unroll
    for (int z = 0; z < 4; z++) x += g_wop[(size_t)z * Nn * CSd + row * CSd + tid];
    float mean = blockSum384(x, red) * (1.f / CSd);
    float dx = x - mean;
    float var = blockSum384(dx * dx, red) * (1.f / CSd);
    g_s1[row * CSd + tid] = dx * rsqrtf(var + 1e-5f) * g[tid] + b[tid];
}

__global__ void ln2_k(const float* __restrict__ g, const float* __restrict__ b,
                      float* __restrict__ out) {
    __shared__ float red[512];
    int row = blockIdx.x, tid = threadIdx.x;
    float x = g_s1[row * CSd + tid] + g_h3[row * CSd + tid];
    float mean = blockSum384(x, red) * (1.f / CSd);
    float dx = x - mean;
    float var = blockSum384(dx * dx, red) * (1.f / CSd);
    float y = dx * rsqrtf(var + 1e-5f) * g[tid] + b[tid];
    out[row * CSd + tid] = y;
    g_s2[row * CSd + tid] = y;
}

// ---------------- backbone update ----------------
__global__ void update_k(const float* __restrict__ rot, const float* __restrict__ trans,
                         const float* __restrict__ Wbu, const float* __restrict__ bbu,
                         float* __restrict__ out) {
    int gtid = blockIdx.x * blockDim.x + threadIdx.x;
    int n = gtid >> 5, lane = gtid & 31;
    if (n >= Nn) return;
    float u[6] = {0, 0, 0, 0, 0, 0};
    for (int s = lane; s < CSd; s += 32) {
        float x = g_s2[n * CSd + s];
        #pragma unroll
        for (int j = 0; j < 6; j++) u[j] += x * Wbu[s * 6 + j];
    }
    #pragma unroll
    for (int j = 0; j < 6; j++)
        #pragma unroll
        for (int off = 16; off; off >>= 1) u[j] += __shfl_xor_sync(0xffffffffu, u[j], off);
    if (lane != 0) return;
    #pragma unroll
    for (int j = 0; j < 6; j++) u[j] += bbu[j];
    float b = u[0], c = u[1], d = u[2];
    float inq = rsqrtf(1.f + b * b + c * c + d * d);
    float a = inq; b *= inq; c *= inq; d *= inq;
    float R[9] = {
        a*a + b*b - c*c - d*d, 2.f*(b*c - a*d),       2.f*(b*d + a*c),
        2.f*(b*c + a*d),       a*a - b*b + c*c - d*d, 2.f*(c*d - a*b),
        2.f*(b*d - a*c),       2.f*(c*d + a*b),       a*a - b*b - c*c + d*d };
    float rn[9];
    #pragma unroll
    for (int aa = 0; aa < 3; aa++)
        #pragma unroll
        for (int cc = 0; cc < 3; cc++) {
            float s2 = 0.f;
            #pragma unroll
            for (int bx = 0; bx < 3; bx++) s2 += rot[n * 9 + aa * 3 + bx] * R[bx * 3 + cc];
            rn[aa * 3 + cc] = s2;
        }
    float t0 = u[3], t1 = u[4], t2 = u[5];
    float tn[3];
    #pragma unroll
    for (int aa = 0; aa < 3; aa++)
        tn[aa] = rot[n * 9 + aa * 3 + 0] * t0 + rot[n * 9 + aa * 3 + 1] * t1 +
                 rot[n * 9 + aa * 3 + 2] * t2 + trans[n * 3 + aa];
    #pragma unroll
    for (int e = 0; e < 9; e++) { g_rotn[n * 9 + e] = rn[e]; out[Nn * CSd + n * 9 + e] = rn[e]; }
    #pragma unroll
    for (int e = 0; e < 3; e++) { g_trn[n * 3 + e] = tn[e]; out[Nn * CSd + Nn * 9 + n * 3 + e] = tn[e]; }
}

// ---------------- loss ----------------
__global__ void loss_part_k(const float* __restrict__ rt, const float* __restrict__ tt) {
    int i = blockIdx.x, tid = threadIdx.x;
    __shared__ float red[256];
    float rn[9], rte[9], tni[3], tti[3];
    #pragma unroll
    for (int e = 0; e < 9; e++) { rn[e] = g_rotn[i * 9 + e]; rte[e] = rt[i * 9 + e]; }
    #pragma unroll
    for (int e = 0; e < 3; e++) { tni[e] = g_trn[i * 3 + e]; tti[e] = tt[i * 3 + e]; }
    float s = 0.f;
    for (int j = tid; j < Nn; j += 256) {
        float db0 = g_trn[j * 3 + 0] - tni[0];
        float db1 = g_trn[j * 3 + 1] - tni[1];
        float db2 = g_trn[j * 3 + 2] - tni[2];
        float dp0 = rn[0] * db0 + rn[3] * db1 + rn[6] * db2;
        float dp1 = rn[1] * db0 + rn[4] * db1 + rn[7] * db2;
        float dp2 = rn[2] * db0 + rn[5] * db1 + rn[8] * db2;
        float eb0 = tt[j * 3 + 0] - tti[0];
        float eb1 = tt[j * 3 + 1] - tti[1];
        float eb2 = tt[j * 3 + 2] - tti[2];
        float dt0 = rte[0] * eb0 + rte[3] * eb1 + rte[6] * eb2;
        float dt1 = rte[1] * eb0 + rte[4] * eb1 + rte[7] * eb2;
        float dt2 = rte[2] * eb0 + rte[5] * eb1 + rte[8] * eb2;
        float d0 = dp0 - dt0, d1 = dp1 - dt1, d2 = dp2 - dt2;
        float dd = sqrtf(d0 * d0 + d1 * d1 + d2 * d2 + 1e-12f);
        s += fminf(dd, 10.f);
    }
    red[tid] = s; __syncthreads();
    for (int st = 128; st > 0; st >>= 1) {
        if (tid < st) red[tid] += red[tid + st];
        __syncthreads();
    }
    if (tid == 0) g_partial[i] = red[0];
}

__global__ void loss_final_k(float* __restrict__ out) {
    __shared__ float red[512];
    int tid = threadIdx.x;
    red[tid] = g_partial[tid];
    __syncthreads();
    for (int s = 256; s > 0; s >>= 1) {
        if (tid < s) red[tid] += red[tid + s];
        __syncthreads();
    }
    if (tid == 0)
        out[Nn * CSd + Nn * 9 + Nn * 3] = red[0] / ((float)Nn * (float)Nn) * 0.1f;
}

// ---------------- host ----------------
template <typename T>
static float* symaddr(T& sym) {
    void* p = nullptr;
    cudaGetSymbolAddress(&p, sym);
    return (float*)p;
}

extern "C" void kernel_launch(void* const* d_in, const int* in_sizes, int n_in,
                              void* d_out, int out_size) {
    const float* single      = (const float*)d_in[0];
    const float* pair        = (const float*)d_in[1];
    const float* rot         = (const float*)d_in[2];
    const float* trans       = (const float*)d_in[3];
    const float* rot_truth   = (const float*)d_in[4];
    const float* trans_truth = (const float*)d_in[5];
    const float* Wq  = (const float*)d_in[6];
    const float* Wk  = (const float*)d_in[7];
    const float* Wv  = (const float*)d_in[8];
    const float* Wqp = (const float*)d_in[9];
    const float* Wkp = (const float*)d_in[10];
    const float* Wvp = (const float*)d_in[11];
    const float* Wb  = (const float*)d_in[12];
    const float* Wo  = (const float*)d_in[13];
    const float* bo  = (const float*)d_in[14];
    const float* gamma_raw = (const float*)d_in[15];
    const float* ln1_g = (const float*)d_in[16];
    const float* ln1_b = (const float*)d_in[17];
    const float* ln2_g = (const float*)d_in[18];
    const float* ln2_b = (const float*)d_in[19];
    const float* W1 = (const float*)d_in[20];
    const float* b1 = (const float*)d_in[21];
    const float* W2 = (const float*)d_in[22];
    const float* b2 = (const float*)d_in[23];
    const float* W3 = (const float*)d_in[24];
    const float* b3 = (const float*)d_in[25];
    const float* Wbu = (const float*)d_in[26];
    const float* bbu = (const float*)d_in[27];
    float* out = (float*)d_out;

    float* pProj   = symaddr(g_proj);
    float* pConcat = symaddr(g_concat);
    float* pS1     = symaddr(g_s1);
    float* pH1     = symaddr(g_h1);
    float* pH2     = symaddr(g_h2);
    float* pH3     = symaddr(g_h3);

    const int FLASH2_SMEM = (8448 + 1584 + 768 + 3200) * 4;   // 56000
    cudaFuncSetAttribute(flash2_k, cudaFuncAttributeMaxDynamicSharedMemorySize, FLASH2_SMEM);

    proj_gemm_k<<<dim3(PROJD/64, Nn/64), 256>>>(single, Wq, Wk, Wv, Wqp, Wkp, Wvp, pProj);
    prep_k<<<Nn, 128>>>(rot, trans, gamma_raw);
    core_k<<<dim3(Nn/128, Nn/64, Hh), 256>>>();

    flash2_k<<<dim3(Nn, 8), 256, FLASH2_SMEM>>>(pair, Wb);   // profiler slot 4
    combine_k<<<Nn, 256>>>();
    ov_k<<<dim3(Nn/32, Hh, 4), 256>>>();
    combine2_k<<<Nn, 256>>>();
    post_pt_k<<<(Nn * Hh * PVd + 255) / 256, 256>>>(rot, trans);

    sgemm_k<64,64,16,4,4,false,false,true><<<dim3(CSd/64, Nn/64, 4), 256>>>(
        pConcat, Wo, nullptr, symaddr(g_wop), Nn, CSd, OUTD, OUTD/4);
    ln1_k<<<Nn, CSd>>>(single, bo, ln1_g, ln1_b);

    sgemm_k<32,64,16,2,4,true,true,false><<<dim3(CSd/64, Nn/32, 1), 256>>>(
        pS1, W1, b1, pH1, Nn, CSd, CSd, CSd);
    sgemm_k<32,64,16,2,4,true,true,false><<<dim3(CSd/64, Nn/32, 1), 256>>>(
        pH1, W2, b2, pH2, Nn, CSd, CSd, CSd);
    sgemm_k<32,64,16,2,4,true,false,false><<<dim3(CSd/64, Nn/32, 1), 256>>>(
        pH2, W3, b3, pH3, Nn, CSd, CSd, CSd);
    ln2_k<<<Nn, CSd>>>(ln2_g, ln2_b, out);

    update_k<<<(Nn * 32 + 127) / 128, 128>>>(rot, trans, Wbu, bbu, out);
    loss_part_k<<<Nn, 256>>>(rot_truth, trans_truth);
    loss_final_k<<<1, 512>>>(out);
}

// round 13
// speedup vs baseline: 1.0283x; 1.0211x over previous
#include <cuda_runtime.h>
#include <math.h>

#define Nn 512
#define CSd 384
#define CZd 128
#define Hh 12
#define Cc 16
#define PQd 4
#define PVd 8
#define OUTD 2112
#define PROJD 1152
#define OQ 0
#define OK0 192
#define OV 384
#define OQP 576
#define OKP 720
#define OVP 864

__device__ float g_proj[Nn * PROJD];
__device__ float g_gv[Nn * Hh * PVd * 3];
__device__ float g_B2[Nn * Hh * 48];
__device__ float g_E[Hh * Nn * 32], g_F[Hh * Nn * 32];
__device__ float g_logits[Nn * Hh * Nn];
__device__ float g_opP[8 * Nn * Hh * CZd];
__device__ float g_ovP[4 * Nn * Hh * 48];
__device__ float g_ms[Nn * Hh * 8 * 2];
__device__ float g_fct[Nn * 96];
__device__ float g_concat[Nn * OUTD];
__device__ float g_wop[4 * Nn * CSd];
__device__ float g_s1[Nn * CSd], g_h1[Nn * CSd], g_h2[Nn * CSd], g_h3[Nn * CSd], g_s2[Nn * CSd];
__device__ float g_rotn[Nn * 9], g_trn[Nn * 3];
__device__ float g_partial[Nn];

#define WLc 0.5773502691896258f
#define WCc 0.23570226039551584f

__device__ __forceinline__ void cp16(void* smem_dst, const void* gmem_src) {
    unsigned s = (unsigned)__cvta_generic_to_shared(smem_dst);
    asm volatile("cp.async.cg.shared.global [%0], [%1], 16;" :: "r"(s), "l"(gmem_src));
}
__device__ __forceinline__ void cp_commit() { asm volatile("cp.async.commit_group;"); }
template<int N> __device__ __forceinline__ void cp_wait() {
    asm volatile("cp.async.wait_group %0;" :: "n"(N));
}

// ---------------- generic double-buffered tiled SGEMM ----------------
template<int BM, int BN, int BK, int TM, int TN, bool BIAS, bool RELU, bool SPLITK>
__global__ void sgemm_k(const float* __restrict__ A, const float* __restrict__ B,
                        const float* __restrict__ bias, float* __restrict__ C,
                        int M, int N, int K, int KC) {
    const int THREADS = (BM / TM) * (BN / TN);
    __shared__ float As[2][BK][BM];
    __shared__ float Bs[2][BK][BN + 4];
    int n0 = blockIdx.x * BN, m0 = blockIdx.y * BM;
    int kstart = SPLITK ? blockIdx.z * KC : 0;
    if (SPLITK) C += (size_t)blockIdx.z * M * N;
    int tid = threadIdx.x;
    int tr = tid / (BN / TN), tc = tid % (BN / TN);
    float acc[TM][TN];
    #pragma unroll
    for (int i = 0; i < TM; i++)
        #pragma unroll
        for (int j = 0; j < TN; j++) acc[i][j] = 0.f;
    int nsteps = KC / BK;

    auto loadA = [&](int kt, int buf) {
        #pragma unroll
        for (int r = tid; r < BM * BK / 4; r += THREADS) {
            int arow = r / (BK / 4), aq = r % (BK / 4);
            float4 v = *(const float4*)&A[(size_t)(m0 + arow) * K + kstart + kt * BK + aq * 4];
            As[buf][aq * 4 + 0][arow] = v.x; As[buf][aq * 4 + 1][arow] = v.y;
            As[buf][aq * 4 + 2][arow] = v.z; As[buf][aq * 4 + 3][arow] = v.w;
        }
    };
    auto loadB = [&](int kt, int buf) {
        #pragma unroll
        for (int r = tid; r < BK * BN / 4; r += THREADS) {
            int brow = r / (BN / 4), bq = r % (BN / 4);
            cp16(&Bs[buf][brow][bq * 4], &B[(size_t)(kstart + kt * BK + brow) * N + n0 + bq * 4]);
        }
    };
    loadA(0, 0); loadB(0, 0); cp_commit();
    for (int kt = 0; kt < nsteps; kt++) {
        int buf = kt & 1;
        if (kt + 1 < nsteps) {
            loadA(kt + 1, buf ^ 1); loadB(kt + 1, buf ^ 1); cp_commit();
            cp_wait<1>();
        } else cp_wait<0>();
        __syncthreads();
        #pragma unroll
        for (int k = 0; k < BK; k++) {
            float ra[TM], rb[TN];
            if constexpr (TM % 4 == 0) {
                #pragma unroll
                for (int i = 0; i < TM; i += 4)
                    *(float4*)&ra[i] = *(const float4*)&As[buf][k][tr * TM + i];
            } else {
                #pragma unroll
                for (int i = 0; i < TM; i++) ra[i] = As[buf][k][tr * TM + i];
            }
            #pragma unroll
            for (int j = 0; j < TN; j += 4)
                *(float4*)&rb[j] = *(const float4*)&Bs[buf][k][tc * TN + j];
            #pragma unroll
            for (int i = 0; i < TM; i++)
                #pragma unroll
                for (int j = 0; j < TN; j++) acc[i][j] += ra[i] * rb[j];
        }
        __syncthreads();
    }
    #pragma unroll
    for (int i = 0; i < TM; i++) {
        int m = m0 + tr * TM + i;
        #pragma unroll
        for (int j = 0; j < TN; j++) {
            int n = n0 + tc * TN + j;
            float v = acc[i][j];
            if (BIAS) v += bias[n];
            if (RELU) v = fmaxf(v, 0.f);
            C[(size_t)m * N + n] = v;
        }
    }
}

// ---------------- projection GEMM with fused 6-way weight gather ----------------
__device__ __forceinline__ const float* wf_ptr(
    const float* Wq, const float* Wk, const float* Wv,
    const float* Wqp, const float* Wkp, const float* Wvp, int kk, int n) {
    if (n < 192) return Wq  + kk * 192 + n;
    if (n < 384) return Wk  + kk * 192 + (n - 192);
    if (n < 576) return Wv  + kk * 192 + (n - 384);
    if (n < 720) return Wqp + kk * 144 + (n - 576);
    if (n < 864) return Wkp + kk * 144 + (n - 720);
    return Wvp + kk * 288 + (n - 864);
}

__global__ void proj_gemm_k(const float* __restrict__ A,
                            const float* __restrict__ Wq, const float* __restrict__ Wk,
                            const float* __restrict__ Wv, const float* __restrict__ Wqp,
                            const float* __restrict__ Wkp, const float* __restrict__ Wvp,
                            float* __restrict__ C) {
    const int BM = 64, BN = 64, BK = 16;
    __shared__ float As[2][BK][BM];
    __shared__ float Bs[2][BK][BN + 4];
    int n0 = blockIdx.x * BN, m0 = blockIdx.y * BM;
    int tid = threadIdx.x;
    int tr = tid / 16, tc = tid % 16;
    float acc[4][4];
    #pragma unroll
    for (int i = 0; i < 4; i++)
        #pragma unroll
        for (int j = 0; j < 4; j++) acc[i][j] = 0.f;
    auto loadA = [&](int kt, int buf) {
        for (int r = tid; r < BM * BK / 4; r += 256) {
            int arow = r / 4, aq = r % 4;
            float4 v = *(const float4*)&A[(size_t)(m0 + arow) * CSd + kt * BK + aq * 4];
            As[buf][aq * 4 + 0][arow] = v.x; As[buf][aq * 4 + 1][arow] = v.y;
            As[buf][aq * 4 + 2][arow] = v.z; As[buf][aq * 4 + 3][arow] = v.w;
        }
    };
    auto loadB = [&](int kt, int buf) {
        for (int r = tid; r < BK * BN / 4; r += 256) {
            int brow = r / 16, bq = r % 16;
            cp16(&Bs[buf][brow][bq * 4],
                 wf_ptr(Wq, Wk, Wv, Wqp, Wkp, Wvp, kt * BK + brow, n0 + bq * 4));
        }
    };
    loadA(0, 0); loadB(0, 0); cp_commit();
    const int nsteps = CSd / BK;
    for (int kt = 0; kt < nsteps; kt++) {
        int buf = kt & 1;
        if (kt + 1 < nsteps) {
            loadA(kt + 1, buf ^ 1); loadB(kt + 1, buf ^ 1); cp_commit();
            cp_wait<1>();
        } else cp_wait<0>();
        __syncthreads();
        #pragma unroll
        for (int k = 0; k < BK; k++) {
            float ra[4], rb[4];
            *(float4*)ra = *(const float4*)&As[buf][k][tr * 4];
            *(float4*)rb = *(const float4*)&Bs[buf][k][tc * 4];
            #pragma unroll
            for (int i = 0; i < 4; i++)
                #pragma unroll
                for (int j = 0; j < 4; j++) acc[i][j] += ra[i] * rb[j];
        }
        __syncthreads();
    }
    #pragma unroll
    for (int i = 0; i < 4; i++)
        #pragma unroll
        for (int j = 0; j < 4; j++)
            C[(size_t)(m0 + tr * 4 + i) * PROJD + n0 + tc * 4 + j] = acc[i][j];
}

// ---------------- prep: frames + E/F + packed B2 ----------------
__global__ void prep_k(const float* __restrict__ rot, const float* __restrict__ trans,
                       const float* __restrict__ gamma_raw) {
    __shared__ float R[9], T[3], gqS[144], gkS[144], sqqS[12], sqkS[12], wcgS[12];
    int n = blockIdx.x, tid = threadIdx.x;
    if (tid < 9) R[tid] = rot[n * 9 + tid];
    if (tid < 3) T[tid] = trans[n * 3 + tid];
    if (tid >= 16 && tid < 28) {
        int h = tid - 16;
        float x = gamma_raw[h];
        wcgS[h] = WCc * ((x > 20.f) ? x : log1pf(expf(x)));
    }
    __syncthreads();
    const float* base = &g_proj[(size_t)n * PROJD];
    for (int t = tid; t < 96; t += 128) {
        int which = t / 48, p = t % 48;
        const float* src = base + (which ? OKP : OQP) + p * 3;
        float b0 = src[0], b1 = src[1], b2 = src[2];
        float* dst = (which ? gkS : gqS) + p * 3;
        #pragma unroll
        for (int a = 0; a < 3; a++)
            dst[a] = R[a * 3 + 0] * b0 + R[a * 3 + 1] * b1 + R[a * 3 + 2] * b2 + T[a];
    }
    for (int t = tid; t < 96; t += 128) {
        int h = t >> 3, p = t & 7;
        const float* src = base + OVP + t * 3;
        float b0 = src[0], b1 = src[1], b2 = src[2];
        #pragma unroll
        for (int a = 0; a < 3; a++) {
            float v = R[a * 3 + 0] * b0 + R[a * 3 + 1] * b1 + R[a * 3 + 2] * b2 + T[a];
            g_gv[n * 288 + t * 3 + a] = v;
            g_B2[n * 576 + h * 48 + 16 + p * 3 + a] = v;
        }
    }
    for (int t = tid; t < 192; t += 128) {
        int h = t >> 4, c = t & 15;
        g_B2[n * 576 + h * 48 + c] = base[OV + t];
    }
    for (int t = tid; t < 96; t += 128) {
        int h = t / 8, c = 40 + (t % 8);
        g_B2[n * 576 + h * 48 + c] = 0.f;
    }
    __syncthreads();
    if (tid < 24) {
        int h = tid >> 1, which = tid & 1;
        const float* g = (which ? gkS : gqS) + h * 12;
        float s = 0.f;
        #pragma unroll
        for (int e = 0; e < 12; e++) s += g[e] * g[e];
        (which ? sqkS : sqqS)[h] = s;
    }
    __syncthreads();
    for (int t = tid; t < Hh * 32; t += 128) {
        int h = t >> 5, c = t & 31;
        float wcg = wcgS[h];
        float e, f;
        if (c < 16)      { e = 0.25f * base[OQ + h * 16 + c]; f = base[OK0 + h * 16 + c]; }
        else if (c < 28) { e = wcg * gqS[h * 12 + c - 16];    f = gkS[h * 12 + c - 16]; }
        else if (c == 28){ e = sqqS[h];                        f = -0.5f * wcg; }
        else if (c == 29){ e = 1.f;                            f = -0.5f * wcg * sqkS[h]; }
        else             { e = 0.f;                            f = 0.f; }
        g_E[(size_t)((h << 9) | n) * 32 + c] = e;
        g_F[(size_t)((h << 9) | n) * 32 + c] = f;
    }
}

// ---------------- logit core: 64i x 128j tile, acc 4x8 ----------------
__global__ void core_k() {
    __shared__ float As[32][64], BsT[32][128];
    int h = blockIdx.z, i0 = blockIdx.y * 64, j0 = blockIdx.x * 128;
    int tid = threadIdx.x;
    const float* Eh = &g_E[((size_t)h * Nn + i0) * 32];
    const float* Fh = &g_F[((size_t)h * Nn + j0) * 32];
    for (int t = tid; t < 512; t += 256) {
        int row = t >> 3, d4 = t & 7;
        float4 v = *(const float4*)&Eh[row * 32 + d4 * 4];
        As[d4 * 4 + 0][row] = v.x; As[d4 * 4 + 1][row] = v.y;
        As[d4 * 4 + 2][row] = v.z; As[d4 * 4 + 3][row] = v.w;
    }
    for (int t = tid; t < 1024; t += 256) {
        int row = t >> 3, d4 = t & 7;
        float4 w = *(const float4*)&Fh[row * 32 + d4 * 4];
        BsT[d4 * 4 + 0][row] = w.x; BsT[d4 * 4 + 1][row] = w.y;
        BsT[d4 * 4 + 2][row] = w.z; BsT[d4 * 4 + 3][row] = w.w;
    }
    __syncthreads();
    int tr = tid >> 4, tc = tid & 15;
    float acc[4][8];
    #pragma unroll
    for (int i = 0; i < 4; i++)
        #pragma unroll
        for (int j = 0; j < 8; j++) acc[i][j] = 0.f;
    #pragma unroll
    for (int d = 0; d < 32; d++) {
        float ra[4], rb[8];
        *(float4*)ra = *(const float4*)&As[d][tr * 4];
        *(float4*)&rb[0] = *(const float4*)&BsT[d][tc * 8];
        *(float4*)&rb[4] = *(const float4*)&BsT[d][tc * 8 + 4];
        #pragma unroll
        for (int i = 0; i < 4; i++)
            #pragma unroll
            for (int j = 0; j < 8; j++) acc[i][j] += ra[i] * rb[j];
    }
    #pragma unroll
    for (int i = 0; i < 4; i++) {
        size_t rowb = ((size_t)(i0 + tr * 4 + i) * Hh + h) * Nn + j0 + tc * 8;
        float4 v0 = make_float4(WLc * acc[i][0], WLc * acc[i][1], WLc * acc[i][2], WLc * acc[i][3]);
        float4 v1 = make_float4(WLc * acc[i][4], WLc * acc[i][5], WLc * acc[i][6], WLc * acc[i][7]);
        *(float4*)&g_logits[rowb] = v0;
        *(float4*)&g_logits[rowb + 4] = v1;
    }
}

// ---------------- FLASH2 (exact R10 form): bias + local softmax + o_pair ----------------
// grid (Nn, 8), 256 thr. smem: pairS[64*132] WbT[12*132] lS[12*64] comb[4*32*25]
__global__ void __launch_bounds__(256) flash2_k(const float* __restrict__ pair,
                                                const float* __restrict__ Wb) {
    extern __shared__ float sm[];
    float* pairS = sm;                  // 8448
    float* WbT   = pairS + 8448;        // 1584
    float* lS    = WbT + 1584;          // 768
    float* comb  = lS + 768;            // 3200
    int i = blockIdx.x, js = blockIdx.y, j0 = js << 6;
    int tid = threadIdx.x;
    int w = tid >> 5, lane = tid & 31;

    for (int r = tid; r < 64 * 32; r += 256) {
        int row = r >> 5, q = r & 31;
        cp16(&pairS[row * 132 + q * 4], &pair[((size_t)i * Nn + j0 + row) * CZd + q * 4]);
    }
    cp_commit();
    for (int t = tid; t < CZd * Hh; t += 256) WbT[(t % Hh) * 132 + (t / Hh)] = Wb[t];
    if (tid < 192) {
        int h = tid >> 4, q = tid & 15;
        *(float4*)&lS[h * 64 + q * 4] =
            *(const float4*)&g_logits[((size_t)i * Hh + h) * Nn + j0 + q * 4];
    }

    // ---- bias: warp w = z-group (16 z), lane = j (2 j) ----
    float acc0[12], acc1[12];
    #pragma unroll
    for (int h = 0; h < 12; h++) { acc0[h] = 0.f; acc1[h] = 0.f; }

    cp_wait<0>();
    __syncthreads();
    {
        const float4* ap0 = (const float4*)&pairS[lane * 132 + w * 16];
        const float4* ap1 = (const float4*)&pairS[(lane + 32) * 132 + w * 16];
        #pragma unroll
        for (int z4 = 0; z4 < 4; z4++) {
            float4 p0 = ap0[z4], p1 = ap1[z4];
            #pragma unroll
            for (int h = 0; h < 12; h++) {
                float4 wv = *(const float4*)&WbT[h * 132 + w * 16 + z4 * 4];
                acc0[h] += p0.x * wv.x + p0.y * wv.y + p0.z * wv.z + p0.w * wv.w;
                acc1[h] += p1.x * wv.x + p1.y * wv.y + p1.z * wv.z + p1.w * wv.w;
            }
        }
    }
    if (w >= 4) {
        float* c = &comb[((w - 4) * 32 + lane) * 25];
        #pragma unroll
        for (int h = 0; h < 12; h++) { c[h] = acc0[h]; c[12 + h] = acc1[h]; }
    }
    __syncthreads();
    if (w < 4) {
        const float* c = &comb[(w * 32 + lane) * 25];
        #pragma unroll
        for (int h = 0; h < 12; h++) { acc0[h] += c[h]; acc1[h] += c[12 + h]; }
    }
    __syncthreads();
    if (w >= 1 && w < 4) {
        float* c = &comb[((w - 1) * 32 + lane) * 25];
        #pragma unroll
        for (int h = 0; h < 12; h++) { c[h] = acc0[h]; c[12 + h] = acc1[h]; }
    }
    __syncthreads();
    if (w == 0) {
        #pragma unroll
        for (int h = 0; h < 12; h++) {
            float s0 = acc0[h], s1 = acc1[h];
            #pragma unroll
            for (int g = 0; g < 3; g++) {
                const float* c = &comb[(g * 32 + lane) * 25];
                s0 += c[h]; s1 += c[12 + h];
            }
            lS[h * 64 + lane] += WLc * s0;
            lS[h * 64 + 32 + lane] += WLc * s1;
        }
    }
    __syncthreads();

    // ---- local softmax: warp w -> head w; warps 0..3 also head 8+w ----
    #pragma unroll
    for (int rep = 0; rep < 2; rep++) {
        int h = w + rep * 8;
        if (h < Hh) {
            float l0 = lS[h * 64 + lane], l1 = lS[h * 64 + 32 + lane];
            float m = fmaxf(l0, l1);
            #pragma unroll
            for (int off = 16; off; off >>= 1) m = fmaxf(m, __shfl_xor_sync(0xffffffffu, m, off));
            float e0 = __expf(l0 - m), e1 = __expf(l1 - m);
            float s = e0 + e1;
            #pragma unroll
            for (int off = 16; off; off >>= 1) s += __shfl_xor_sync(0xffffffffu, s, off);
            lS[h * 64 + lane] = e0;
            lS[h * 64 + 32 + lane] = e1;
            size_t gb = ((size_t)i * Hh + h) * Nn + j0;
            g_logits[gb + lane] = e0;
            g_logits[gb + 32 + lane] = e1;
            if (lane == 0) {
                int msb = (((i * Hh) + h) * 8 + js) * 2;
                g_ms[msb] = m;
                g_ms[msb + 1] = s;
            }
        }
    }
    __syncthreads();

    // ---- o_pair: jh halves of 32 j; thread = (ht 3h) x (zz 4z float4) ----
    int jh = tid >> 7, rem = tid & 127, ht = rem >> 5, zz = rem & 31;
    float a3[3][4];
    #pragma unroll
    for (int b = 0; b < 3; b++)
        #pragma unroll
        for (int a = 0; a < 4; a++) a3[b][a] = 0.f;
    const float* E0 = &lS[(ht * 3 + 0) * 64 + jh * 32];
    const float* E1 = &lS[(ht * 3 + 1) * 64 + jh * 32];
    const float* E2 = &lS[(ht * 3 + 2) * 64 + jh * 32];
    const float* pb = &pairS[jh * 32 * 132];
    #pragma unroll 8
    for (int j = 0; j < 32; j++) {
        float4 p = *(const float4*)&pb[j * 132 + zz * 4];
        float v0 = E0[j], v1 = E1[j], v2 = E2[j];
        a3[0][0] += v0 * p.x; a3[0][1] += v0 * p.y; a3[0][2] += v0 * p.z; a3[0][3] += v0 * p.w;
        a3[1][0] += v1 * p.x; a3[1][1] += v1 * p.y; a3[1][2] += v1 * p.z; a3[1][3] += v1 * p.w;
        a3[2][0] += v2 * p.x; a3[2][1] += v2 * p.y; a3[2][2] += v2 * p.z; a3[2][3] += v2 * p.w;
    }
    if (jh == 1) {
        float* c = &comb[rem * 13];
        #pragma unroll
        for (int b = 0; b < 3; b++)
            #pragma unroll
            for (int a = 0; a < 4; a++) c[b * 4 + a] = a3[b][a];
    }
    __syncthreads();
    if (jh == 0) {
        const float* c = &comb[rem * 13];
        float* dst = &g_opP[((size_t)js * Nn + i) * (Hh * CZd)];
        #pragma unroll
        for (int b = 0; b < 3; b++) {
            float4 v;
            v.x = a3[b][0] + c[b * 4 + 0];
            v.y = a3[b][1] + c[b * 4 + 1];
            v.z = a3[b][2] + c[b * 4 + 2];
            v.w = a3[b][3] + c[b * 4 + 3];
            *(float4*)&dst[(ht * 3 + b) * CZd + zz * 4] = v;
        }
    }
}

// ---------------- combine: global stats + o_pair; factors -> g_fct ----------------
__global__ void combine_k() {
    __shared__ float fctS[96];
    int i = blockIdx.x, tid = threadIdx.x;
    if (tid < 96) {
        int h = tid >> 3, js = tid & 7;
        float mv[8], sv[8];
        float mg = -1e30f;
        #pragma unroll
        for (int k = 0; k < 8; k++) {
            int b = ((i * Hh + h) * 8 + k) * 2;
            mv[k] = g_ms[b]; sv[k] = g_ms[b + 1];
            mg = fmaxf(mg, mv[k]);
        }
        float sg = 0.f;
        #pragma unroll
        for (int k = 0; k < 8; k++) sg += sv[k] * __expf(mv[k] - mg);
        float f = __expf(mv[js] - mg) / sg;
        fctS[tid] = f;
        g_fct[i * 96 + tid] = f;
    }
    __syncthreads();
    const size_t S = (size_t)Nn * Hh * CZd;
    for (int c = tid; c < Hh * CZd; c += 256) {
        int h = c >> 7;
        float s = 0.f;
        #pragma unroll
        for (int js = 0; js < 8; js++)
            s += fctS[h * 8 + js] * g_opP[js * S + (size_t)i * (Hh * CZd) + c];
        g_concat[(size_t)i * OUTD + 576 + c] = s;
    }
}

// ---------------- o_v & o_pt: 4-way j-split partials ----------------
__global__ void ov_k() {
    __shared__ float As[2][32 * 36];
    __shared__ float Bs[2][32 * 48];
    __shared__ float fS[32 * 8];
    int i0 = blockIdx.x * 32, h = blockIdx.y, jp = blockIdx.z;
    int tid = threadIdx.x;
    int tr = tid / 16, tc = tid % 16;
    {
        int row = tid >> 3, js = tid & 7;
        fS[row * 8 + js] = g_fct[(i0 + row) * 96 + h * 8 + js];
    }
    float acc[2][3];
    #pragma unroll
    for (int a = 0; a < 2; a++)
        #pragma unroll
        for (int b = 0; b < 3; b++) acc[a][b] = 0.f;

    auto loadA = [&](int c, int buf) {
        int j0 = (jp * 4 + c) * 32;
        int row = tid >> 3, q = tid & 7;
        cp16(&As[buf][row * 36 + q * 4],
             &g_logits[((size_t)(i0 + row) * Hh + h) * Nn + j0 + q * 4]);
    };
    auto loadB = [&](int c, int buf) {
        int j0 = (jp * 4 + c) * 32;
        for (int t = tid; t < 384; t += 256) {
            int row = t / 12, q = t % 12;
            cp16(&Bs[buf][row * 48 + q * 4], &g_B2[(size_t)(j0 + row) * 576 + h * 48 + q * 4]);
        }
    };
    loadA(0, 0); loadB(0, 0); cp_commit();
    for (int c = 0; c < 4; c++) {
        int buf = c & 1;
        if (c + 1 < 4) {
            loadA(c + 1, buf ^ 1); loadB(c + 1, buf ^ 1); cp_commit();
            cp_wait<1>();
        } else cp_wait<0>();
        __syncthreads();
        float pacc[2][3];
        #pragma unroll
        for (int a = 0; a < 2; a++)
            #pragma unroll
            for (int b = 0; b < 3; b++) pacc[a][b] = 0.f;
        #pragma unroll 8
        for (int jl = 0; jl < 32; jl++) {
            float ra[2], rb[3];
            #pragma unroll
            for (int a = 0; a < 2; a++) ra[a] = As[buf][(tr * 2 + a) * 36 + jl];
            #pragma unroll
            for (int b = 0; b < 3; b++) rb[b] = Bs[buf][jl * 48 + tc * 3 + b];
            #pragma unroll
            for (int a = 0; a < 2; a++)
                #pragma unroll
                for (int b = 0; b < 3; b++) pacc[a][b] += ra[a] * rb[b];
        }
        int js = (jp * 4 + c) >> 1;
        #pragma unroll
        for (int a = 0; a < 2; a++) {
            float f = fS[(tr * 2 + a) * 8 + js];
            #pragma unroll
            for (int b = 0; b < 3; b++) acc[a][b] += f * pacc[a][b];
        }
        __syncthreads();
    }
    float* dst = &g_ovP[((size_t)jp * Nn) * (Hh * 48)];
    #pragma unroll
    for (int a = 0; a < 2; a++) {
        int i = i0 + tr * 2 + a;
        #pragma unroll
        for (int b = 0; b < 3; b++) {
            int c = tc * 3 + b;
            dst[(size_t)i * (Hh * 48) + h * 48 + c] = acc[a][b];
        }
    }
}

// ---------------- combine2 (+fused post_pt): sum 4 ov partials, route & transform ----------------
__global__ void combine2_k(const float* __restrict__ rot, const float* __restrict__ trans) {
    int i = blockIdx.x, tid = threadIdx.x;
    const size_t S = (size_t)Nn * Hh * 48;
    const size_t ibase = (size_t)i * (Hh * 48);
    // o_v -> concat[0:192)
    for (int t = tid; t < 192; t += 256) {
        int h = t >> 4, c = t & 15;
        size_t base = ibase + h * 48 + c;
        float s = g_ovP[base] + g_ovP[S + base] + g_ovP[2 * S + base] + g_ovP[3 * S + base];
        g_concat[(size_t)i * OUTD + h * Cc + c] = s;
    }
    // o_pt -> local frame + norms
    if (tid < 96) {
        int t = tid;  // h*8+p
        float pt[3];
        #pragma unroll
        for (int a = 0; a < 3; a++) {
            size_t base = ibase + (t >> 3) * 48 + 16 + (t & 7) * 3 + a;
            pt[a] = g_ovP[base] + g_ovP[S + base] + g_ovP[2 * S + base] + g_ovP[3 * S + base];
        }
        float b0 = pt[0] - trans[i * 3 + 0];
        float b1 = pt[1] - trans[i * 3 + 1];
        float b2 = pt[2] - trans[i * 3 + 2];
        float l0 = rot[i * 9 + 0] * b0 + rot[i * 9 + 3] * b1 + rot[i * 9 + 6] * b2;
        float l1 = rot[i * 9 + 1] * b0 + rot[i * 9 + 4] * b1 + rot[i * 9 + 7] * b2;
        float l2 = rot[i * 9 + 2] * b0 + rot[i * 9 + 5] * b1 + rot[i * 9 + 8] * b2;
        float* crow = &g_concat[(size_t)i * OUTD];
        crow[192 + t * 3 + 0] = l0;
        crow[192 + t * 3 + 1] = l1;
        crow[192 + t * 3 + 2] = l2;
        crow[480 + t] = sqrtf(l0 * l0 + l1 * l1 + l2 * l2 + 1e-8f);
    }
}

// ---------------- layer norms ----------------
__device__ __forceinline__ float blockSum384(float v, float* red) {
    int tid = threadIdx.x;
    red[tid] = v;
    if (tid < 128) red[384 + tid] = 0.f;
    __syncthreads();
    for (int s = 256; s > 0; s >>= 1) {
        if (tid < s) red[tid] += red[tid + s];
        __syncthreads();
    }
    float r = red[0];
    __syncthreads();
    return r;
}

__global__ void ln1_k(const float* __restrict__ single_in, const float* __restrict__ bo,
                      const float* __restrict__ g, const float* __restrict__ b) {
    __shared__ float red[512];
    int row = blockIdx.x, tid = threadIdx.x;
    float x = single_in[row * CSd + tid] + bo[tid];
    #pragma unroll
    for (int z = 0; z < 4; z++) x += g_wop[(size_t)z * Nn * CSd + row * CSd + tid];
    float mean = blockSum384(x, red) * (1.f / CSd);
    float dx = x - mean;
    float var = blockSum384(dx * dx, red) * (1.f / CSd);
    g_s1[row * CSd + tid] = dx * rsqrtf(var + 1e-5f) * g[tid] + b[tid];
}

__global__ void ln2_k(const float* __restrict__ g, const float* __restrict__ b,
                      float* __restrict__ out) {
    __shared__ float red[512];
    int row = blockIdx.x, tid = threadIdx.x;
    float x = g_s1[row * CSd + tid] + g_h3[row * CSd + tid];
    float mean = blockSum384(x, red) * (1.f / CSd);
    float dx = x - mean;
    float var = blockSum384(dx * dx, red) * (1.f / CSd);
    float y = dx * rsqrtf(var + 1e-5f) * g[tid] + b[tid];
    out[row * CSd + tid] = y;
    g_s2[row * CSd + tid] = y;
}

// ---------------- backbone update ----------------
__global__ void update_k(const float* __restrict__ rot, const float* __restrict__ trans,
                         const float* __restrict__ Wbu, const float* __restrict__ bbu,
                         float* __restrict__ out) {
    int gtid = blockIdx.x * blockDim.x + threadIdx.x;
    int n = gtid >> 5, lane = gtid & 31;
    if (n >= Nn) return;
    float u[6] = {0, 0, 0, 0, 0, 0};
    for (int s = lane; s < CSd; s += 32) {
        float x = g_s2[n * CSd + s];
        #pragma unroll
        for (int j = 0; j < 6; j++) u[j] += x * Wbu[s * 6 + j];
    }
    #pragma unroll
    for (int j = 0; j < 6; j++)
        #pragma unroll
        for (int off = 16; off; off >>= 1) u[j] += __shfl_xor_sync(0xffffffffu, u[j], off);
    if (lane != 0) return;
    #pragma unroll
    for (int j = 0; j < 6; j++) u[j] += bbu[j];
    float b = u[0], c = u[1], d = u[2];
    float inq = rsqrtf(1.f + b * b + c * c + d * d);
    float a = inq; b *= inq; c *= inq; d *= inq;
    float R[9] = {
        a*a + b*b - c*c - d*d, 2.f*(b*c - a*d),       2.f*(b*d + a*c),
        2.f*(b*c + a*d),       a*a - b*b + c*c - d*d, 2.f*(c*d - a*b),
        2.f*(b*d - a*c),       2.f*(c*d + a*b),       a*a - b*b - c*c + d*d };
    float rn[9];
    #pragma unroll
    for (int aa = 0; aa < 3; aa++)
        #pragma unroll
        for (int cc = 0; cc < 3; cc++) {
            float s2 = 0.f;
            #pragma unroll
            for (int bx = 0; bx < 3; bx++) s2 += rot[n * 9 + aa * 3 + bx] * R[bx * 3 + cc];
            rn[aa * 3 + cc] = s2;
        }
    float t0 = u[3], t1 = u[4], t2 = u[5];
    float tn[3];
    #pragma unroll
    for (int aa = 0; aa < 3; aa++)
        tn[aa] = rot[n * 9 + aa * 3 + 0] * t0 + rot[n * 9 + aa * 3 + 1] * t1 +
                 rot[n * 9 + aa * 3 + 2] * t2 + trans[n * 3 + aa];
    #pragma unroll
    for (int e = 0; e < 9; e++) { g_rotn[n * 9 + e] = rn[e]; out[Nn * CSd + n * 9 + e] = rn[e]; }
    #pragma unroll
    for (int e = 0; e < 3; e++) { g_trn[n * 3 + e] = tn[e]; out[Nn * CSd + Nn * 9 + n * 3 + e] = tn[e]; }
}

// ---------------- loss ----------------
__global__ void loss_part_k(const float* __restrict__ rt, const float* __restrict__ tt) {
    int i = blockIdx.x, tid = threadIdx.x;
    __shared__ float red[256];
    float rn[9], rte[9], tni[3], tti[3];
    #pragma unroll
    for (int e = 0; e < 9; e++) { rn[e] = g_rotn[i * 9 + e]; rte[e] = rt[i * 9 + e]; }
    #pragma unroll
    for (int e = 0; e < 3; e++) { tni[e] = g_trn[i * 3 + e]; tti[e] = tt[i * 3 + e]; }
    float s = 0.f;
    for (int j = tid; j < Nn; j += 256) {
        float db0 = g_trn[j * 3 + 0] - tni[0];
        float db1 = g_trn[j * 3 + 1] - tni[1];
        float db2 = g_trn[j * 3 + 2] - tni[2];
        float dp0 = rn[0] * db0 + rn[3] * db1 + rn[6] * db2;
        float dp1 = rn[1] * db0 + rn[4] * db1 + rn[7] * db2;
        float dp2 = rn[2] * db0 + rn[5] * db1 + rn[8] * db2;
        float eb0 = tt[j * 3 + 0] - tti[0];
        float eb1 = tt[j * 3 + 1] - tti[1];
        float eb2 = tt[j * 3 + 2] - tti[2];
        float dt0 = rte[0] * eb0 + rte[3] * eb1 + rte[6] * eb2;
        float dt1 = rte[1] * eb0 + rte[4] * eb1 + rte[7] * eb2;
        float dt2 = rte[2] * eb0 + rte[5] * eb1 + rte[8] * eb2;
        float d0 = dp0 - dt0, d1 = dp1 - dt1, d2 = dp2 - dt2;
        float dd = sqrtf(d0 * d0 + d1 * d1 + d2 * d2 + 1e-12f);
        s += fminf(dd, 10.f);
    }
    red[tid] = s; __syncthreads();
    for (int st = 128; st > 0; st >>= 1) {
        if (tid < st) red[tid] += red[tid + st];
        __syncthreads();
    }
    if (tid == 0) g_partial[i] = red[0];
}

__global__ void loss_final_k(float* __restrict__ out) {
    __shared__ float red[512];
    int tid = threadIdx.x;
    red[tid] = g_partial[tid];
    __syncthreads();
    for (int s = 256; s > 0; s >>= 1) {
        if (tid < s) red[tid] += red[tid + s];
        __syncthreads();
    }
    if (tid == 0)
        out[Nn * CSd + Nn * 9 + Nn * 3] = red[0] / ((float)Nn * (float)Nn) * 0.1f;
}

// ---------------- host ----------------
template <typename T>
static float* symaddr(T& sym) {
    void* p = nullptr;
    cudaGetSymbolAddress(&p, sym);
    return (float*)p;
}

extern "C" void kernel_launch(void* const* d_in, const int* in_sizes, int n_in,
                              void* d_out, int out_size) {
    const float* single      = (const float*)d_in[0];
    const float* pair        = (const float*)d_in[1];
    const float* rot         = (const float*)d_in[2];
    const float* trans       = (const float*)d_in[3];
    const float* rot_truth   = (const float*)d_in[4];
    const float* trans_truth = (const float*)d_in[5];
    const float* Wq  = (const float*)d_in[6];
    const float* Wk  = (const float*)d_in[7];
    const float* Wv  = (const float*)d_in[8];
    const float* Wqp = (const float*)d_in[9];
    const float* Wkp = (const float*)d_in[10];
    const float* Wvp = (const float*)d_in[11];
    const float* Wb  = (const float*)d_in[12];
    const float* Wo  = (const float*)d_in[13];
    const float* bo  = (const float*)d_in[14];
    const float* gamma_raw = (const float*)d_in[15];
    const float* ln1_g = (const float*)d_in[16];
    const float* ln1_b = (const float*)d_in[17];
    const float* ln2_g = (const float*)d_in[18];
    const float* ln2_b = (const float*)d_in[19];
    const float* W1 = (const float*)d_in[20];
    const float* b1 = (const float*)d_in[21];
    const float* W2 = (const float*)d_in[22];
    const float* b2 = (const float*)d_in[23];
    const float* W3 = (const float*)d_in[24];
    const float* b3 = (const float*)d_in[25];
    const float* Wbu = (const float*)d_in[26];
    const float* bbu = (const float*)d_in[27];
    float* out = (float*)d_out;

    float* pProj   = symaddr(g_proj);
    float* pConcat = symaddr(g_concat);
    float* pS1     = symaddr(g_s1);
    float* pH1     = symaddr(g_h1);
    float* pH2     = symaddr(g_h2);
    float* pH3     = symaddr(g_h3);

    const int FLASH2_SMEM = (8448 + 1584 + 768 + 3200) * 4;   // 56000
    cudaFuncSetAttribute(flash2_k, cudaFuncAttributeMaxDynamicSharedMemorySize, FLASH2_SMEM);

    proj_gemm_k<<<dim3(PROJD/64, Nn/64), 256>>>(single, Wq, Wk, Wv, Wqp, Wkp, Wvp, pProj);
    prep_k<<<Nn, 128>>>(rot, trans, gamma_raw);
    core_k<<<dim3(Nn/128, Nn/64, Hh), 256>>>();

    flash2_k<<<dim3(Nn, 8), 256, FLASH2_SMEM>>>(pair, Wb);   // profiler slot 4
    combine_k<<<Nn, 256>>>();
    ov_k<<<dim3(Nn/32, Hh, 4), 256>>>();
    combine2_k<<<Nn, 256>>>(rot, trans);

    sgemm_k<64,64,16,4,4,false,false,true><<<dim3(CSd/64, Nn/64, 4), 256>>>(
        pConcat, Wo, nullptr, symaddr(g_wop), Nn, CSd, OUTD, OUTD/4);
    ln1_k<<<Nn, CSd>>>(single, bo, ln1_g, ln1_b);

    sgemm_k<32,64,16,2,4,true,true,false><<<dim3(CSd/64, Nn/32, 1), 256>>>(
        pS1, W1, b1, pH1, Nn, CSd, CSd, CSd);
    sgemm_k<32,64,16,2,4,true,true,false><<<dim3(CSd/64, Nn/32, 1), 256>>>(
        pH1, W2, b2, pH2, Nn, CSd, CSd, CSd);
    sgemm_k<32,64,16,2,4,true,false,false><<<dim3(CSd/64, Nn/32, 1), 256>>>(
        pH2, W3, b3, pH3, Nn, CSd, CSd, CSd);
    ln2_k<<<Nn, CSd>>>(ln2_g, ln2_b, out);

    update_k<<<(Nn * 32 + 127) / 128, 128>>>(rot, trans, Wbu, bbu, out);
    loss_part_k<<<Nn, 256>>>(rot_truth, trans_truth);
    loss_final_k<<<1, 512>>>(out);
}

// round 14
// speedup vs baseline: 1.0287x; 1.0003x over previous
#include <cuda_runtime.h>
#include <math.h>

#define Nn 512
#define CSd 384
#define CZd 128
#define Hh 12
#define Cc 16
#define PQd 4
#define PVd 8
#define OUTD 2112
#define PROJD 1152
#define OQ 0
#define OK0 192
#define OV 384
#define OQP 576
#define OKP 720
#define OVP 864

__device__ float g_proj[Nn * PROJD];
__device__ float g_gv[Nn * Hh * PVd * 3];
__device__ float g_B2[Nn * Hh * 48];
__device__ float g_E[Hh * Nn * 32], g_F[Hh * Nn * 32];
__device__ float g_logits[Nn * Hh * Nn];
__device__ float g_opP[8 * Nn * Hh * CZd];
__device__ float g_ovP[4 * Nn * Hh * 48];
__device__ float g_ms[Nn * Hh * 8 * 2];
__device__ float g_fct[Nn * 96];
__device__ float g_concat[Nn * OUTD];
__device__ float g_wop[4 * Nn * CSd];
__device__ float g_s1[Nn * CSd], g_h1[Nn * CSd], g_h2[Nn * CSd], g_h3[Nn * CSd];
__device__ float g_rotn[Nn * 9], g_trn[Nn * 3];
__device__ float g_partial[Nn];

#define WLc 0.5773502691896258f
#define WCc 0.23570226039551584f

__device__ __forceinline__ void cp16(void* smem_dst, const void* gmem_src) {
    unsigned s = (unsigned)__cvta_generic_to_shared(smem_dst);
    asm volatile("cp.async.cg.shared.global [%0], [%1], 16;" :: "r"(s), "l"(gmem_src));
}
__device__ __forceinline__ void cp_commit() { asm volatile("cp.async.commit_group;"); }
template<int N> __device__ __forceinline__ void cp_wait() {
    asm volatile("cp.async.wait_group %0;" :: "n"(N));
}

// ---------------- generic double-buffered tiled SGEMM ----------------
template<int BM, int BN, int BK, int TM, int TN, bool BIAS, bool RELU, bool SPLITK>
__global__ void sgemm_k(const float* __restrict__ A, const float* __restrict__ B,
                        const float* __restrict__ bias, float* __restrict__ C,
                        int M, int N, int K, int KC) {
    const int THREADS = (BM / TM) * (BN / TN);
    __shared__ float As[2][BK][BM];
    __shared__ float Bs[2][BK][BN + 4];
    int n0 = blockIdx.x * BN, m0 = blockIdx.y * BM;
    int kstart = SPLITK ? blockIdx.z * KC : 0;
    if (SPLITK) C += (size_t)blockIdx.z * M * N;
    int tid = threadIdx.x;
    int tr = tid / (BN / TN), tc = tid % (BN / TN);
    float acc[TM][TN];
    #pragma unroll
    for (int i = 0; i < TM; i++)
        #pragma unroll
        for (int j = 0; j < TN; j++) acc[i][j] = 0.f;
    int nsteps = KC / BK;

    auto loadA = [&](int kt, int buf) {
        #pragma unroll
        for (int r = tid; r < BM * BK / 4; r += THREADS) {
            int arow = r / (BK / 4), aq = r % (BK / 4);
            float4 v = *(const float4*)&A[(size_t)(m0 + arow) * K + kstart + kt * BK + aq * 4];
            As[buf][aq * 4 + 0][arow] = v.x; As[buf][aq * 4 + 1][arow] = v.y;
            As[buf][aq * 4 + 2][arow] = v.z; As[buf][aq * 4 + 3][arow] = v.w;
        }
    };
    auto loadB = [&](int kt, int buf) {
        #pragma unroll
        for (int r = tid; r < BK * BN / 4; r += THREADS) {
            int brow = r / (BN / 4), bq = r % (BN / 4);
            cp16(&Bs[buf][brow][bq * 4], &B[(size_t)(kstart + kt * BK + brow) * N + n0 + bq * 4]);
        }
    };
    loadA(0, 0); loadB(0, 0); cp_commit();
    for (int kt = 0; kt < nsteps; kt++) {
        int buf = kt & 1;
        if (kt + 1 < nsteps) {
            loadA(kt + 1, buf ^ 1); loadB(kt + 1, buf ^ 1); cp_commit();
            cp_wait<1>();
        } else cp_wait<0>();
        __syncthreads();
        #pragma unroll
        for (int k = 0; k < BK; k++) {
            float ra[TM], rb[TN];
            if constexpr (TM % 4 == 0) {
                #pragma unroll
                for (int i = 0; i < TM; i += 4)
                    *(float4*)&ra[i] = *(const float4*)&As[buf][k][tr * TM + i];
            } else {
                #pragma unroll
                for (int i = 0; i < TM; i++) ra[i] = As[buf][k][tr * TM + i];
            }
            #pragma unroll
            for (int j = 0; j < TN; j += 4)
                *(float4*)&rb[j] = *(const float4*)&Bs[buf][k][tc * TN + j];
            #pragma unroll
            for (int i = 0; i < TM; i++)
                #pragma unroll
                for (int j = 0; j < TN; j++) acc[i][j] += ra[i] * rb[j];
        }
        __syncthreads();
    }
    #pragma unroll
    for (int i = 0; i < TM; i++) {
        int m = m0 + tr * TM + i;
        #pragma unroll
        for (int j = 0; j < TN; j++) {
            int n = n0 + tc * TN + j;
            float v = acc[i][j];
            if (BIAS) v += bias[n];
            if (RELU) v = fmaxf(v, 0.f);
            C[(size_t)m * N + n] = v;
        }
    }
}

// ---------------- projection GEMM with fused 6-way weight gather ----------------
__device__ __forceinline__ const float* wf_ptr(
    const float* Wq, const float* Wk, const float* Wv,
    const float* Wqp, const float* Wkp, const float* Wvp, int kk, int n) {
    if (n < 192) return Wq  + kk * 192 + n;
    if (n < 384) return Wk  + kk * 192 + (n - 192);
    if (n < 576) return Wv  + kk * 192 + (n - 384);
    if (n < 720) return Wqp + kk * 144 + (n - 576);
    if (n < 864) return Wkp + kk * 144 + (n - 720);
    return Wvp + kk * 288 + (n - 864);
}

__global__ void proj_gemm_k(const float* __restrict__ A,
                            const float* __restrict__ Wq, const float* __restrict__ Wk,
                            const float* __restrict__ Wv, const float* __restrict__ Wqp,
                            const float* __restrict__ Wkp, const float* __restrict__ Wvp,
                            float* __restrict__ C) {
    const int BM = 64, BN = 64, BK = 16;
    __shared__ float As[2][BK][BM];
    __shared__ float Bs[2][BK][BN + 4];
    int n0 = blockIdx.x * BN, m0 = blockIdx.y * BM;
    int tid = threadIdx.x;
    int tr = tid / 16, tc = tid % 16;
    float acc[4][4];
    #pragma unroll
    for (int i = 0; i < 4; i++)
        #pragma unroll
        for (int j = 0; j < 4; j++) acc[i][j] = 0.f;
    auto loadA = [&](int kt, int buf) {
        for (int r = tid; r < BM * BK / 4; r += 256) {
            int arow = r / 4, aq = r % 4;
            float4 v = *(const float4*)&A[(size_t)(m0 + arow) * CSd + kt * BK + aq * 4];
            As[buf][aq * 4 + 0][arow] = v.x; As[buf][aq * 4 + 1][arow] = v.y;
            As[buf][aq * 4 + 2][arow] = v.z; As[buf][aq * 4 + 3][arow] = v.w;
        }
    };
    auto loadB = [&](int kt, int buf) {
        for (int r = tid; r < BK * BN / 4; r += 256) {
            int brow = r / 16, bq = r % 16;
            cp16(&Bs[buf][brow][bq * 4],
                 wf_ptr(Wq, Wk, Wv, Wqp, Wkp, Wvp, kt * BK + brow, n0 + bq * 4));
        }
    };
    loadA(0, 0); loadB(0, 0); cp_commit();
    const int nsteps = CSd / BK;
    for (int kt = 0; kt < nsteps; kt++) {
        int buf = kt & 1;
        if (kt + 1 < nsteps) {
            loadA(kt + 1, buf ^ 1); loadB(kt + 1, buf ^ 1); cp_commit();
            cp_wait<1>();
        } else cp_wait<0>();
        __syncthreads();
        #pragma unroll
        for (int k = 0; k < BK; k++) {
            float ra[4], rb[4];
            *(float4*)ra = *(const float4*)&As[buf][k][tr * 4];
            *(float4*)rb = *(const float4*)&Bs[buf][k][tc * 4];
            #pragma unroll
            for (int i = 0; i < 4; i++)
                #pragma unroll
                for (int j = 0; j < 4; j++) acc[i][j] += ra[i] * rb[j];
        }
        __syncthreads();
    }
    #pragma unroll
    for (int i = 0; i < 4; i++)
        #pragma unroll
        for (int j = 0; j < 4; j++)
            C[(size_t)(m0 + tr * 4 + i) * PROJD + n0 + tc * 4 + j] = acc[i][j];
}

// ---------------- prep: frames + E/F + packed B2 ----------------
__global__ void prep_k(const float* __restrict__ rot, const float* __restrict__ trans,
                       const float* __restrict__ gamma_raw) {
    __shared__ float R[9], T[3], gqS[144], gkS[144], sqqS[12], sqkS[12], wcgS[12];
    int n = blockIdx.x, tid = threadIdx.x;
    if (tid < 9) R[tid] = rot[n * 9 + tid];
    if (tid < 3) T[tid] = trans[n * 3 + tid];
    if (tid >= 16 && tid < 28) {
        int h = tid - 16;
        float x = gamma_raw[h];
        wcgS[h] = WCc * ((x > 20.f) ? x : log1pf(expf(x)));
    }
    __syncthreads();
    const float* base = &g_proj[(size_t)n * PROJD];
    for (int t = tid; t < 96; t += 128) {
        int which = t / 48, p = t % 48;
        const float* src = base + (which ? OKP : OQP) + p * 3;
        float b0 = src[0], b1 = src[1], b2 = src[2];
        float* dst = (which ? gkS : gqS) + p * 3;
        #pragma unroll
        for (int a = 0; a < 3; a++)
            dst[a] = R[a * 3 + 0] * b0 + R[a * 3 + 1] * b1 + R[a * 3 + 2] * b2 + T[a];
    }
    for (int t = tid; t < 96; t += 128) {
        int h = t >> 3, p = t & 7;
        const float* src = base + OVP + t * 3;
        float b0 = src[0], b1 = src[1], b2 = src[2];
        #pragma unroll
        for (int a = 0; a < 3; a++) {
            float v = R[a * 3 + 0] * b0 + R[a * 3 + 1] * b1 + R[a * 3 + 2] * b2 + T[a];
            g_gv[n * 288 + t * 3 + a] = v;
            g_B2[n * 576 + h * 48 + 16 + p * 3 + a] = v;
        }
    }
    for (int t = tid; t < 192; t += 128) {
        int h = t >> 4, c = t & 15;
        g_B2[n * 576 + h * 48 + c] = base[OV + t];
    }
    for (int t = tid; t < 96; t += 128) {
        int h = t / 8, c = 40 + (t % 8);
        g_B2[n * 576 + h * 48 + c] = 0.f;
    }
    __syncthreads();
    if (tid < 24) {
        int h = tid >> 1, which = tid & 1;
        const float* g = (which ? gkS : gqS) + h * 12;
        float s = 0.f;
        #pragma unroll
        for (int e = 0; e < 12; e++) s += g[e] * g[e];
        (which ? sqkS : sqqS)[h] = s;
    }
    __syncthreads();
    for (int t = tid; t < Hh * 32; t += 128) {
        int h = t >> 5, c = t & 31;
        float wcg = wcgS[h];
        float e, f;
        if (c < 16)      { e = 0.25f * base[OQ + h * 16 + c]; f = base[OK0 + h * 16 + c]; }
        else if (c < 28) { e = wcg * gqS[h * 12 + c - 16];    f = gkS[h * 12 + c - 16]; }
        else if (c == 28){ e = sqqS[h];                        f = -0.5f * wcg; }
        else if (c == 29){ e = 1.f;                            f = -0.5f * wcg * sqkS[h]; }
        else             { e = 0.f;                            f = 0.f; }
        g_E[(size_t)((h << 9) | n) * 32 + c] = e;
        g_F[(size_t)((h << 9) | n) * 32 + c] = f;
    }
}

// ---------------- logit core: 64i x 128j tile, acc 4x8 ----------------
__global__ void core_k() {
    __shared__ float As[32][64], BsT[32][128];
    int h = blockIdx.z, i0 = blockIdx.y * 64, j0 = blockIdx.x * 128;
    int tid = threadIdx.x;
    const float* Eh = &g_E[((size_t)h * Nn + i0) * 32];
    const float* Fh = &g_F[((size_t)h * Nn + j0) * 32];
    for (int t = tid; t < 512; t += 256) {
        int row = t >> 3, d4 = t & 7;
        float4 v = *(const float4*)&Eh[row * 32 + d4 * 4];
        As[d4 * 4 + 0][row] = v.x; As[d4 * 4 + 1][row] = v.y;
        As[d4 * 4 + 2][row] = v.z; As[d4 * 4 + 3][row] = v.w;
    }
    for (int t = tid; t < 1024; t += 256) {
        int row = t >> 3, d4 = t & 7;
        float4 w = *(const float4*)&Fh[row * 32 + d4 * 4];
        BsT[d4 * 4 + 0][row] = w.x; BsT[d4 * 4 + 1][row] = w.y;
        BsT[d4 * 4 + 2][row] = w.z; BsT[d4 * 4 + 3][row] = w.w;
    }
    __syncthreads();
    int tr = tid >> 4, tc = tid & 15;
    float acc[4][8];
    #pragma unroll
    for (int i = 0; i < 4; i++)
        #pragma unroll
        for (int j = 0; j < 8; j++) acc[i][j] = 0.f;
    #pragma unroll
    for (int d = 0; d < 32; d++) {
        float ra[4], rb[8];
        *(float4*)ra = *(const float4*)&As[d][tr * 4];
        *(float4*)&rb[0] = *(const float4*)&BsT[d][tc * 8];
        *(float4*)&rb[4] = *(const float4*)&BsT[d][tc * 8 + 4];
        #pragma unroll
        for (int i = 0; i < 4; i++)
            #pragma unroll
            for (int j = 0; j < 8; j++) acc[i][j] += ra[i] * rb[j];
    }
    #pragma unroll
    for (int i = 0; i < 4; i++) {
        size_t rowb = ((size_t)(i0 + tr * 4 + i) * Hh + h) * Nn + j0 + tc * 8;
        float4 v0 = make_float4(WLc * acc[i][0], WLc * acc[i][1], WLc * acc[i][2], WLc * acc[i][3]);
        float4 v1 = make_float4(WLc * acc[i][4], WLc * acc[i][5], WLc * acc[i][6], WLc * acc[i][7]);
        *(float4*)&g_logits[rowb] = v0;
        *(float4*)&g_logits[rowb + 4] = v1;
    }
}

// ---------------- FLASH2: bias + local softmax + o_pair (6h x 4z, 4 j-quarters) ----------------
// grid (Nn, 8), 256 thr. smem: pairS[64*132] WbT[12*132] lS[12*64] comb[4*32*25]
__global__ void __launch_bounds__(256) flash2_k(const float* __restrict__ pair,
                                                const float* __restrict__ Wb) {
    extern __shared__ float sm[];
    float* pairS = sm;                  // 8448
    float* WbT   = pairS + 8448;        // 1584
    float* lS    = WbT + 1584;          // 768
    float* comb  = lS + 768;            // 3200
    int i = blockIdx.x, js = blockIdx.y, j0 = js << 6;
    int tid = threadIdx.x;
    int w = tid >> 5, lane = tid & 31;

    for (int r = tid; r < 64 * 32; r += 256) {
        int row = r >> 5, q = r & 31;
        cp16(&pairS[row * 132 + q * 4], &pair[((size_t)i * Nn + j0 + row) * CZd + q * 4]);
    }
    cp_commit();
    for (int t = tid; t < CZd * Hh; t += 256) WbT[(t % Hh) * 132 + (t / Hh)] = Wb[t];
    if (tid < 192) {
        int h = tid >> 4, q = tid & 15;
        *(float4*)&lS[h * 64 + q * 4] =
            *(const float4*)&g_logits[((size_t)i * Hh + h) * Nn + j0 + q * 4];
    }

    // ---- bias: warp w = z-group (16 z), lane = j (2 j) ----
    float acc0[12], acc1[12];
    #pragma unroll
    for (int h = 0; h < 12; h++) { acc0[h] = 0.f; acc1[h] = 0.f; }

    cp_wait<0>();
    __syncthreads();
    {
        const float4* ap0 = (const float4*)&pairS[lane * 132 + w * 16];
        const float4* ap1 = (const float4*)&pairS[(lane + 32) * 132 + w * 16];
        #pragma unroll
        for (int z4 = 0; z4 < 4; z4++) {
            float4 p0 = ap0[z4], p1 = ap1[z4];
            #pragma unroll
            for (int h = 0; h < 12; h++) {
                float4 wv = *(const float4*)&WbT[h * 132 + w * 16 + z4 * 4];
                acc0[h] += p0.x * wv.x + p0.y * wv.y + p0.z * wv.z + p0.w * wv.w;
                acc1[h] += p1.x * wv.x + p1.y * wv.y + p1.z * wv.z + p1.w * wv.w;
            }
        }
    }
    if (w >= 4) {
        float* c = &comb[((w - 4) * 32 + lane) * 25];
        #pragma unroll
        for (int h = 0; h < 12; h++) { c[h] = acc0[h]; c[12 + h] = acc1[h]; }
    }
    __syncthreads();
    if (w < 4) {
        const float* c = &comb[(w * 32 + lane) * 25];
        #pragma unroll
        for (int h = 0; h < 12; h++) { acc0[h] += c[h]; acc1[h] += c[12 + h]; }
    }
    __syncthreads();
    if (w >= 1 && w < 4) {
        float* c = &comb[((w - 1) * 32 + lane) * 25];
        #pragma unroll
        for (int h = 0; h < 12; h++) { c[h] = acc0[h]; c[12 + h] = acc1[h]; }
    }
    __syncthreads();
    if (w == 0) {
        #pragma unroll
        for (int h = 0; h < 12; h++) {
            float s0 = acc0[h], s1 = acc1[h];
            #pragma unroll
            for (int g = 0; g < 3; g++) {
                const float* c = &comb[(g * 32 + lane) * 25];
                s0 += c[h]; s1 += c[12 + h];
            }
            lS[h * 64 + lane] += WLc * s0;
            lS[h * 64 + 32 + lane] += WLc * s1;
        }
    }
    __syncthreads();

    // ---- local softmax: warp w -> head w; warps 0..3 also head 8+w ----
    #pragma unroll
    for (int rep = 0; rep < 2; rep++) {
        int h = w + rep * 8;
        if (h < Hh) {
            float l0 = lS[h * 64 + lane], l1 = lS[h * 64 + 32 + lane];
            float m = fmaxf(l0, l1);
            #pragma unroll
            for (int off = 16; off; off >>= 1) m = fmaxf(m, __shfl_xor_sync(0xffffffffu, m, off));
            float e0 = __expf(l0 - m), e1 = __expf(l1 - m);
            float s = e0 + e1;
            #pragma unroll
            for (int off = 16; off; off >>= 1) s += __shfl_xor_sync(0xffffffffu, s, off);
            lS[h * 64 + lane] = e0;
            lS[h * 64 + 32 + lane] = e1;
            size_t gb = ((size_t)i * Hh + h) * Nn + j0;
            g_logits[gb + lane] = e0;
            g_logits[gb + 32 + lane] = e1;
            if (lane == 0) {
                int msb = (((i * Hh) + h) * 8 + js) * 2;
                g_ms[msb] = m;
                g_ms[msb + 1] = s;
            }
        }
    }
    __syncthreads();

    // ---- o_pair: 4 j-quarters (16 j); thread = (htg 6h) x (zz 4z float4) ----
    int jq = tid >> 6, rem = tid & 63, htg = rem >> 5, zz = rem & 31;
    int hb = htg * 6;
    float a6[6][4];
    #pragma unroll
    for (int b = 0; b < 6; b++)
        #pragma unroll
        for (int a = 0; a < 4; a++) a6[b][a] = 0.f;
    {
        int jb = jq * 16;
        #pragma unroll 4
        for (int l = 0; l < 16; l++) {
            int j = jb + l;
            float4 p = *(const float4*)&pairS[j * 132 + zz * 4];
            #pragma unroll
            for (int b = 0; b < 6; b++) {
                float v = lS[(hb + b) * 64 + j];
                a6[b][0] += v * p.x; a6[b][1] += v * p.y;
                a6[b][2] += v * p.z; a6[b][3] += v * p.w;
            }
        }
    }
    // 3-round combine over 4 j-quarters (comb rows stride 25, 24 payload)
    if (jq >= 2) {
        float* c = &comb[((jq - 2) * 64 + rem) * 25];
        #pragma unroll
        for (int b = 0; b < 6; b++)
            #pragma unroll
            for (int a = 0; a < 4; a++) c[b * 4 + a] = a6[b][a];
    }
    __syncthreads();
    if (jq < 2) {
        const float* c = &comb[(jq * 64 + rem) * 25];
        #pragma unroll
        for (int b = 0; b < 6; b++)
            #pragma unroll
            for (int a = 0; a < 4; a++) a6[b][a] += c[b * 4 + a];
    }
    __syncthreads();
    if (jq == 1) {
        float* c = &comb[rem * 25];
        #pragma unroll
        for (int b = 0; b < 6; b++)
            #pragma unroll
            for (int a = 0; a < 4; a++) c[b * 4 + a] = a6[b][a];
    }
    __syncthreads();
    if (jq == 0) {
        const float* c = &comb[rem * 25];
        float* dst = &g_opP[((size_t)js * Nn + i) * (Hh * CZd)];
        #pragma unroll
        for (int b = 0; b < 6; b++) {
            float4 v;
            v.x = a6[b][0] + c[b * 4 + 0];
            v.y = a6[b][1] + c[b * 4 + 1];
            v.z = a6[b][2] + c[b * 4 + 2];
            v.w = a6[b][3] + c[b * 4 + 3];
            *(float4*)&dst[(hb + b) * CZd + zz * 4] = v;
        }
    }
}

// ---------------- combine: global stats + o_pair; factors -> g_fct ----------------
__global__ void combine_k() {
    __shared__ float fctS[96];
    int i = blockIdx.x, tid = threadIdx.x;
    if (tid < 96) {
        int h = tid >> 3, js = tid & 7;
        float mv[8], sv[8];
        float mg = -1e30f;
        #pragma unroll
        for (int k = 0; k < 8; k++) {
            int b = ((i * Hh + h) * 8 + k) * 2;
            mv[k] = g_ms[b]; sv[k] = g_ms[b + 1];
            mg = fmaxf(mg, mv[k]);
        }
        float sg = 0.f;
        #pragma unroll
        for (int k = 0; k < 8; k++) sg += sv[k] * __expf(mv[k] - mg);
        float f = __expf(mv[js] - mg) / sg;
        fctS[tid] = f;
        g_fct[i * 96 + tid] = f;
    }
    __syncthreads();
    const size_t S = (size_t)Nn * Hh * CZd;
    for (int c = tid; c < Hh * CZd; c += 256) {
        int h = c >> 7;
        float s = 0.f;
        #pragma unroll
        for (int js = 0; js < 8; js++)
            s += fctS[h * 8 + js] * g_opP[js * S + (size_t)i * (Hh * CZd) + c];
        g_concat[(size_t)i * OUTD + 576 + c] = s;
    }
}

// ---------------- o_v & o_pt: 4-way j-split partials ----------------
__global__ void ov_k() {
    __shared__ float As[2][32 * 36];
    __shared__ float Bs[2][32 * 48];
    __shared__ float fS[32 * 8];
    int i0 = blockIdx.x * 32, h = blockIdx.y, jp = blockIdx.z;
    int tid = threadIdx.x;
    int tr = tid / 16, tc = tid % 16;
    {
        int row = tid >> 3, js = tid & 7;
        fS[row * 8 + js] = g_fct[(i0 + row) * 96 + h * 8 + js];
    }
    float acc[2][3];
    #pragma unroll
    for (int a = 0; a < 2; a++)
        #pragma unroll
        for (int b = 0; b < 3; b++) acc[a][b] = 0.f;

    auto loadA = [&](int c, int buf) {
        int j0 = (jp * 4 + c) * 32;
        int row = tid >> 3, q = tid & 7;
        cp16(&As[buf][row * 36 + q * 4],
             &g_logits[((size_t)(i0 + row) * Hh + h) * Nn + j0 + q * 4]);
    };
    auto loadB = [&](int c, int buf) {
        int j0 = (jp * 4 + c) * 32;
        for (int t = tid; t < 384; t += 256) {
            int row = t / 12, q = t % 12;
            cp16(&Bs[buf][row * 48 + q * 4], &g_B2[(size_t)(j0 + row) * 576 + h * 48 + q * 4]);
        }
    };
    loadA(0, 0); loadB(0, 0); cp_commit();
    for (int c = 0; c < 4; c++) {
        int buf = c & 1;
        if (c + 1 < 4) {
            loadA(c + 1, buf ^ 1); loadB(c + 1, buf ^ 1); cp_commit();
            cp_wait<1>();
        } else cp_wait<0>();
        __syncthreads();
        float pacc[2][3];
        #pragma unroll
        for (int a = 0; a < 2; a++)
            #pragma unroll
            for (int b = 0; b < 3; b++) pacc[a][b] = 0.f;
        #pragma unroll 8
        for (int jl = 0; jl < 32; jl++) {
            float ra[2], rb[3];
            #pragma unroll
            for (int a = 0; a < 2; a++) ra[a] = As[buf][(tr * 2 + a) * 36 + jl];
            #pragma unroll
            for (int b = 0; b < 3; b++) rb[b] = Bs[buf][jl * 48 + tc * 3 + b];
            #pragma unroll
            for (int a = 0; a < 2; a++)
                #pragma unroll
                for (int b = 0; b < 3; b++) pacc[a][b] += ra[a] * rb[b];
        }
        int js = (jp * 4 + c) >> 1;
        #pragma unroll
        for (int a = 0; a < 2; a++) {
            float f = fS[(tr * 2 + a) * 8 + js];
            #pragma unroll
            for (int b = 0; b < 3; b++) acc[a][b] += f * pacc[a][b];
        }
        __syncthreads();
    }
    float* dst = &g_ovP[((size_t)jp * Nn) * (Hh * 48)];
    #pragma unroll
    for (int a = 0; a < 2; a++) {
        int i = i0 + tr * 2 + a;
        #pragma unroll
        for (int b = 0; b < 3; b++) {
            int c = tc * 3 + b;
            dst[(size_t)i * (Hh * 48) + h * 48 + c] = acc[a][b];
        }
    }
}

// ---------------- combine2 (+fused post_pt) ----------------
__global__ void combine2_k(const float* __restrict__ rot, const float* __restrict__ trans) {
    int i = blockIdx.x, tid = threadIdx.x;
    const size_t S = (size_t)Nn * Hh * 48;
    const size_t ibase = (size_t)i * (Hh * 48);
    for (int t = tid; t < 192; t += 256) {
        int h = t >> 4, c = t & 15;
        size_t base = ibase + h * 48 + c;
        float s = g_ovP[base] + g_ovP[S + base] + g_ovP[2 * S + base] + g_ovP[3 * S + base];
        g_concat[(size_t)i * OUTD + h * Cc + c] = s;
    }
    if (tid < 96) {
        int t = tid;
        float pt[3];
        #pragma unroll
        for (int a = 0; a < 3; a++) {
            size_t base = ibase + (t >> 3) * 48 + 16 + (t & 7) * 3 + a;
            pt[a] = g_ovP[base] + g_ovP[S + base] + g_ovP[2 * S + base] + g_ovP[3 * S + base];
        }
        float b0 = pt[0] - trans[i * 3 + 0];
        float b1 = pt[1] - trans[i * 3 + 1];
        float b2 = pt[2] - trans[i * 3 + 2];
        float l0 = rot[i * 9 + 0] * b0 + rot[i * 9 + 3] * b1 + rot[i * 9 + 6] * b2;
        float l1 = rot[i * 9 + 1] * b0 + rot[i * 9 + 4] * b1 + rot[i * 9 + 7] * b2;
        float l2 = rot[i * 9 + 2] * b0 + rot[i * 9 + 5] * b1 + rot[i * 9 + 8] * b2;
        float* crow = &g_concat[(size_t)i * OUTD];
        crow[192 + t * 3 + 0] = l0;
        crow[192 + t * 3 + 1] = l1;
        crow[192 + t * 3 + 2] = l2;
        crow[480 + t] = sqrtf(l0 * l0 + l1 * l1 + l2 * l2 + 1e-8f);
    }
}

// ---------------- layer norms ----------------
__device__ __forceinline__ float blockSum384(float v, float* red) {
    int tid = threadIdx.x;
    red[tid] = v;
    if (tid < 128) red[384 + tid] = 0.f;
    __syncthreads();
    for (int s = 256; s > 0; s >>= 1) {
        if (tid < s) red[tid] += red[tid + s];
        __syncthreads();
    }
    float r = red[0];
    __syncthreads();
    return r;
}

__global__ void ln1_k(const float* __restrict__ single_in, const float* __restrict__ bo,
                      const float* __restrict__ g, const float* __restrict__ b) {
    __shared__ float red[512];
    int row = blockIdx.x, tid = threadIdx.x;
    float x = single_in[row * CSd + tid] + bo[tid];
    #pragma unroll
    for (int z = 0; z < 4; z++) x += g_wop[(size_t)z * Nn * CSd + row * CSd + tid];
    float mean = blockSum384(x, red) * (1.f / CSd);
    float dx = x - mean;
    float var = blockSum384(dx * dx, red) * (1.f / CSd);
    g_s1[row * CSd + tid] = dx * rsqrtf(var + 1e-5f) * g[tid] + b[tid];
}

// ---------------- ln2 + backbone update, fused ----------------
__global__ void ln2_update_k(const float* __restrict__ g, const float* __restrict__ bb,
                             const float* __restrict__ rot, const float* __restrict__ trans,
                             const float* __restrict__ Wbu, const float* __restrict__ bbu,
                             float* __restrict__ out) {
    __shared__ float red[512];
    __shared__ float yS[384];
    int row = blockIdx.x, tid = threadIdx.x;
    float x = g_s1[row * CSd + tid] + g_h3[row * CSd + tid];
    float mean = blockSum384(x, red) * (1.f / CSd);
    float dx = x - mean;
    float var = blockSum384(dx * dx, red) * (1.f / CSd);
    float y = dx * rsqrtf(var + 1e-5f) * g[tid] + bb[tid];
    out[row * CSd + tid] = y;
    yS[tid] = y;
    __syncthreads();
    if (tid >= 32) return;
    int lane = tid;
    float u[6] = {0, 0, 0, 0, 0, 0};
    for (int s = lane; s < CSd; s += 32) {
        float xv = yS[s];
        #pragma unroll
        for (int j = 0; j < 6; j++) u[j] += xv * Wbu[s * 6 + j];
    }
    #pragma unroll
    for (int j = 0; j < 6; j++)
        #pragma unroll
        for (int off = 16; off; off >>= 1) u[j] += __shfl_xor_sync(0xffffffffu, u[j], off);
    if (lane != 0) return;
    int n = row;
    #pragma unroll
    for (int j = 0; j < 6; j++) u[j] += bbu[j];
    float b = u[0], c = u[1], d = u[2];
    float inq = rsqrtf(1.f + b * b + c * c + d * d);
    float a = inq; b *= inq; c *= inq; d *= inq;
    float R[9] = {
        a*a + b*b - c*c - d*d, 2.f*(b*c - a*d),       2.f*(b*d + a*c),
        2.f*(b*c + a*d),       a*a - b*b + c*c - d*d, 2.f*(c*d - a*b),
        2.f*(b*d - a*c),       2.f*(c*d + a*b),       a*a - b*b - c*c + d*d };
    float rn[9];
    #pragma unroll
    for (int aa = 0; aa < 3; aa++)
        #pragma unroll
        for (int cc = 0; cc < 3; cc++) {
            float s2 = 0.f;
            #pragma unroll
            for (int bx = 0; bx < 3; bx++) s2 += rot[n * 9 + aa * 3 + bx] * R[bx * 3 + cc];
            rn[aa * 3 + cc] = s2;
        }
    float t0 = u[3], t1 = u[4], t2 = u[5];
    float tn[3];
    #pragma unroll
    for (int aa = 0; aa < 3; aa++)
        tn[aa] = rot[n * 9 + aa * 3 + 0] * t0 + rot[n * 9 + aa * 3 + 1] * t1 +
                 rot[n * 9 + aa * 3 + 2] * t2 + trans[n * 3 + aa];
    #pragma unroll
    for (int e = 0; e < 9; e++) { g_rotn[n * 9 + e] = rn[e]; out[Nn * CSd + n * 9 + e] = rn[e]; }
    #pragma unroll
    for (int e = 0; e < 3; e++) { g_trn[n * 3 + e] = tn[e]; out[Nn * CSd + Nn * 9 + n * 3 + e] = tn[e]; }
}

// ---------------- loss ----------------
__global__ void loss_part_k(const float* __restrict__ rt, const float* __restrict__ tt) {
    int i = blockIdx.x, tid = threadIdx.x;
    __shared__ float red[256];
    float rn[9], rte[9], tni[3], tti[3];
    #pragma unroll
    for (int e = 0; e < 9; e++) { rn[e] = g_rotn[i * 9 + e]; rte[e] = rt[i * 9 + e]; }
    #pragma unroll
    for (int e = 0; e < 3; e++) { tni[e] = g_trn[i * 3 + e]; tti[e] = tt[i * 3 + e]; }
    float s = 0.f;
    for (int j = tid; j < Nn; j += 256) {
        float db0 = g_trn[j * 3 + 0] - tni[0];
        float db1 = g_trn[j * 3 + 1] - tni[1];
        float db2 = g_trn[j * 3 + 2] - tni[2];
        float dp0 = rn[0] * db0 + rn[3] * db1 + rn[6] * db2;
        float dp1 = rn[1] * db0 + rn[4] * db1 + rn[7] * db2;
        float dp2 = rn[2] * db0 + rn[5] * db1 + rn[8] * db2;
        float eb0 = tt[j * 3 + 0] - tti[0];
        float eb1 = tt[j * 3 + 1] - tti[1];
        float eb2 = tt[j * 3 + 2] - tti[2];
        float dt0 = rte[0] * eb0 + rte[3] * eb1 + rte[6] * eb2;
        float dt1 = rte[1] * eb0 + rte[4] * eb1 + rte[7] * eb2;
        float dt2 = rte[2] * eb0 + rte[5] * eb1 + rte[8] * eb2;
        float d0 = dp0 - dt0, d1 = dp1 - dt1, d2 = dp2 - dt2;
        float dd = sqrtf(d0 * d0 + d1 * d1 + d2 * d2 + 1e-12f);
        s += fminf(dd, 10.f);
    }
    red[tid] = s; __syncthreads();
    for (int st = 128; st > 0; st >>= 1) {
        if (tid < st) red[tid] += red[tid + st];
        __syncthreads();
    }
    if (tid == 0) g_partial[i] = red[0];
}

__global__ void loss_final_k(float* __restrict__ out) {
    __shared__ float red[512];
    int tid = threadIdx.x;
    red[tid] = g_partial[tid];
    __syncthreads();
    for (int s = 256; s > 0; s >>= 1) {
        if (tid < s) red[tid] += red[tid + s];
        __syncthreads();
    }
    if (tid == 0)
        out[Nn * CSd + Nn * 9 + Nn * 3] = red[0] / ((float)Nn * (float)Nn) * 0.1f;
}

// ---------------- host ----------------
template <typename T>
static float* symaddr(T& sym) {
    void* p = nullptr;
    cudaGetSymbolAddress(&p, sym);
    return (float*)p;
}

extern "C" void kernel_launch(void* const* d_in, const int* in_sizes, int n_in,
                              void* d_out, int out_size) {
    const float* single      = (const float*)d_in[0];
    const float* pair        = (const float*)d_in[1];
    const float* rot         = (const float*)d_in[2];
    const float* trans       = (const float*)d_in[3];
    const float* rot_truth   = (const float*)d_in[4];
    const float* trans_truth = (const float*)d_in[5];
    const float* Wq  = (const float*)d_in[6];
    const float* Wk  = (const float*)d_in[7];
    const float* Wv  = (const float*)d_in[8];
    const float* Wqp = (const float*)d_in[9];
    const float* Wkp = (const float*)d_in[10];
    const float* Wvp = (const float*)d_in[11];
    const float* Wb  = (const float*)d_in[12];
    const float* Wo  = (const float*)d_in[13];
    const float* bo  = (const float*)d_in[14];
    const float* gamma_raw = (const float*)d_in[15];
    const float* ln1_g = (const float*)d_in[16];
    const float* ln1_b = (const float*)d_in[17];
    const float* ln2_g = (const float*)d_in[18];
    const float* ln2_b = (const float*)d_in[19];
    const float* W1 = (const float*)d_in[20];
    const float* b1 = (const float*)d_in[21];
    const float* W2 = (const float*)d_in[22];
    const float* b2 = (const float*)d_in[23];
    const float* W3 = (const float*)d_in[24];
    const float* b3 = (const float*)d_in[25];
    const float* Wbu = (const float*)d_in[26];
    const float* bbu = (const float*)d_in[27];
    float* out = (float*)d_out;

    float* pProj   = symaddr(g_proj);
    float* pConcat = symaddr(g_concat);
    float* pS1     = symaddr(g_s1);
    float* pH1     = symaddr(g_h1);
    float* pH2     = symaddr(g_h2);
    float* pH3     = symaddr(g_h3);

    const int FLASH2_SMEM = (8448 + 1584 + 768 + 3200) * 4;   // 56000
    cudaFuncSetAttribute(flash2_k, cudaFuncAttributeMaxDynamicSharedMemorySize, FLASH2_SMEM);

    proj_gemm_k<<<dim3(PROJD/64, Nn/64), 256>>>(single, Wq, Wk, Wv, Wqp, Wkp, Wvp, pProj);
    prep_k<<<Nn, 128>>>(rot, trans, gamma_raw);
    core_k<<<dim3(Nn/128, Nn/64, Hh), 256>>>();

    flash2_k<<<dim3(Nn, 8), 256, FLASH2_SMEM>>>(pair, Wb);   // profiler slot 4
    combine_k<<<Nn, 256>>>();
    ov_k<<<dim3(Nn/32, Hh, 4), 256>>>();
    combine2_k<<<Nn, 256>>>(rot, trans);

    sgemm_k<64,64,16,4,4,false,false,true><<<dim3(CSd/64, Nn/64, 4), 256>>>(
        pConcat, Wo, nullptr, symaddr(g_wop), Nn, CSd, OUTD, OUTD/4);
    ln1_k<<<Nn, CSd>>>(single, bo, ln1_g, ln1_b);

    sgemm_k<32,64,16,2,4,true,true,false><<<dim3(CSd/64, Nn/32, 1), 256>>>(
        pS1, W1, b1, pH1, Nn, CSd, CSd, CSd);
    sgemm_k<32,64,16,2,4,true,true,false><<<dim3(CSd/64, Nn/32, 1), 256>>>(
        pH1, W2, b2, pH2, Nn, CSd, CSd, CSd);
    sgemm_k<32,64,16,2,4,true,false,false><<<dim3(CSd/64, Nn/32, 1), 256>>>(
        pH2, W3, b3, pH3, Nn, CSd, CSd, CSd);
    ln2_update_k<<<Nn, CSd>>>(ln2_g, ln2_b, rot, trans, Wbu, bbu, out);

    loss_part_k<<<Nn, 256>>>(rot_truth, trans_truth);
    loss_final_k<<<1, 512>>>(out);
}

// round 15
// speedup vs baseline: 1.0405x; 1.0115x over previous
#include <cuda_runtime.h>
#include <math.h>

#define Nn 512
#define CSd 384
#define CZd 128
#define Hh 12
#define Cc 16
#define PQd 4
#define PVd 8
#define OUTD 2112
#define PROJD 1152
#define OQ 0
#define OK0 192
#define OV 384
#define OQP 576
#define OKP 720
#define OVP 864

__device__ float g_proj[Nn * PROJD];
__device__ float g_gv[Nn * Hh * PVd * 3];
__device__ float g_B2[Nn * Hh * 48];
__device__ float g_E[Hh * Nn * 32], g_F[Hh * Nn * 32];
__device__ float g_logits[Nn * Hh * Nn];
__device__ float g_opP[8 * Nn * Hh * CZd];
__device__ float g_ovP[4 * Nn * Hh * 48];
__device__ float g_ms[Nn * Hh * 8 * 2];
__device__ float g_fct[Nn * 96];
__device__ float g_concat[Nn * OUTD];
__device__ float g_wop[4 * Nn * CSd];
__device__ float g_s1[Nn * CSd], g_h1[Nn * CSd], g_h2[Nn * CSd], g_h3[Nn * CSd];
__device__ float g_rotn[Nn * 9], g_trn[Nn * 3];
__device__ float g_partial[Nn];

#define WLc 0.5773502691896258f
#define WCc 0.23570226039551584f

__device__ __forceinline__ void cp16(void* smem_dst, const void* gmem_src) {
    unsigned s = (unsigned)__cvta_generic_to_shared(smem_dst);
    asm volatile("cp.async.cg.shared.global [%0], [%1], 16;" :: "r"(s), "l"(gmem_src));
}
__device__ __forceinline__ void cp_commit() { asm volatile("cp.async.commit_group;"); }
template<int N> __device__ __forceinline__ void cp_wait() {
    asm volatile("cp.async.wait_group %0;" :: "n"(N));
}

// ---------------- generic double-buffered tiled SGEMM ----------------
template<int BM, int BN, int BK, int TM, int TN, bool BIAS, bool RELU, bool SPLITK>
__global__ void sgemm_k(const float* __restrict__ A, const float* __restrict__ B,
                        const float* __restrict__ bias, float* __restrict__ C,
                        int M, int N, int K, int KC) {
    const int THREADS = (BM / TM) * (BN / TN);
    __shared__ float As[2][BK][BM];
    __shared__ float Bs[2][BK][BN + 4];
    int n0 = blockIdx.x * BN, m0 = blockIdx.y * BM;
    int kstart = SPLITK ? blockIdx.z * KC : 0;
    if (SPLITK) C += (size_t)blockIdx.z * M * N;
    int tid = threadIdx.x;
    int tr = tid / (BN / TN), tc = tid % (BN / TN);
    float acc[TM][TN];
    #pragma unroll
    for (int i = 0; i < TM; i++)
        #pragma unroll
        for (int j = 0; j < TN; j++) acc[i][j] = 0.f;
    int nsteps = KC / BK;

    auto loadA = [&](int kt, int buf) {
        #pragma unroll
        for (int r = tid; r < BM * BK / 4; r += THREADS) {
            int arow = r / (BK / 4), aq = r % (BK / 4);
            float4 v = *(const float4*)&A[(size_t)(m0 + arow) * K + kstart + kt * BK + aq * 4];
            As[buf][aq * 4 + 0][arow] = v.x; As[buf][aq * 4 + 1][arow] = v.y;
            As[buf][aq * 4 + 2][arow] = v.z; As[buf][aq * 4 + 3][arow] = v.w;
        }
    };
    auto loadB = [&](int kt, int buf) {
        #pragma unroll
        for (int r = tid; r < BK * BN / 4; r += THREADS) {
            int brow = r / (BN / 4), bq = r % (BN / 4);
            cp16(&Bs[buf][brow][bq * 4], &B[(size_t)(kstart + kt * BK + brow) * N + n0 + bq * 4]);
        }
    };
    loadA(0, 0); loadB(0, 0); cp_commit();
    for (int kt = 0; kt < nsteps; kt++) {
        int buf = kt & 1;
        if (kt + 1 < nsteps) {
            loadA(kt + 1, buf ^ 1); loadB(kt + 1, buf ^ 1); cp_commit();
            cp_wait<1>();
        } else cp_wait<0>();
        __syncthreads();
        #pragma unroll
        for (int k = 0; k < BK; k++) {
            float ra[TM], rb[TN];
            if constexpr (TM % 4 == 0) {
                #pragma unroll
                for (int i = 0; i < TM; i += 4)
                    *(float4*)&ra[i] = *(const float4*)&As[buf][k][tr * TM + i];
            } else {
                #pragma unroll
                for (int i = 0; i < TM; i++) ra[i] = As[buf][k][tr * TM + i];
            }
            #pragma unroll
            for (int j = 0; j < TN; j += 4)
                *(float4*)&rb[j] = *(const float4*)&Bs[buf][k][tc * TN + j];
            #pragma unroll
            for (int i = 0; i < TM; i++)
                #pragma unroll
                for (int j = 0; j < TN; j++) acc[i][j] += ra[i] * rb[j];
        }
        __syncthreads();
    }
    #pragma unroll
    for (int i = 0; i < TM; i++) {
        int m = m0 + tr * TM + i;
        #pragma unroll
        for (int j = 0; j < TN; j++) {
            int n = n0 + tc * TN + j;
            float v = acc[i][j];
            if (BIAS) v += bias[n];
            if (RELU) v = fmaxf(v, 0.f);
            C[(size_t)m * N + n] = v;
        }
    }
}

// ---------------- projection GEMM with fused 6-way weight gather ----------------
__device__ __forceinline__ const float* wf_ptr(
    const float* Wq, const float* Wk, const float* Wv,
    const float* Wqp, const float* Wkp, const float* Wvp, int kk, int n) {
    if (n < 192) return Wq  + kk * 192 + n;
    if (n < 384) return Wk  + kk * 192 + (n - 192);
    if (n < 576) return Wv  + kk * 192 + (n - 384);
    if (n < 720) return Wqp + kk * 144 + (n - 576);
    if (n < 864) return Wkp + kk * 144 + (n - 720);
    return Wvp + kk * 288 + (n - 864);
}

__global__ void proj_gemm_k(const float* __restrict__ A,
                            const float* __restrict__ Wq, const float* __restrict__ Wk,
                            const float* __restrict__ Wv, const float* __restrict__ Wqp,
                            const float* __restrict__ Wkp, const float* __restrict__ Wvp,
                            float* __restrict__ C) {
    const int BM = 64, BN = 64, BK = 16;
    __shared__ float As[2][BK][BM];
    __shared__ float Bs[2][BK][BN + 4];
    int n0 = blockIdx.x * BN, m0 = blockIdx.y * BM;
    int tid = threadIdx.x;
    int tr = tid / 16, tc = tid % 16;
    float acc[4][4];
    #pragma unroll
    for (int i = 0; i < 4; i++)
        #pragma unroll
        for (int j = 0; j < 4; j++) acc[i][j] = 0.f;
    auto loadA = [&](int kt, int buf) {
        for (int r = tid; r < BM * BK / 4; r += 256) {
            int arow = r / 4, aq = r % 4;
            float4 v = *(const float4*)&A[(size_t)(m0 + arow) * CSd + kt * BK + aq * 4];
            As[buf][aq * 4 + 0][arow] = v.x; As[buf][aq * 4 + 1][arow] = v.y;
            As[buf][aq * 4 + 2][arow] = v.z; As[buf][aq * 4 + 3][arow] = v.w;
        }
    };
    auto loadB = [&](int kt, int buf) {
        for (int r = tid; r < BK * BN / 4; r += 256) {
            int brow = r / 16, bq = r % 16;
            cp16(&Bs[buf][brow][bq * 4],
                 wf_ptr(Wq, Wk, Wv, Wqp, Wkp, Wvp, kt * BK + brow, n0 + bq * 4));
        }
    };
    loadA(0, 0); loadB(0, 0); cp_commit();
    const int nsteps = CSd / BK;
    for (int kt = 0; kt < nsteps; kt++) {
        int buf = kt & 1;
        if (kt + 1 < nsteps) {
            loadA(kt + 1, buf ^ 1); loadB(kt + 1, buf ^ 1); cp_commit();
            cp_wait<1>();
        } else cp_wait<0>();
        __syncthreads();
        #pragma unroll
        for (int k = 0; k < BK; k++) {
            float ra[4], rb[4];
            *(float4*)ra = *(const float4*)&As[buf][k][tr * 4];
            *(float4*)rb = *(const float4*)&Bs[buf][k][tc * 4];
            #pragma unroll
            for (int i = 0; i < 4; i++)
                #pragma unroll
                for (int j = 0; j < 4; j++) acc[i][j] += ra[i] * rb[j];
        }
        __syncthreads();
    }
    #pragma unroll
    for (int i = 0; i < 4; i++)
        #pragma unroll
        for (int j = 0; j < 4; j++)
            C[(size_t)(m0 + tr * 4 + i) * PROJD + n0 + tc * 4 + j] = acc[i][j];
}

// ---------------- prep: frames + E/F + packed B2 ----------------
__global__ void prep_k(const float* __restrict__ rot, const float* __restrict__ trans,
                       const float* __restrict__ gamma_raw) {
    __shared__ float R[9], T[3], gqS[144], gkS[144], sqqS[12], sqkS[12], wcgS[12];
    int n = blockIdx.x, tid = threadIdx.x;
    if (tid < 9) R[tid] = rot[n * 9 + tid];
    if (tid < 3) T[tid] = trans[n * 3 + tid];
    if (tid >= 16 && tid < 28) {
        int h = tid - 16;
        float x = gamma_raw[h];
        wcgS[h] = WCc * ((x > 20.f) ? x : log1pf(expf(x)));
    }
    __syncthreads();
    const float* base = &g_proj[(size_t)n * PROJD];
    for (int t = tid; t < 96; t += 128) {
        int which = t / 48, p = t % 48;
        const float* src = base + (which ? OKP : OQP) + p * 3;
        float b0 = src[0], b1 = src[1], b2 = src[2];
        float* dst = (which ? gkS : gqS) + p * 3;
        #pragma unroll
        for (int a = 0; a < 3; a++)
            dst[a] = R[a * 3 + 0] * b0 + R[a * 3 + 1] * b1 + R[a * 3 + 2] * b2 + T[a];
    }
    for (int t = tid; t < 96; t += 128) {
        int h = t >> 3, p = t & 7;
        const float* src = base + OVP + t * 3;
        float b0 = src[0], b1 = src[1], b2 = src[2];
        #pragma unroll
        for (int a = 0; a < 3; a++) {
            float v = R[a * 3 + 0] * b0 + R[a * 3 + 1] * b1 + R[a * 3 + 2] * b2 + T[a];
            g_gv[n * 288 + t * 3 + a] = v;
            g_B2[n * 576 + h * 48 + 16 + p * 3 + a] = v;
        }
    }
    for (int t = tid; t < 192; t += 128) {
        int h = t >> 4, c = t & 15;
        g_B2[n * 576 + h * 48 + c] = base[OV + t];
    }
    for (int t = tid; t < 96; t += 128) {
        int h = t / 8, c = 40 + (t % 8);
        g_B2[n * 576 + h * 48 + c] = 0.f;
    }
    __syncthreads();
    if (tid < 24) {
        int h = tid >> 1, which = tid & 1;
        const float* g = (which ? gkS : gqS) + h * 12;
        float s = 0.f;
        #pragma unroll
        for (int e = 0; e < 12; e++) s += g[e] * g[e];
        (which ? sqkS : sqqS)[h] = s;
    }
    __syncthreads();
    for (int t = tid; t < Hh * 32; t += 128) {
        int h = t >> 5, c = t & 31;
        float wcg = wcgS[h];
        float e, f;
        if (c < 16)      { e = 0.25f * base[OQ + h * 16 + c]; f = base[OK0 + h * 16 + c]; }
        else if (c < 28) { e = wcg * gqS[h * 12 + c - 16];    f = gkS[h * 12 + c - 16]; }
        else if (c == 28){ e = sqqS[h];                        f = -0.5f * wcg; }
        else if (c == 29){ e = 1.f;                            f = -0.5f * wcg * sqkS[h]; }
        else             { e = 0.f;                            f = 0.f; }
        g_E[(size_t)((h << 9) | n) * 32 + c] = e;
        g_F[(size_t)((h << 9) | n) * 32 + c] = f;
    }
}

// ---------------- logit core: 64i x 128j tile, acc 4x8 ----------------
__global__ void core_k() {
    __shared__ float As[32][64], BsT[32][128];
    int h = blockIdx.z, i0 = blockIdx.y * 64, j0 = blockIdx.x * 128;
    int tid = threadIdx.x;
    const float* Eh = &g_E[((size_t)h * Nn + i0) * 32];
    const float* Fh = &g_F[((size_t)h * Nn + j0) * 32];
    for (int t = tid; t < 512; t += 256) {
        int row = t >> 3, d4 = t & 7;
        float4 v = *(const float4*)&Eh[row * 32 + d4 * 4];
        As[d4 * 4 + 0][row] = v.x; As[d4 * 4 + 1][row] = v.y;
        As[d4 * 4 + 2][row] = v.z; As[d4 * 4 + 3][row] = v.w;
    }
    for (int t = tid; t < 1024; t += 256) {
        int row = t >> 3, d4 = t & 7;
        float4 w = *(const float4*)&Fh[row * 32 + d4 * 4];
        BsT[d4 * 4 + 0][row] = w.x; BsT[d4 * 4 + 1][row] = w.y;
        BsT[d4 * 4 + 2][row] = w.z; BsT[d4 * 4 + 3][row] = w.w;
    }
    __syncthreads();
    int tr = tid >> 4, tc = tid & 15;
    float acc[4][8];
    #pragma unroll
    for (int i = 0; i < 4; i++)
        #pragma unroll
        for (int j = 0; j < 8; j++) acc[i][j] = 0.f;
    #pragma unroll
    for (int d = 0; d < 32; d++) {
        float ra[4], rb[8];
        *(float4*)ra = *(const float4*)&As[d][tr * 4];
        *(float4*)&rb[0] = *(const float4*)&BsT[d][tc * 8];
        *(float4*)&rb[4] = *(const float4*)&BsT[d][tc * 8 + 4];
        #pragma unroll
        for (int i = 0; i < 4; i++)
            #pragma unroll
            for (int j = 0; j < 8; j++) acc[i][j] += ra[i] * rb[j];
    }
    #pragma unroll
    for (int i = 0; i < 4; i++) {
        size_t rowb = ((size_t)(i0 + tr * 4 + i) * Hh + h) * Nn + j0 + tc * 8;
        float4 v0 = make_float4(WLc * acc[i][0], WLc * acc[i][1], WLc * acc[i][2], WLc * acc[i][3]);
        float4 v1 = make_float4(WLc * acc[i][4], WLc * acc[i][5], WLc * acc[i][6], WLc * acc[i][7]);
        *(float4*)&g_logits[rowb] = v0;
        *(float4*)&g_logits[rowb + 4] = v1;
    }
}

// ---------------- FLASH2 (R13 proven form): bias + local softmax + o_pair ----------------
// grid (Nn, 8), 256 thr. smem: pairS[64*132] WbT[12*132] lS[12*64] comb[4*32*25]
__global__ void __launch_bounds__(256) flash2_k(const float* __restrict__ pair,
                                                const float* __restrict__ Wb) {
    extern __shared__ float sm[];
    float* pairS = sm;                  // 8448
    float* WbT   = pairS + 8448;        // 1584
    float* lS    = WbT + 1584;          // 768
    float* comb  = lS + 768;            // 3200
    int i = blockIdx.x, js = blockIdx.y, j0 = js << 6;
    int tid = threadIdx.x;
    int w = tid >> 5, lane = tid & 31;

    for (int r = tid; r < 64 * 32; r += 256) {
        int row = r >> 5, q = r & 31;
        cp16(&pairS[row * 132 + q * 4], &pair[((size_t)i * Nn + j0 + row) * CZd + q * 4]);
    }
    cp_commit();
    for (int t = tid; t < CZd * Hh; t += 256) WbT[(t % Hh) * 132 + (t / Hh)] = Wb[t];
    if (tid < 192) {
        int h = tid >> 4, q = tid & 15;
        *(float4*)&lS[h * 64 + q * 4] =
            *(const float4*)&g_logits[((size_t)i * Hh + h) * Nn + j0 + q * 4];
    }

    // ---- bias: warp w = z-group (16 z), lane = j (2 j) ----
    float acc0[12], acc1[12];
    #pragma unroll
    for (int h = 0; h < 12; h++) { acc0[h] = 0.f; acc1[h] = 0.f; }

    cp_wait<0>();
    __syncthreads();
    {
        const float4* ap0 = (const float4*)&pairS[lane * 132 + w * 16];
        const float4* ap1 = (const float4*)&pairS[(lane + 32) * 132 + w * 16];
        #pragma unroll
        for (int z4 = 0; z4 < 4; z4++) {
            float4 p0 = ap0[z4], p1 = ap1[z4];
            #pragma unroll
            for (int h = 0; h < 12; h++) {
                float4 wv = *(const float4*)&WbT[h * 132 + w * 16 + z4 * 4];
                acc0[h] += p0.x * wv.x + p0.y * wv.y + p0.z * wv.z + p0.w * wv.w;
                acc1[h] += p1.x * wv.x + p1.y * wv.y + p1.z * wv.z + p1.w * wv.w;
            }
        }
    }
    if (w >= 4) {
        float* c = &comb[((w - 4) * 32 + lane) * 25];
        #pragma unroll
        for (int h = 0; h < 12; h++) { c[h] = acc0[h]; c[12 + h] = acc1[h]; }
    }
    __syncthreads();
    if (w < 4) {
        const float* c = &comb[(w * 32 + lane) * 25];
        #pragma unroll
        for (int h = 0; h < 12; h++) { acc0[h] += c[h]; acc1[h] += c[12 + h]; }
    }
    __syncthreads();
    if (w >= 1 && w < 4) {
        float* c = &comb[((w - 1) * 32 + lane) * 25];
        #pragma unroll
        for (int h = 0; h < 12; h++) { c[h] = acc0[h]; c[12 + h] = acc1[h]; }
    }
    __syncthreads();
    if (w == 0) {
        #pragma unroll
        for (int h = 0; h < 12; h++) {
            float s0 = acc0[h], s1 = acc1[h];
            #pragma unroll
            for (int g = 0; g < 3; g++) {
                const float* c = &comb[(g * 32 + lane) * 25];
                s0 += c[h]; s1 += c[12 + h];
            }
            lS[h * 64 + lane] += WLc * s0;
            lS[h * 64 + 32 + lane] += WLc * s1;
        }
    }
    __syncthreads();

    // ---- local softmax: warp w -> head w; warps 0..3 also head 8+w ----
    #pragma unroll
    for (int rep = 0; rep < 2; rep++) {
        int h = w + rep * 8;
        if (h < Hh) {
            float l0 = lS[h * 64 + lane], l1 = lS[h * 64 + 32 + lane];
            float m = fmaxf(l0, l1);
            #pragma unroll
            for (int off = 16; off; off >>= 1) m = fmaxf(m, __shfl_xor_sync(0xffffffffu, m, off));
            float e0 = __expf(l0 - m), e1 = __expf(l1 - m);
            float s = e0 + e1;
            #pragma unroll
            for (int off = 16; off; off >>= 1) s += __shfl_xor_sync(0xffffffffu, s, off);
            lS[h * 64 + lane] = e0;
            lS[h * 64 + 32 + lane] = e1;
            size_t gb = ((size_t)i * Hh + h) * Nn + j0;
            g_logits[gb + lane] = e0;
            g_logits[gb + 32 + lane] = e1;
            if (lane == 0) {
                int msb = (((i * Hh) + h) * 8 + js) * 2;
                g_ms[msb] = m;
                g_ms[msb + 1] = s;
            }
        }
    }
    __syncthreads();

    // ---- o_pair: jh halves of 32 j; thread = (ht 3h) x (zz 4z float4) ----
    int jh = tid >> 7, rem = tid & 127, ht = rem >> 5, zz = rem & 31;
    float a3[3][4];
    #pragma unroll
    for (int b = 0; b < 3; b++)
        #pragma unroll
        for (int a = 0; a < 4; a++) a3[b][a] = 0.f;
    const float* E0 = &lS[(ht * 3 + 0) * 64 + jh * 32];
    const float* E1 = &lS[(ht * 3 + 1) * 64 + jh * 32];
    const float* E2 = &lS[(ht * 3 + 2) * 64 + jh * 32];
    const float* pb = &pairS[jh * 32 * 132];
    #pragma unroll 8
    for (int j = 0; j < 32; j++) {
        float4 p = *(const float4*)&pb[j * 132 + zz * 4];
        float v0 = E0[j], v1 = E1[j], v2 = E2[j];
        a3[0][0] += v0 * p.x; a3[0][1] += v0 * p.y; a3[0][2] += v0 * p.z; a3[0][3] += v0 * p.w;
        a3[1][0] += v1 * p.x; a3[1][1] += v1 * p.y; a3[1][2] += v1 * p.z; a3[1][3] += v1 * p.w;
        a3[2][0] += v2 * p.x; a3[2][1] += v2 * p.y; a3[2][2] += v2 * p.z; a3[2][3] += v2 * p.w;
    }
    if (jh == 1) {
        float* c = &comb[rem * 13];
        #pragma unroll
        for (int b = 0; b < 3; b++)
            #pragma unroll
            for (int a = 0; a < 4; a++) c[b * 4 + a] = a3[b][a];
    }
    __syncthreads();
    if (jh == 0) {
        const float* c = &comb[rem * 13];
        float* dst = &g_opP[((size_t)js * Nn + i) * (Hh * CZd)];
        #pragma unroll
        for (int b = 0; b < 3; b++) {
            float4 v;
            v.x = a3[b][0] + c[b * 4 + 0];
            v.y = a3[b][1] + c[b * 4 + 1];
            v.z = a3[b][2] + c[b * 4 + 2];
            v.w = a3[b][3] + c[b * 4 + 3];
            *(float4*)&dst[(ht * 3 + b) * CZd + zz * 4] = v;
        }
    }
}

// ---------------- combine: global stats + o_pair; factors -> g_fct ----------------
__global__ void combine_k() {
    __shared__ float fctS[96];
    int i = blockIdx.x, tid = threadIdx.x;
    if (tid < 96) {
        int h = tid >> 3, js = tid & 7;
        float mv[8], sv[8];
        float mg = -1e30f;
        #pragma unroll
        for (int k = 0; k < 8; k++) {
            int b = ((i * Hh + h) * 8 + k) * 2;
            mv[k] = g_ms[b]; sv[k] = g_ms[b + 1];
            mg = fmaxf(mg, mv[k]);
        }
        float sg = 0.f;
        #pragma unroll
        for (int k = 0; k < 8; k++) sg += sv[k] * __expf(mv[k] - mg);
        float f = __expf(mv[js] - mg) / sg;
        fctS[tid] = f;
        g_fct[i * 96 + tid] = f;
    }
    __syncthreads();
    const size_t S = (size_t)Nn * Hh * CZd;
    for (int c = tid; c < Hh * CZd; c += 256) {
        int h = c >> 7;
        float s = 0.f;
        #pragma unroll
        for (int js = 0; js < 8; js++)
            s += fctS[h * 8 + js] * g_opP[js * S + (size_t)i * (Hh * CZd) + c];
        g_concat[(size_t)i * OUTD + 576 + c] = s;
    }
}

// ---------------- o_v & o_pt: 4-way j-split partials ----------------
__global__ void ov_k() {
    __shared__ float As[2][32 * 36];
    __shared__ float Bs[2][32 * 48];
    __shared__ float fS[32 * 8];
    int i0 = blockIdx.x * 32, h = blockIdx.y, jp = blockIdx.z;
    int tid = threadIdx.x;
    int tr = tid / 16, tc = tid % 16;
    {
        int row = tid >> 3, js = tid & 7;
        fS[row * 8 + js] = g_fct[(i0 + row) * 96 + h * 8 + js];
    }
    float acc[2][3];
    #pragma unroll
    for (int a = 0; a < 2; a++)
        #pragma unroll
        for (int b = 0; b < 3; b++) acc[a][b] = 0.f;

    auto loadA = [&](int c, int buf) {
        int j0 = (jp * 4 + c) * 32;
        int row = tid >> 3, q = tid & 7;
        cp16(&As[buf][row * 36 + q * 4],
             &g_logits[((size_t)(i0 + row) * Hh + h) * Nn + j0 + q * 4]);
    };
    auto loadB = [&](int c, int buf) {
        int j0 = (jp * 4 + c) * 32;
        for (int t = tid; t < 384; t += 256) {
            int row = t / 12, q = t % 12;
            cp16(&Bs[buf][row * 48 + q * 4], &g_B2[(size_t)(j0 + row) * 576 + h * 48 + q * 4]);
        }
    };
    loadA(0, 0); loadB(0, 0); cp_commit();
    for (int c = 0; c < 4; c++) {
        int buf = c & 1;
        if (c + 1 < 4) {
            loadA(c + 1, buf ^ 1); loadB(c + 1, buf ^ 1); cp_commit();
            cp_wait<1>();
        } else cp_wait<0>();
        __syncthreads();
        float pacc[2][3];
        #pragma unroll
        for (int a = 0; a < 2; a++)
            #pragma unroll
            for (int b = 0; b < 3; b++) pacc[a][b] = 0.f;
        #pragma unroll 8
        for (int jl = 0; jl < 32; jl++) {
            float ra[2], rb[3];
            #pragma unroll
            for (int a = 0; a < 2; a++) ra[a] = As[buf][(tr * 2 + a) * 36 + jl];
            #pragma unroll
            for (int b = 0; b < 3; b++) rb[b] = Bs[buf][jl * 48 + tc * 3 + b];
            #pragma unroll
            for (int a = 0; a < 2; a++)
                #pragma unroll
                for (int b = 0; b < 3; b++) pacc[a][b] += ra[a] * rb[b];
        }
        int js = (jp * 4 + c) >> 1;
        #pragma unroll
        for (int a = 0; a < 2; a++) {
            float f = fS[(tr * 2 + a) * 8 + js];
            #pragma unroll
            for (int b = 0; b < 3; b++) acc[a][b] += f * pacc[a][b];
        }
        __syncthreads();
    }
    float* dst = &g_ovP[((size_t)jp * Nn) * (Hh * 48)];
    #pragma unroll
    for (int a = 0; a < 2; a++) {
        int i = i0 + tr * 2 + a;
        #pragma unroll
        for (int b = 0; b < 3; b++) {
            int c = tc * 3 + b;
            dst[(size_t)i * (Hh * 48) + h * 48 + c] = acc[a][b];
        }
    }
}

// ---------------- combine2 (+fused post_pt) ----------------
__global__ void combine2_k(const float* __restrict__ rot, const float* __restrict__ trans) {
    int i = blockIdx.x, tid = threadIdx.x;
    const size_t S = (size_t)Nn * Hh * 48;
    const size_t ibase = (size_t)i * (Hh * 48);
    for (int t = tid; t < 192; t += 256) {
        int h = t >> 4, c = t & 15;
        size_t base = ibase + h * 48 + c;
        float s = g_ovP[base] + g_ovP[S + base] + g_ovP[2 * S + base] + g_ovP[3 * S + base];
        g_concat[(size_t)i * OUTD + h * Cc + c] = s;
    }
    if (tid < 96) {
        int t = tid;
        float pt[3];
        #pragma unroll
        for (int a = 0; a < 3; a++) {
            size_t base = ibase + (t >> 3) * 48 + 16 + (t & 7) * 3 + a;
            pt[a] = g_ovP[base] + g_ovP[S + base] + g_ovP[2 * S + base] + g_ovP[3 * S + base];
        }
        float b0 = pt[0] - trans[i * 3 + 0];
        float b1 = pt[1] - trans[i * 3 + 1];
        float b2 = pt[2] - trans[i * 3 + 2];
        float l0 = rot[i * 9 + 0] * b0 + rot[i * 9 + 3] * b1 + rot[i * 9 + 6] * b2;
        float l1 = rot[i * 9 + 1] * b0 + rot[i * 9 + 4] * b1 + rot[i * 9 + 7] * b2;
        float l2 = rot[i * 9 + 2] * b0 + rot[i * 9 + 5] * b1 + rot[i * 9 + 8] * b2;
        float* crow = &g_concat[(size_t)i * OUTD];
        crow[192 + t * 3 + 0] = l0;
        crow[192 + t * 3 + 1] = l1;
        crow[192 + t * 3 + 2] = l2;
        crow[480 + t] = sqrtf(l0 * l0 + l1 * l1 + l2 * l2 + 1e-8f);
    }
}

// ---------------- layer norms ----------------
__device__ __forceinline__ float blockSum384(float v, float* red) {
    int tid = threadIdx.x;
    red[tid] = v;
    if (tid < 128) red[384 + tid] = 0.f;
    __syncthreads();
    for (int s = 256; s > 0; s >>= 1) {
        if (tid < s) red[tid] += red[tid + s];
        __syncthreads();
    }
    float r = red[0];
    __syncthreads();
    return r;
}

__global__ void ln1_k(const float* __restrict__ single_in, const float* __restrict__ bo,
                      const float* __restrict__ g, const float* __restrict__ b) {
    __shared__ float red[512];
    int row = blockIdx.x, tid = threadIdx.x;
    float x = single_in[row * CSd + tid] + bo[tid];
    #pragma unroll
    for (int z = 0; z < 4; z++) x += g_wop[(size_t)z * Nn * CSd + row * CSd + tid];
    float mean = blockSum384(x, red) * (1.f / CSd);
    float dx = x - mean;
    float var = blockSum384(dx * dx, red) * (1.f / CSd);
    g_s1[row * CSd + tid] = dx * rsqrtf(var + 1e-5f) * g[tid] + b[tid];
}

// ---------------- ln2 + backbone update, fused ----------------
__global__ void ln2_update_k(const float* __restrict__ g, const float* __restrict__ bb,
                             const float* __restrict__ rot, const float* __restrict__ trans,
                             const float* __restrict__ Wbu, const float* __restrict__ bbu,
                             float* __restrict__ out) {
    __shared__ float red[512];
    __shared__ float yS[384];
    int row = blockIdx.x, tid = threadIdx.x;
    float x = g_s1[row * CSd + tid] + g_h3[row * CSd + tid];
    float mean = blockSum384(x, red) * (1.f / CSd);
    float dx = x - mean;
    float var = blockSum384(dx * dx, red) * (1.f / CSd);
    float y = dx * rsqrtf(var + 1e-5f) * g[tid] + bb[tid];
    out[row * CSd + tid] = y;
    yS[tid] = y;
    __syncthreads();
    if (tid >= 32) return;
    int lane = tid;
    float u[6] = {0, 0, 0, 0, 0, 0};
    for (int s = lane; s < CSd; s += 32) {
        float xv = yS[s];
        #pragma unroll
        for (int j = 0; j < 6; j++) u[j] += xv * Wbu[s * 6 + j];
    }
    #pragma unroll
    for (int j = 0; j < 6; j++)
        #pragma unroll
        for (int off = 16; off; off >>= 1) u[j] += __shfl_xor_sync(0xffffffffu, u[j], off);
    if (lane != 0) return;
    int n = row;
    #pragma unroll
    for (int j = 0; j < 6; j++) u[j] += bbu[j];
    float b = u[0], c = u[1], d = u[2];
    float inq = rsqrtf(1.f + b * b + c * c + d * d);
    float a = inq; b *= inq; c *= inq; d *= inq;
    float R[9] = {
        a*a + b*b - c*c - d*d, 2.f*(b*c - a*d),       2.f*(b*d + a*c),
        2.f*(b*c + a*d),       a*a - b*b + c*c - d*d, 2.f*(c*d - a*b),
        2.f*(b*d - a*c),       2.f*(c*d + a*b),       a*a - b*b - c*c + d*d };
    float rn[9];
    #pragma unroll
    for (int aa = 0; aa < 3; aa++)
        #pragma unroll
        for (int cc = 0; cc < 3; cc++) {
            float s2 = 0.f;
            #pragma unroll
            for (int bx = 0; bx < 3; bx++) s2 += rot[n * 9 + aa * 3 + bx] * R[bx * 3 + cc];
            rn[aa * 3 + cc] = s2;
        }
    float t0 = u[3], t1 = u[4], t2 = u[5];
    float tn[3];
    #pragma unroll
    for (int aa = 0; aa < 3; aa++)
        tn[aa] = rot[n * 9 + aa * 3 + 0] * t0 + rot[n * 9 + aa * 3 + 1] * t1 +
                 rot[n * 9 + aa * 3 + 2] * t2 + trans[n * 3 + aa];
    #pragma unroll
    for (int e = 0; e < 9; e++) { g_rotn[n * 9 + e] = rn[e]; out[Nn * CSd + n * 9 + e] = rn[e]; }
    #pragma unroll
    for (int e = 0; e < 3; e++) { g_trn[n * 3 + e] = tn[e]; out[Nn * CSd + Nn * 9 + n * 3 + e] = tn[e]; }
}

// ---------------- loss ----------------
__global__ void loss_part_k(const float* __restrict__ rt, const float* __restrict__ tt) {
    int i = blockIdx.x, tid = threadIdx.x;
    __shared__ float red[256];
    float rn[9], rte[9], tni[3], tti[3];
    #pragma unroll
    for (int e = 0; e < 9; e++) { rn[e] = g_rotn[i * 9 + e]; rte[e] = rt[i * 9 + e]; }
    #pragma unroll
    for (int e = 0; e < 3; e++) { tni[e] = g_trn[i * 3 + e]; tti[e] = tt[i * 3 + e]; }
    float s = 0.f;
    for (int j = tid; j < Nn; j += 256) {
        float db0 = g_trn[j * 3 + 0] - tni[0];
        float db1 = g_trn[j * 3 + 1] - tni[1];
        float db2 = g_trn[j * 3 + 2] - tni[2];
        float dp0 = rn[0] * db0 + rn[3] * db1 + rn[6] * db2;
        float dp1 = rn[1] * db0 + rn[4] * db1 + rn[7] * db2;
        float dp2 = rn[2] * db0 + rn[5] * db1 + rn[8] * db2;
        float eb0 = tt[j * 3 + 0] - tti[0];
        float eb1 = tt[j * 3 + 1] - tti[1];
        float eb2 = tt[j * 3 + 2] - tti[2];
        float dt0 = rte[0] * eb0 + rte[3] * eb1 + rte[6] * eb2;
        float dt1 = rte[1] * eb0 + rte[4] * eb1 + rte[7] * eb2;
        float dt2 = rte[2] * eb0 + rte[5] * eb1 + rte[8] * eb2;
        float d0 = dp0 - dt0, d1 = dp1 - dt1, d2 = dp2 - dt2;
        float dd = sqrtf(d0 * d0 + d1 * d1 + d2 * d2 + 1e-12f);
        s += fminf(dd, 10.f);
    }
    red[tid] = s; __syncthreads();
    for (int st = 128; st > 0; st >>= 1) {
        if (tid < st) red[tid] += red[tid + st];
        __syncthreads();
    }
    if (tid == 0) g_partial[i] = red[0];
}

__global__ void loss_final_k(float* __restrict__ out) {
    __shared__ float red[512];
    int tid = threadIdx.x;
    red[tid] = g_partial[tid];
    __syncthreads();
    for (int s = 256; s > 0; s >>= 1) {
        if (tid < s) red[tid] += red[tid + s];
        __syncthreads();
    }
    if (tid == 0)
        out[Nn * CSd + Nn * 9 + Nn * 3] = red[0] / ((float)Nn * (float)Nn) * 0.1f;
}

// ---------------- host ----------------
template <typename T>
static float* symaddr(T& sym) {
    void* p = nullptr;
    cudaGetSymbolAddress(&p, sym);
    return (float*)p;
}

extern "C" void kernel_launch(void* const* d_in, const int* in_sizes, int n_in,
                              void* d_out, int out_size) {
    const float* single      = (const float*)d_in[0];
    const float* pair        = (const float*)d_in[1];
    const float* rot         = (const float*)d_in[2];
    const float* trans       = (const float*)d_in[3];
    const float* rot_truth   = (const float*)d_in[4];
    const float* trans_truth = (const float*)d_in[5];
    const float* Wq  = (const float*)d_in[6];
    const float* Wk  = (const float*)d_in[7];
    const float* Wv  = (const float*)d_in[8];
    const float* Wqp = (const float*)d_in[9];
    const float* Wkp = (const float*)d_in[10];
    const float* Wvp = (const float*)d_in[11];
    const float* Wb  = (const float*)d_in[12];
    const float* Wo  = (const float*)d_in[13];
    const float* bo  = (const float*)d_in[14];
    const float* gamma_raw = (const float*)d_in[15];
    const float* ln1_g = (const float*)d_in[16];
    const float* ln1_b = (const float*)d_in[17];
    const float* ln2_g = (const float*)d_in[18];
    const float* ln2_b = (const float*)d_in[19];
    const float* W1 = (const float*)d_in[20];
    const float* b1 = (const float*)d_in[21];
    const float* W2 = (const float*)d_in[22];
    const float* b2 = (const float*)d_in[23];
    const float* W3 = (const float*)d_in[24];
    const float* b3 = (const float*)d_in[25];
    const float* Wbu = (const float*)d_in[26];
    const float* bbu = (const float*)d_in[27];
    float* out = (float*)d_out;

    float* pProj   = symaddr(g_proj);
    float* pConcat = symaddr(g_concat);
    float* pS1     = symaddr(g_s1);
    float* pH1     = symaddr(g_h1);
    float* pH2     = symaddr(g_h2);
    float* pH3     = symaddr(g_h3);

    const int FLASH2_SMEM = (8448 + 1584 + 768 + 3200) * 4;   // 56000
    cudaFuncSetAttribute(flash2_k, cudaFuncAttributeMaxDynamicSharedMemorySize, FLASH2_SMEM);

    proj_gemm_k<<<dim3(PROJD/64, Nn/64), 256>>>(single, Wq, Wk, Wv, Wqp, Wkp, Wvp, pProj);
    prep_k<<<Nn, 128>>>(rot, trans, gamma_raw);
    core_k<<<dim3(Nn/128, Nn/64, Hh), 256>>>();

    flash2_k<<<dim3(Nn, 8), 256, FLASH2_SMEM>>>(pair, Wb);
    combine_k<<<Nn, 256>>>();
    ov_k<<<dim3(Nn/32, Hh, 4), 256>>>();
    combine2_k<<<Nn, 256>>>(rot, trans);

    sgemm_k<64,64,16,4,4,false,false,true><<<dim3(CSd/64, Nn/64, 4), 256>>>(
        pConcat, Wo, nullptr, symaddr(g_wop), Nn, CSd, OUTD, OUTD/4);
    ln1_k<<<Nn, CSd>>>(single, bo, ln1_g, ln1_b);

    sgemm_k<32,64,16,2,4,true,true,false><<<dim3(CSd/64, Nn/32, 1), 256>>>(
        pS1, W1, b1, pH1, Nn, CSd, CSd, CSd);
    sgemm_k<32,64,16,2,4,true,true,false><<<dim3(CSd/64, Nn/32, 1), 256>>>(
        pH1, W2, b2, pH2, Nn, CSd, CSd, CSd);
    sgemm_k<32,64,16,2,4,true,false,false><<<dim3(CSd/64, Nn/32, 1), 256>>>(
        pH2, W3, b3, pH3, Nn, CSd, CSd, CSd);
    ln2_update_k<<<Nn, CSd>>>(ln2_g, ln2_b, rot, trans, Wbu, bbu, out);

    loss_part_k<<<Nn, 256>>>(rot_truth, trans_truth);
    loss_final_k<<<1, 512>>>(out);
}

// round 16
// speedup vs baseline: 1.1083x; 1.0652x over previous
#include <cuda_runtime.h>
#include <math.h>

#define Nn 512
#define CSd 384
#define CZd 128
#define Hh 12
#define Cc 16
#define PQd 4
#define PVd 8
#define OUTD 2112
#define PROJD 1152
#define OQ 0
#define OK0 192
#define OV 384
#define OQP 576
#define OKP 720
#define OVP 864

__device__ float g_proj[Nn * PROJD];
__device__ float g_gv[Nn * Hh * PVd * 3];
__device__ float g_B2[Nn * Hh * 48];
__device__ float g_E[Hh * Nn * 32], g_F[Hh * Nn * 32];
__device__ float g_logits[Nn * Hh * Nn];
__device__ float g_opP[8 * Nn * Hh * CZd];
__device__ float g_ovP[4 * Nn * Hh * 48];
__device__ float g_ms[Nn * Hh * 8 * 2];
__device__ float g_fct[Nn * 96];
__device__ float g_concat[Nn * OUTD];
__device__ float g_wop[6 * Nn * CSd];
__device__ float g_s1[Nn * CSd], g_h1[Nn * CSd], g_h2[Nn * CSd], g_h3[Nn * CSd];
__device__ float g_rotn[Nn * 9], g_trn[Nn * 3];
__device__ float g_partial[Nn];

#define WLc 0.5773502691896258f
#define WCc 0.23570226039551584f

__device__ __forceinline__ void cp16(void* smem_dst, const void* gmem_src) {
    unsigned s = (unsigned)__cvta_generic_to_shared(smem_dst);
    asm volatile("cp.async.cg.shared.global [%0], [%1], 16;" :: "r"(s), "l"(gmem_src));
}
__device__ __forceinline__ void cp_commit() { asm volatile("cp.async.commit_group;"); }
template<int N> __device__ __forceinline__ void cp_wait() {
    asm volatile("cp.async.wait_group %0;" :: "n"(N));
}

// ---------------- generic double-buffered tiled SGEMM ----------------
template<int BM, int BN, int BK, int TM, int TN, bool BIAS, bool RELU, bool SPLITK>
__global__ void sgemm_k(const float* __restrict__ A, const float* __restrict__ B,
                        const float* __restrict__ bias, float* __restrict__ C,
                        int M, int N, int K, int KC) {
    const int THREADS = (BM / TM) * (BN / TN);
    __shared__ float As[2][BK][BM];
    __shared__ float Bs[2][BK][BN + 4];
    int n0 = blockIdx.x * BN, m0 = blockIdx.y * BM;
    int kstart = SPLITK ? blockIdx.z * KC : 0;
    if (SPLITK) C += (size_t)blockIdx.z * M * N;
    int tid = threadIdx.x;
    int tr = tid / (BN / TN), tc = tid % (BN / TN);
    float acc[TM][TN];
    #pragma unroll
    for (int i = 0; i < TM; i++)
        #pragma unroll
        for (int j = 0; j < TN; j++) acc[i][j] = 0.f;
    int nsteps = KC / BK;

    auto loadA = [&](int kt, int buf) {
        #pragma unroll
        for (int r = tid; r < BM * BK / 4; r += THREADS) {
            int arow = r / (BK / 4), aq = r % (BK / 4);
            float4 v = *(const float4*)&A[(size_t)(m0 + arow) * K + kstart + kt * BK + aq * 4];
            As[buf][aq * 4 + 0][arow] = v.x; As[buf][aq * 4 + 1][arow] = v.y;
            As[buf][aq * 4 + 2][arow] = v.z; As[buf][aq * 4 + 3][arow] = v.w;
        }
    };
    auto loadB = [&](int kt, int buf) {
        #pragma unroll
        for (int r = tid; r < BK * BN / 4; r += THREADS) {
            int brow = r / (BN / 4), bq = r % (BN / 4);
            cp16(&Bs[buf][brow][bq * 4], &B[(size_t)(kstart + kt * BK + brow) * N + n0 + bq * 4]);
        }
    };
    loadA(0, 0); loadB(0, 0); cp_commit();
    for (int kt = 0; kt < nsteps; kt++) {
        int buf = kt & 1;
        if (kt + 1 < nsteps) {
            loadA(kt + 1, buf ^ 1); loadB(kt + 1, buf ^ 1); cp_commit();
            cp_wait<1>();
        } else cp_wait<0>();
        __syncthreads();
        #pragma unroll
        for (int k = 0; k < BK; k++) {
            float ra[TM], rb[TN];
            if constexpr (TM % 4 == 0) {
                #pragma unroll
                for (int i = 0; i < TM; i += 4)
                    *(float4*)&ra[i] = *(const float4*)&As[buf][k][tr * TM + i];
            } else {
                #pragma unroll
                for (int i = 0; i < TM; i++) ra[i] = As[buf][k][tr * TM + i];
            }
            if constexpr (TN % 4 == 0) {
                #pragma unroll
                for (int j = 0; j < TN; j += 4)
                    *(float4*)&rb[j] = *(const float4*)&Bs[buf][k][tc * TN + j];
            } else {
                #pragma unroll
                for (int j = 0; j < TN; j++) rb[j] = Bs[buf][k][tc * TN + j];
            }
            #pragma unroll
            for (int i = 0; i < TM; i++)
                #pragma unroll
                for (int j = 0; j < TN; j++) acc[i][j] += ra[i] * rb[j];
        }
        __syncthreads();
    }
    #pragma unroll
    for (int i = 0; i < TM; i++) {
        int m = m0 + tr * TM + i;
        #pragma unroll
        for (int j = 0; j < TN; j++) {
            int n = n0 + tc * TN + j;
            float v = acc[i][j];
            if (BIAS) v += bias[n];
            if (RELU) v = fmaxf(v, 0.f);
            C[(size_t)m * N + n] = v;
        }
    }
}

// ---------------- projection GEMM with fused 6-way weight gather ----------------
__device__ __forceinline__ const float* wf_ptr(
    const float* Wq, const float* Wk, const float* Wv,
    const float* Wqp, const float* Wkp, const float* Wvp, int kk, int n) {
    if (n < 192) return Wq  + kk * 192 + n;
    if (n < 384) return Wk  + kk * 192 + (n - 192);
    if (n < 576) return Wv  + kk * 192 + (n - 384);
    if (n < 720) return Wqp + kk * 144 + (n - 576);
    if (n < 864) return Wkp + kk * 144 + (n - 720);
    return Wvp + kk * 288 + (n - 864);
}

__global__ void proj_gemm_k(const float* __restrict__ A,
                            const float* __restrict__ Wq, const float* __restrict__ Wk,
                            const float* __restrict__ Wv, const float* __restrict__ Wqp,
                            const float* __restrict__ Wkp, const float* __restrict__ Wvp,
                            float* __restrict__ C) {
    const int BM = 64, BN = 64, BK = 16;
    __shared__ float As[2][BK][BM];
    __shared__ float Bs[2][BK][BN + 4];
    int n0 = blockIdx.x * BN, m0 = blockIdx.y * BM;
    int tid = threadIdx.x;
    int tr = tid / 16, tc = tid % 16;
    float acc[4][4];
    #pragma unroll
    for (int i = 0; i < 4; i++)
        #pragma unroll
        for (int j = 0; j < 4; j++) acc[i][j] = 0.f;
    auto loadA = [&](int kt, int buf) {
        for (int r = tid; r < BM * BK / 4; r += 256) {
            int arow = r / 4, aq = r % 4;
            float4 v = *(const float4*)&A[(size_t)(m0 + arow) * CSd + kt * BK + aq * 4];
            As[buf][aq * 4 + 0][arow] = v.x; As[buf][aq * 4 + 1][arow] = v.y;
            As[buf][aq * 4 + 2][arow] = v.z; As[buf][aq * 4 + 3][arow] = v.w;
        }
    };
    auto loadB = [&](int kt, int buf) {
        for (int r = tid; r < BK * BN / 4; r += 256) {
            int brow = r / 16, bq = r % 16;
            cp16(&Bs[buf][brow][bq * 4],
                 wf_ptr(Wq, Wk, Wv, Wqp, Wkp, Wvp, kt * BK + brow, n0 + bq * 4));
        }
    };
    loadA(0, 0); loadB(0, 0); cp_commit();
    const int nsteps = CSd / BK;
    for (int kt = 0; kt < nsteps; kt++) {
        int buf = kt & 1;
        if (kt + 1 < nsteps) {
            loadA(kt + 1, buf ^ 1); loadB(kt + 1, buf ^ 1); cp_commit();
            cp_wait<1>();
        } else cp_wait<0>();
        __syncthreads();
        #pragma unroll
        for (int k = 0; k < BK; k++) {
            float ra[4], rb[4];
            *(float4*)ra = *(const float4*)&As[buf][k][tr * 4];
            *(float4*)rb = *(const float4*)&Bs[buf][k][tc * 4];
            #pragma unroll
            for (int i = 0; i < 4; i++)
                #pragma unroll
                for (int j = 0; j < 4; j++) acc[i][j] += ra[i] * rb[j];
        }
        __syncthreads();
    }
    #pragma unroll
    for (int i = 0; i < 4; i++)
        #pragma unroll
        for (int j = 0; j < 4; j++)
            C[(size_t)(m0 + tr * 4 + i) * PROJD + n0 + tc * 4 + j] = acc[i][j];
}

// ---------------- prep: frames + E/F + packed B2 ----------------
__global__ void prep_k(const float* __restrict__ rot, const float* __restrict__ trans,
                       const float* __restrict__ gamma_raw) {
    __shared__ float R[9], T[3], gqS[144], gkS[144], sqqS[12], sqkS[12], wcgS[12];
    int n = blockIdx.x, tid = threadIdx.x;
    if (tid < 9) R[tid] = rot[n * 9 + tid];
    if (tid < 3) T[tid] = trans[n * 3 + tid];
    if (tid >= 16 && tid < 28) {
        int h = tid - 16;
        float x = gamma_raw[h];
        wcgS[h] = WCc * ((x > 20.f) ? x : log1pf(expf(x)));
    }
    __syncthreads();
    const float* base = &g_proj[(size_t)n * PROJD];
    for (int t = tid; t < 96; t += 128) {
        int which = t / 48, p = t % 48;
        const float* src = base + (which ? OKP : OQP) + p * 3;
        float b0 = src[0], b1 = src[1], b2 = src[2];
        float* dst = (which ? gkS : gqS) + p * 3;
        #pragma unroll
        for (int a = 0; a < 3; a++)
            dst[a] = R[a * 3 + 0] * b0 + R[a * 3 + 1] * b1 + R[a * 3 + 2] * b2 + T[a];
    }
    for (int t = tid; t < 96; t += 128) {
        int h = t >> 3, p = t & 7;
        const float* src = base + OVP + t * 3;
        float b0 = src[0], b1 = src[1], b2 = src[2];
        #pragma unroll
        for (int a = 0; a < 3; a++) {
            float v = R[a * 3 + 0] * b0 + R[a * 3 + 1] * b1 + R[a * 3 + 2] * b2 + T[a];
            g_gv[n * 288 + t * 3 + a] = v;
            g_B2[n * 576 + h * 48 + 16 + p * 3 + a] = v;
        }
    }
    for (int t = tid; t < 192; t += 128) {
        int h = t >> 4, c = t & 15;
        g_B2[n * 576 + h * 48 + c] = base[OV + t];
    }
    for (int t = tid; t < 96; t += 128) {
        int h = t / 8, c = 40 + (t % 8);
        g_B2[n * 576 + h * 48 + c] = 0.f;
    }
    __syncthreads();
    if (tid < 24) {
        int h = tid >> 1, which = tid & 1;
        const float* g = (which ? gkS : gqS) + h * 12;
        float s = 0.f;
        #pragma unroll
        for (int e = 0; e < 12; e++) s += g[e] * g[e];
        (which ? sqkS : sqqS)[h] = s;
    }
    __syncthreads();
    for (int t = tid; t < Hh * 32; t += 128) {
        int h = t >> 5, c = t & 31;
        float wcg = wcgS[h];
        float e, f;
        if (c < 16)      { e = 0.25f * base[OQ + h * 16 + c]; f = base[OK0 + h * 16 + c]; }
        else if (c < 28) { e = wcg * gqS[h * 12 + c - 16];    f = gkS[h * 12 + c - 16]; }
        else if (c == 28){ e = sqqS[h];                        f = -0.5f * wcg; }
        else if (c == 29){ e = 1.f;                            f = -0.5f * wcg * sqkS[h]; }
        else             { e = 0.f;                            f = 0.f; }
        g_E[(size_t)((h << 9) | n) * 32 + c] = e;
        g_F[(size_t)((h << 9) | n) * 32 + c] = f;
    }
}

// ---------------- logit core: 64i x 128j tile, acc 4x8 ----------------
__global__ void core_k() {
    __shared__ float As[32][64], BsT[32][128];
    int h = blockIdx.z, i0 = blockIdx.y * 64, j0 = blockIdx.x * 128;
    int tid = threadIdx.x;
    const float* Eh = &g_E[((size_t)h * Nn + i0) * 32];
    const float* Fh = &g_F[((size_t)h * Nn + j0) * 32];
    for (int t = tid; t < 512; t += 256) {
        int row = t >> 3, d4 = t & 7;
        float4 v = *(const float4*)&Eh[row * 32 + d4 * 4];
        As[d4 * 4 + 0][row] = v.x; As[d4 * 4 + 1][row] = v.y;
        As[d4 * 4 + 2][row] = v.z; As[d4 * 4 + 3][row] = v.w;
    }
    for (int t = tid; t < 1024; t += 256) {
        int row = t >> 3, d4 = t & 7;
        float4 w = *(const float4*)&Fh[row * 32 + d4 * 4];
        BsT[d4 * 4 + 0][row] = w.x; BsT[d4 * 4 + 1][row] = w.y;
        BsT[d4 * 4 + 2][row] = w.z; BsT[d4 * 4 + 3][row] = w.w;
    }
    __syncthreads();
    int tr = tid >> 4, tc = tid & 15;
    float acc[4][8];
    #pragma unroll
    for (int i = 0; i < 4; i++)
        #pragma unroll
        for (int j = 0; j < 8; j++) acc[i][j] = 0.f;
    #pragma unroll
    for (int d = 0; d < 32; d++) {
        float ra[4], rb[8];
        *(float4*)ra = *(const float4*)&As[d][tr * 4];
        *(float4*)&rb[0] = *(const float4*)&BsT[d][tc * 8];
        *(float4*)&rb[4] = *(const float4*)&BsT[d][tc * 8 + 4];
        #pragma unroll
        for (int i = 0; i < 4; i++)
            #pragma unroll
            for (int j = 0; j < 8; j++) acc[i][j] += ra[i] * rb[j];
    }
    #pragma unroll
    for (int i = 0; i < 4; i++) {
        size_t rowb = ((size_t)(i0 + tr * 4 + i) * Hh + h) * Nn + j0 + tc * 8;
        float4 v0 = make_float4(WLc * acc[i][0], WLc * acc[i][1], WLc * acc[i][2], WLc * acc[i][3]);
        float4 v1 = make_float4(WLc * acc[i][4], WLc * acc[i][5], WLc * acc[i][6], WLc * acc[i][7]);
        *(float4*)&g_logits[rowb] = v0;
        *(float4*)&g_logits[rowb + 4] = v1;
    }
}

// ---------------- FLASH2 (R13 proven form): bias + local softmax + o_pair ----------------
__global__ void __launch_bounds__(256) flash2_k(const float* __restrict__ pair,
                                                const float* __restrict__ Wb) {
    extern __shared__ float sm[];
    float* pairS = sm;                  // 8448
    float* WbT   = pairS + 8448;        // 1584
    float* lS    = WbT + 1584;          // 768
    float* comb  = lS + 768;            // 3200
    int i = blockIdx.x, js = blockIdx.y, j0 = js << 6;
    int tid = threadIdx.x;
    int w = tid >> 5, lane = tid & 31;

    for (int r = tid; r < 64 * 32; r += 256) {
        int row = r >> 5, q = r & 31;
        cp16(&pairS[row * 132 + q * 4], &pair[((size_t)i * Nn + j0 + row) * CZd + q * 4]);
    }
    cp_commit();
    for (int t = tid; t < CZd * Hh; t += 256) WbT[(t % Hh) * 132 + (t / Hh)] = Wb[t];
    if (tid < 192) {
        int h = tid >> 4, q = tid & 15;
        *(float4*)&lS[h * 64 + q * 4] =
            *(const float4*)&g_logits[((size_t)i * Hh + h) * Nn + j0 + q * 4];
    }

    float acc0[12], acc1[12];
    #pragma unroll
    for (int h = 0; h < 12; h++) { acc0[h] = 0.f; acc1[h] = 0.f; }

    cp_wait<0>();
    __syncthreads();
    {
        const float4* ap0 = (const float4*)&pairS[lane * 132 + w * 16];
        const float4* ap1 = (const float4*)&pairS[(lane + 32) * 132 + w * 16];
        #pragma unroll
        for (int z4 = 0; z4 < 4; z4++) {
            float4 p0 = ap0[z4], p1 = ap1[z4];
            #pragma unroll
            for (int h = 0; h < 12; h++) {
                float4 wv = *(const float4*)&WbT[h * 132 + w * 16 + z4 * 4];
                acc0[h] += p0.x * wv.x + p0.y * wv.y + p0.z * wv.z + p0.w * wv.w;
                acc1[h] += p1.x * wv.x + p1.y * wv.y + p1.z * wv.z + p1.w * wv.w;
            }
        }
    }
    if (w >= 4) {
        float* c = &comb[((w - 4) * 32 + lane) * 25];
        #pragma unroll
        for (int h = 0; h < 12; h++) { c[h] = acc0[h]; c[12 + h] = acc1[h]; }
    }
    __syncthreads();
    if (w < 4) {
        const float* c = &comb[(w * 32 + lane) * 25];
        #pragma unroll
        for (int h = 0; h < 12; h++) { acc0[h] += c[h]; acc1[h] += c[12 + h]; }
    }
    __syncthreads();
    if (w >= 1 && w < 4) {
        float* c = &comb[((w - 1) * 32 + lane) * 25];
        #pragma unroll
        for (int h = 0; h < 12; h++) { c[h] = acc0[h]; c[12 + h] = acc1[h]; }
    }
    __syncthreads();
    if (w == 0) {
        #pragma unroll
        for (int h = 0; h < 12; h++) {
            float s0 = acc0[h], s1 = acc1[h];
            #pragma unroll
            for (int g = 0; g < 3; g++) {
                const float* c = &comb[(g * 32 + lane) * 25];
                s0 += c[h]; s1 += c[12 + h];
            }
            lS[h * 64 + lane] += WLc * s0;
            lS[h * 64 + 32 + lane] += WLc * s1;
        }
    }
    __syncthreads();

    #pragma unroll
    for (int rep = 0; rep < 2; rep++) {
        int h = w + rep * 8;
        if (h < Hh) {
            float l0 = lS[h * 64 + lane], l1 = lS[h * 64 + 32 + lane];
            float m = fmaxf(l0, l1);
            #pragma unroll
            for (int off = 16; off; off >>= 1) m = fmaxf(m, __shfl_xor_sync(0xffffffffu, m, off));
            float e0 = __expf(l0 - m), e1 = __expf(l1 - m);
            float s = e0 + e1;
            #pragma unroll
            for (int off = 16; off; off >>= 1) s += __shfl_xor_sync(0xffffffffu, s, off);
            lS[h * 64 + lane] = e0;
            lS[h * 64 + 32 + lane] = e1;
            size_t gb = ((size_t)i * Hh + h) * Nn + j0;
            g_logits[gb + lane] = e0;
            g_logits[gb + 32 + lane] = e1;
            if (lane == 0) {
                int msb = (((i * Hh) + h) * 8 + js) * 2;
                g_ms[msb] = m;
                g_ms[msb + 1] = s;
            }
        }
    }
    __syncthreads();

    int jh = tid >> 7, rem = tid & 127, ht = rem >> 5, zz = rem & 31;
    float a3[3][4];
    #pragma unroll
    for (int b = 0; b < 3; b++)
        #pragma unroll
        for (int a = 0; a < 4; a++) a3[b][a] = 0.f;
    const float* E0 = &lS[(ht * 3 + 0) * 64 + jh * 32];
    const float* E1 = &lS[(ht * 3 + 1) * 64 + jh * 32];
    const float* E2 = &lS[(ht * 3 + 2) * 64 + jh * 32];
    const float* pb = &pairS[jh * 32 * 132];
    #pragma unroll 8
    for (int j = 0; j < 32; j++) {
        float4 p = *(const float4*)&pb[j * 132 + zz * 4];
        float v0 = E0[j], v1 = E1[j], v2 = E2[j];
        a3[0][0] += v0 * p.x; a3[0][1] += v0 * p.y; a3[0][2] += v0 * p.z; a3[0][3] += v0 * p.w;
        a3[1][0] += v1 * p.x; a3[1][1] += v1 * p.y; a3[1][2] += v1 * p.z; a3[1][3] += v1 * p.w;
        a3[2][0] += v2 * p.x; a3[2][1] += v2 * p.y; a3[2][2] += v2 * p.z; a3[2][3] += v2 * p.w;
    }
    if (jh == 1) {
        float* c = &comb[rem * 13];
        #pragma unroll
        for (int b = 0; b < 3; b++)
            #pragma unroll
            for (int a = 0; a < 4; a++) c[b * 4 + a] = a3[b][a];
    }
    __syncthreads();
    if (jh == 0) {
        const float* c = &comb[rem * 13];
        float* dst = &g_opP[((size_t)js * Nn + i) * (Hh * CZd)];
        #pragma unroll
        for (int b = 0; b < 3; b++) {
            float4 v;
            v.x = a3[b][0] + c[b * 4 + 0];
            v.y = a3[b][1] + c[b * 4 + 1];
            v.z = a3[b][2] + c[b * 4 + 2];
            v.w = a3[b][3] + c[b * 4 + 3];
            *(float4*)&dst[(ht * 3 + b) * CZd + zz * 4] = v;
        }
    }
}

// ---------------- combine: global stats + o_pair; factors -> g_fct ----------------
__global__ void combine_k() {
    __shared__ float fctS[96];
    int i = blockIdx.x, tid = threadIdx.x;
    if (tid < 96) {
        int h = tid >> 3, js = tid & 7;
        float mv[8], sv[8];
        float mg = -1e30f;
        #pragma unroll
        for (int k = 0; k < 8; k++) {
            int b = ((i * Hh + h) * 8 + k) * 2;
            mv[k] = g_ms[b]; sv[k] = g_ms[b + 1];
            mg = fmaxf(mg, mv[k]);
        }
        float sg = 0.f;
        #pragma unroll
        for (int k = 0; k < 8; k++) sg += sv[k] * __expf(mv[k] - mg);
        float f = __expf(mv[js] - mg) / sg;
        fctS[tid] = f;
        g_fct[i * 96 + tid] = f;
    }
    __syncthreads();
    const size_t S = (size_t)Nn * Hh * CZd;
    for (int c = tid; c < Hh * CZd; c += 256) {
        int h = c >> 7;
        float s = 0.f;
        #pragma unroll
        for (int js = 0; js < 8; js++)
            s += fctS[h * 8 + js] * g_opP[js * S + (size_t)i * (Hh * CZd) + c];
        g_concat[(size_t)i * OUTD + 576 + c] = s;
    }
}

// ---------------- o_v & o_pt: 4-way j-split partials ----------------
__global__ void ov_k() {
    __shared__ float As[2][32 * 36];
    __shared__ float Bs[2][32 * 48];
    __shared__ float fS[32 * 8];
    int i0 = blockIdx.x * 32, h = blockIdx.y, jp = blockIdx.z;
    int tid = threadIdx.x;
    int tr = tid / 16, tc = tid % 16;
    {
        int row = tid >> 3, js = tid & 7;
        fS[row * 8 + js] = g_fct[(i0 + row) * 96 + h * 8 + js];
    }
    float acc[2][3];
    #pragma unroll
    for (int a = 0; a < 2; a++)
        #pragma unroll
        for (int b = 0; b < 3; b++) acc[a][b] = 0.f;

    auto loadA = [&](int c, int buf) {
        int j0 = (jp * 4 + c) * 32;
        int row = tid >> 3, q = tid & 7;
        cp16(&As[buf][row * 36 + q * 4],
             &g_logits[((size_t)(i0 + row) * Hh + h) * Nn + j0 + q * 4]);
    };
    auto loadB = [&](int c, int buf) {
        int j0 = (jp * 4 + c) * 32;
        for (int t = tid; t < 384; t += 256) {
            int row = t / 12, q = t % 12;
            cp16(&Bs[buf][row * 48 + q * 4], &g_B2[(size_t)(j0 + row) * 576 + h * 48 + q * 4]);
        }
    };
    loadA(0, 0); loadB(0, 0); cp_commit();
    for (int c = 0; c < 4; c++) {
        int buf = c & 1;
        if (c + 1 < 4) {
            loadA(c + 1, buf ^ 1); loadB(c + 1, buf ^ 1); cp_commit();
            cp_wait<1>();
        } else cp_wait<0>();
        __syncthreads();
        float pacc[2][3];
        #pragma unroll
        for (int a = 0; a < 2; a++)
            #pragma unroll
            for (int b = 0; b < 3; b++) pacc[a][b] = 0.f;
        #pragma unroll 8
        for (int jl = 0; jl < 32; jl++) {
            float ra[2], rb[3];
            #pragma unroll
            for (int a = 0; a < 2; a++) ra[a] = As[buf][(tr * 2 + a) * 36 + jl];
            #pragma unroll
            for (int b = 0; b < 3; b++) rb[b] = Bs[buf][jl * 48 + tc * 3 + b];
            #pragma unroll
            for (int a = 0; a < 2; a++)
                #pragma unroll
                for (int b = 0; b < 3; b++) pacc[a][b] += ra[a] * rb[b];
        }
        int js = (jp * 4 + c) >> 1;
        #pragma unroll
        for (int a = 0; a < 2; a++) {
            float f = fS[(tr * 2 + a) * 8 + js];
            #pragma unroll
            for (int b = 0; b < 3; b++) acc[a][b] += f * pacc[a][b];
        }
        __syncthreads();
    }
    float* dst = &g_ovP[((size_t)jp * Nn) * (Hh * 48)];
    #pragma unroll
    for (int a = 0; a < 2; a++) {
        int i = i0 + tr * 2 + a;
        #pragma unroll
        for (int b = 0; b < 3; b++) {
            int c = tc * 3 + b;
            dst[(size_t)i * (Hh * 48) + h * 48 + c] = acc[a][b];
        }
    }
}

// ---------------- combine2 (+fused post_pt) ----------------
__global__ void combine2_k(const float* __restrict__ rot, const float* __restrict__ trans) {
    int i = blockIdx.x, tid = threadIdx.x;
    const size_t S = (size_t)Nn * Hh * 48;
    const size_t ibase = (size_t)i * (Hh * 48);
    for (int t = tid; t < 192; t += 256) {
        int h = t >> 4, c = t & 15;
        size_t base = ibase + h * 48 + c;
        float s = g_ovP[base] + g_ovP[S + base] + g_ovP[2 * S + base] + g_ovP[3 * S + base];
        g_concat[(size_t)i * OUTD + h * Cc + c] = s;
    }
    if (tid < 96) {
        int t = tid;
        float pt[3];
        #pragma unroll
        for (int a = 0; a < 3; a++) {
            size_t base = ibase + (t >> 3) * 48 + 16 + (t & 7) * 3 + a;
            pt[a] = g_ovP[base] + g_ovP[S + base] + g_ovP[2 * S + base] + g_ovP[3 * S + base];
        }
        float b0 = pt[0] - trans[i * 3 + 0];
        float b1 = pt[1] - trans[i * 3 + 1];
        float b2 = pt[2] - trans[i * 3 + 2];
        float l0 = rot[i * 9 + 0] * b0 + rot[i * 9 + 3] * b1 + rot[i * 9 + 6] * b2;
        float l1 = rot[i * 9 + 1] * b0 + rot[i * 9 + 4] * b1 + rot[i * 9 + 7] * b2;
        float l2 = rot[i * 9 + 2] * b0 + rot[i * 9 + 5] * b1 + rot[i * 9 + 8] * b2;
        float* crow = &g_concat[(size_t)i * OUTD];
        crow[192 + t * 3 + 0] = l0;
        crow[192 + t * 3 + 1] = l1;
        crow[192 + t * 3 + 2] = l2;
        crow[480 + t] = sqrtf(l0 * l0 + l1 * l1 + l2 * l2 + 1e-8f);
    }
}

// ---------------- layer norms ----------------
__device__ __forceinline__ float blockSum384(float v, float* red) {
    int tid = threadIdx.x;
    red[tid] = v;
    if (tid < 128) red[384 + tid] = 0.f;
    __syncthreads();
    for (int s = 256; s > 0; s >>= 1) {
        if (tid < s) red[tid] += red[tid + s];
        __syncthreads();
    }
    float r = red[0];
    __syncthreads();
    return r;
}

__global__ void ln1_k(const float* __restrict__ single_in, const float* __restrict__ bo,
                      const float* __restrict__ g, const float* __restrict__ b) {
    __shared__ float red[512];
    int row = blockIdx.x, tid = threadIdx.x;
    float x = single_in[row * CSd + tid] + bo[tid];
    #pragma unroll
    for (int z = 0; z < 6; z++) x += g_wop[(size_t)z * Nn * CSd + row * CSd + tid];
    float mean = blockSum384(x, red) * (1.f / CSd);
    float dx = x - mean;
    float var = blockSum384(dx * dx, red) * (1.f / CSd);
    g_s1[row * CSd + tid] = dx * rsqrtf(var + 1e-5f) * g[tid] + b[tid];
}

// ---------------- ln2 + backbone update, fused ----------------
__global__ void ln2_update_k(const float* __restrict__ g, const float* __restrict__ bb,
                             const float* __restrict__ rot, const float* __restrict__ trans,
                             const float* __restrict__ Wbu, const float* __restrict__ bbu,
                             float* __restrict__ out) {
    __shared__ float red[512];
    __shared__ float yS[384];
    int row = blockIdx.x, tid = threadIdx.x;
    float x = g_s1[row * CSd + tid] + g_h3[row * CSd + tid];
    float mean = blockSum384(x, red) * (1.f / CSd);
    float dx = x - mean;
    float var = blockSum384(dx * dx, red) * (1.f / CSd);
    float y = dx * rsqrtf(var + 1e-5f) * g[tid] + bb[tid];
    out[row * CSd + tid] = y;
    yS[tid] = y;
    __syncthreads();
    if (tid >= 32) return;
    int lane = tid;
    float u[6] = {0, 0, 0, 0, 0, 0};
    for (int s = lane; s < CSd; s += 32) {
        float xv = yS[s];
        #pragma unroll
        for (int j = 0; j < 6; j++) u[j] += xv * Wbu[s * 6 + j];
    }
    #pragma unroll
    for (int j = 0; j < 6; j++)
        #pragma unroll
        for (int off = 16; off; off >>= 1) u[j] += __shfl_xor_sync(0xffffffffu, u[j], off);
    if (lane != 0) return;
    int n = row;
    #pragma unroll
    for (int j = 0; j < 6; j++) u[j] += bbu[j];
    float b = u[0], c = u[1], d = u[2];
    float inq = rsqrtf(1.f + b * b + c * c + d * d);
    float a = inq; b *= inq; c *= inq; d *= inq;
    float R[9] = {
        a*a + b*b - c*c - d*d, 2.f*(b*c - a*d),       2.f*(b*d + a*c),
        2.f*(b*c + a*d),       a*a - b*b + c*c - d*d, 2.f*(c*d - a*b),
        2.f*(b*d - a*c),       2.f*(c*d + a*b),       a*a - b*b - c*c + d*d };
    float rn[9];
    #pragma unroll
    for (int aa = 0; aa < 3; aa++)
        #pragma unroll
        for (int cc = 0; cc < 3; cc++) {
            float s2 = 0.f;
            #pragma unroll
            for (int bx = 0; bx < 3; bx++) s2 += rot[n * 9 + aa * 3 + bx] * R[bx * 3 + cc];
            rn[aa * 3 + cc] = s2;
        }
    float t0 = u[3], t1 = u[4], t2 = u[5];
    float tn[3];
    #pragma unroll
    for (int aa = 0; aa < 3; aa++)
        tn[aa] = rot[n * 9 + aa * 3 + 0] * t0 + rot[n * 9 + aa * 3 + 1] * t1 +
                 rot[n * 9 + aa * 3 + 2] * t2 + trans[n * 3 + aa];
    #pragma unroll
    for (int e = 0; e < 9; e++) { g_rotn[n * 9 + e] = rn[e]; out[Nn * CSd + n * 9 + e] = rn[e]; }
    #pragma unroll
    for (int e = 0; e < 3; e++) { g_trn[n * 3 + e] = tn[e]; out[Nn * CSd + Nn * 9 + n * 3 + e] = tn[e]; }
}

// ---------------- loss ----------------
__global__ void loss_part_k(const float* __restrict__ rt, const float* __restrict__ tt) {
    int i = blockIdx.x, tid = threadIdx.x;
    __shared__ float red[256];
    float rn[9], rte[9], tni[3], tti[3];
    #pragma unroll
    for (int e = 0; e < 9; e++) { rn[e] = g_rotn[i * 9 + e]; rte[e] = rt[i * 9 + e]; }
    #pragma unroll
    for (int e = 0; e < 3; e++) { tni[e] = g_trn[i * 3 + e]; tti[e] = tt[i * 3 + e]; }
    float s = 0.f;
    for (int j = tid; j < Nn; j += 256) {
        float db0 = g_trn[j * 3 + 0] - tni[0];
        float db1 = g_trn[j * 3 + 1] - tni[1];
        float db2 = g_trn[j * 3 + 2] - tni[2];
        float dp0 = rn[0] * db0 + rn[3] * db1 + rn[6] * db2;
        float dp1 = rn[1] * db0 + rn[4] * db1 + rn[7] * db2;
        float dp2 = rn[2] * db0 + rn[5] * db1 + rn[8] * db2;
        float eb0 = tt[j * 3 + 0] - tti[0];
        float eb1 = tt[j * 3 + 1] - tti[1];
        float eb2 = tt[j * 3 + 2] - tti[2];
        float dt0 = rte[0] * eb0 + rte[3] * eb1 + rte[6] * eb2;
        float dt1 = rte[1] * eb0 + rte[4] * eb1 + rte[7] * eb2;
        float dt2 = rte[2] * eb0 + rte[5] * eb1 + rte[8] * eb2;
        float d0 = dp0 - dt0, d1 = dp1 - dt1, d2 = dp2 - dt2;
        float dd = sqrtf(d0 * d0 + d1 * d1 + d2 * d2 + 1e-12f);
        s += fminf(dd, 10.f);
    }
    red[tid] = s; __syncthreads();
    for (int st = 128; st > 0; st >>= 1) {
        if (tid < st) red[tid] += red[tid + st];
        __syncthreads();
    }
    if (tid == 0) g_partial[i] = red[0];
}

__global__ void loss_final_k(float* __restrict__ out) {
    __shared__ float red[512];
    int tid = threadIdx.x;
    red[tid] = g_partial[tid];
    __syncthreads();
    for (int s = 256; s > 0; s >>= 1) {
        if (tid < s) red[tid] += red[tid + s];
        __syncthreads();
    }
    if (tid == 0)
        out[Nn * CSd + Nn * 9 + Nn * 3] = red[0] / ((float)Nn * (float)Nn) * 0.1f;
}

// ---------------- host ----------------
template <typename T>
static float* symaddr(T& sym) {
    void* p = nullptr;
    cudaGetSymbolAddress(&p, sym);
    return (float*)p;
}

extern "C" void kernel_launch(void* const* d_in, const int* in_sizes, int n_in,
                              void* d_out, int out_size) {
    const float* single      = (const float*)d_in[0];
    const float* pair        = (const float*)d_in[1];
    const float* rot         = (const float*)d_in[2];
    const float* trans       = (const float*)d_in[3];
    const float* rot_truth   = (const float*)d_in[4];
    const float* trans_truth = (const float*)d_in[5];
    const float* Wq  = (const float*)d_in[6];
    const float* Wk  = (const float*)d_in[7];
    const float* Wv  = (const float*)d_in[8];
    const float* Wqp = (const float*)d_in[9];
    const float* Wkp = (const float*)d_in[10];
    const float* Wvp = (const float*)d_in[11];
    const float* Wb  = (const float*)d_in[12];
    const float* Wo  = (const float*)d_in[13];
    const float* bo  = (const float*)d_in[14];
    const float* gamma_raw = (const float*)d_in[15];
    const float* ln1_g = (const float*)d_in[16];
    const float* ln1_b = (const float*)d_in[17];
    const float* ln2_g = (const float*)d_in[18];
    const float* ln2_b = (const float*)d_in[19];
    const float* W1 = (const float*)d_in[20];
    const float* b1 = (const float*)d_in[21];
    const float* W2 = (const float*)d_in[22];
    const float* b2 = (const float*)d_in[23];
    const float* W3 = (const float*)d_in[24];
    const float* b3 = (const float*)d_in[25];
    const float* Wbu = (const float*)d_in[26];
    const float* bbu = (const float*)d_in[27];
    float* out = (float*)d_out;

    float* pProj   = symaddr(g_proj);
    float* pConcat = symaddr(g_concat);
    float* pS1     = symaddr(g_s1);
    float* pH1     = symaddr(g_h1);
    float* pH2     = symaddr(g_h2);
    float* pH3     = symaddr(g_h3);

    const int FLASH2_SMEM = (8448 + 1584 + 768 + 3200) * 4;   // 56000
    cudaFuncSetAttribute(flash2_k, cudaFuncAttributeMaxDynamicSharedMemorySize, FLASH2_SMEM);

    proj_gemm_k<<<dim3(PROJD/64, Nn/64), 256>>>(single, Wq, Wk, Wv, Wqp, Wkp, Wvp, pProj);
    prep_k<<<Nn, 128>>>(rot, trans, gamma_raw);
    core_k<<<dim3(Nn/128, Nn/64, Hh), 256>>>();

    flash2_k<<<dim3(Nn, 8), 256, FLASH2_SMEM>>>(pair, Wb);
    combine_k<<<Nn, 256>>>();
    ov_k<<<dim3(Nn/32, Hh, 4), 256>>>();
    combine2_k<<<Nn, 256>>>(rot, trans);

    // Wo split-K=6: 6x8x6 = 288 blocks
    sgemm_k<64,64,16,4,4,false,false,true><<<dim3(CSd/64, Nn/64, 6), 256>>>(
        pConcat, Wo, nullptr, symaddr(g_wop), Nn, CSd, OUTD, OUTD/6);
    ln1_k<<<Nn, CSd>>>(single, bo, ln1_g, ln1_b);

    // FFN: BM32/BN32 -> 12x16 = 192 blocks each
    sgemm_k<32,32,16,2,2,true,true,false><<<dim3(CSd/32, Nn/32, 1), 256>>>(
        pS1, W1, b1, pH1, Nn, CSd, CSd, CSd);
    sgemm_k<32,32,16,2,2,true,true,false><<<dim3(CSd/32, Nn/32, 1), 256>>>(
        pH1, W2, b2, pH2, Nn, CSd, CSd, CSd);
    sgemm_k<32,32,16,2,2,true,false,false><<<dim3(CSd/32, Nn/32, 1), 256>>>(
        pH2, W3, b3, pH3, Nn, CSd, CSd, CSd);
    ln2_update_k<<<Nn, CSd>>>(ln2_g, ln2_b, rot, trans, Wbu, bbu, out);

    loss_part_k<<<Nn, 256>>>(rot_truth, trans_truth);
    loss_final_k<<<1, 512>>>(out);
}

// round 17
// speedup vs baseline: 1.1259x; 1.0159x over previous
#include <cuda_runtime.h>
#include <cuda_bf16.h>
#include <math.h>

#define Nn 512
#define CSd 384
#define CZd 128
#define Hh 12
#define Cc 16
#define PQd 4
#define PVd 8
#define OUTD 2112
#define PROJD 1152
#define OQ 0
#define OK0 192
#define OV 384
#define OQP 576
#define OKP 720
#define OVP 864

__device__ float g_proj[Nn * PROJD];
__device__ float g_gv[Nn * Hh * PVd * 3];
__device__ float g_B2[Nn * Hh * 48];
__device__ float g_E[Hh * Nn * 32], g_F[Hh * Nn * 32];
__device__ float g_logits[Nn * Hh * Nn];
__device__ __nv_bfloat16 g_opP[8 * Nn * Hh * CZd];
__device__ float g_ovP[4 * Nn * Hh * 48];
__device__ float g_ms[Nn * Hh * 8 * 2];
__device__ float g_concat[Nn * OUTD];
__device__ float g_wop[6 * Nn * CSd];
__device__ float g_s1[Nn * CSd], g_h1[Nn * CSd], g_h2[Nn * CSd], g_h3[Nn * CSd];
__device__ float g_rotn[Nn * 9], g_trn[Nn * 3];
__device__ float g_partial[Nn];

#define WLc 0.5773502691896258f
#define WCc 0.23570226039551584f

__device__ __forceinline__ void cp16(void* smem_dst, const void* gmem_src) {
    unsigned s = (unsigned)__cvta_generic_to_shared(smem_dst);
    asm volatile("cp.async.cg.shared.global [%0], [%1], 16;" :: "r"(s), "l"(gmem_src));
}
__device__ __forceinline__ void cp_commit() { asm volatile("cp.async.commit_group;"); }
template<int N> __device__ __forceinline__ void cp_wait() {
    asm volatile("cp.async.wait_group %0;" :: "n"(N));
}

// ---------------- generic double-buffered tiled SGEMM ----------------
template<int BM, int BN, int BK, int TM, int TN, bool BIAS, bool RELU, bool SPLITK>
__global__ void sgemm_k(const float* __restrict__ A, const float* __restrict__ B,
                        const float* __restrict__ bias, float* __restrict__ C,
                        int M, int N, int K, int KC) {
    const int THREADS = (BM / TM) * (BN / TN);
    __shared__ float As[2][BK][BM];
    __shared__ float Bs[2][BK][BN + 4];
    int n0 = blockIdx.x * BN, m0 = blockIdx.y * BM;
    int kstart = SPLITK ? blockIdx.z * KC : 0;
    if (SPLITK) C += (size_t)blockIdx.z * M * N;
    int tid = threadIdx.x;
    int tr = tid / (BN / TN), tc = tid % (BN / TN);
    float acc[TM][TN];
    #pragma unroll
    for (int i = 0; i < TM; i++)
        #pragma unroll
        for (int j = 0; j < TN; j++) acc[i][j] = 0.f;
    int nsteps = KC / BK;

    auto loadA = [&](int kt, int buf) {
        #pragma unroll
        for (int r = tid; r < BM * BK / 4; r += THREADS) {
            int arow = r / (BK / 4), aq = r % (BK / 4);
            float4 v = *(const float4*)&A[(size_t)(m0 + arow) * K + kstart + kt * BK + aq * 4];
            As[buf][aq * 4 + 0][arow] = v.x; As[buf][aq * 4 + 1][arow] = v.y;
            As[buf][aq * 4 + 2][arow] = v.z; As[buf][aq * 4 + 3][arow] = v.w;
        }
    };
    auto loadB = [&](int kt, int buf) {
        #pragma unroll
        for (int r = tid; r < BK * BN / 4; r += THREADS) {
            int brow = r / (BN / 4), bq = r % (BN / 4);
            cp16(&Bs[buf][brow][bq * 4], &B[(size_t)(kstart + kt * BK + brow) * N + n0 + bq * 4]);
        }
    };
    loadA(0, 0); loadB(0, 0); cp_commit();
    for (int kt = 0; kt < nsteps; kt++) {
        int buf = kt & 1;
        if (kt + 1 < nsteps) {
            loadA(kt + 1, buf ^ 1); loadB(kt + 1, buf ^ 1); cp_commit();
            cp_wait<1>();
        } else cp_wait<0>();
        __syncthreads();
        #pragma unroll
        for (int k = 0; k < BK; k++) {
            float ra[TM], rb[TN];
            if constexpr (TM % 4 == 0) {
                #pragma unroll
                for (int i = 0; i < TM; i += 4)
                    *(float4*)&ra[i] = *(const float4*)&As[buf][k][tr * TM + i];
            } else {
                #pragma unroll
                for (int i = 0; i < TM; i++) ra[i] = As[buf][k][tr * TM + i];
            }
            if constexpr (TN % 4 == 0) {
                #pragma unroll
                for (int j = 0; j < TN; j += 4)
                    *(float4*)&rb[j] = *(const float4*)&Bs[buf][k][tc * TN + j];
            } else {
                #pragma unroll
                for (int j = 0; j < TN; j++) rb[j] = Bs[buf][k][tc * TN + j];
            }
            #pragma unroll
            for (int i = 0; i < TM; i++)
                #pragma unroll
                for (int j = 0; j < TN; j++) acc[i][j] += ra[i] * rb[j];
        }
        __syncthreads();
    }
    #pragma unroll
    for (int i = 0; i < TM; i++) {
        int m = m0 + tr * TM + i;
        #pragma unroll
        for (int j = 0; j < TN; j++) {
            int n = n0 + tc * TN + j;
            float v = acc[i][j];
            if (BIAS) v += bias[n];
            if (RELU) v = fmaxf(v, 0.f);
            C[(size_t)m * N + n] = v;
        }
    }
}

// ---------------- projection GEMM with fused 6-way weight gather ----------------
__device__ __forceinline__ const float* wf_ptr(
    const float* Wq, const float* Wk, const float* Wv,
    const float* Wqp, const float* Wkp, const float* Wvp, int kk, int n) {
    if (n < 192) return Wq  + kk * 192 + n;
    if (n < 384) return Wk  + kk * 192 + (n - 192);
    if (n < 576) return Wv  + kk * 192 + (n - 384);
    if (n < 720) return Wqp + kk * 144 + (n - 576);
    if (n < 864) return Wkp + kk * 144 + (n - 720);
    return Wvp + kk * 288 + (n - 864);
}

__global__ void proj_gemm_k(const float* __restrict__ A,
                            const float* __restrict__ Wq, const float* __restrict__ Wk,
                            const float* __restrict__ Wv, const float* __restrict__ Wqp,
                            const float* __restrict__ Wkp, const float* __restrict__ Wvp,
                            float* __restrict__ C) {
    const int BM = 64, BN = 64, BK = 16;
    __shared__ float As[2][BK][BM];
    __shared__ float Bs[2][BK][BN + 4];
    int n0 = blockIdx.x * BN, m0 = blockIdx.y * BM;
    int tid = threadIdx.x;
    int tr = tid / 16, tc = tid % 16;
    float acc[4][4];
    #pragma unroll
    for (int i = 0; i < 4; i++)
        #pragma unroll
        for (int j = 0; j < 4; j++) acc[i][j] = 0.f;
    auto loadA = [&](int kt, int buf) {
        for (int r = tid; r < BM * BK / 4; r += 256) {
            int arow = r / 4, aq = r % 4;
            float4 v = *(const float4*)&A[(size_t)(m0 + arow) * CSd + kt * BK + aq * 4];
            As[buf][aq * 4 + 0][arow] = v.x; As[buf][aq * 4 + 1][arow] = v.y;
            As[buf][aq * 4 + 2][arow] = v.z; As[buf][aq * 4 + 3][arow] = v.w;
        }
    };
    auto loadB = [&](int kt, int buf) {
        for (int r = tid; r < BK * BN / 4; r += 256) {
            int brow = r / 16, bq = r % 16;
            cp16(&Bs[buf][brow][bq * 4],
                 wf_ptr(Wq, Wk, Wv, Wqp, Wkp, Wvp, kt * BK + brow, n0 + bq * 4));
        }
    };
    loadA(0, 0); loadB(0, 0); cp_commit();
    const int nsteps = CSd / BK;
    for (int kt = 0; kt < nsteps; kt++) {
        int buf = kt & 1;
        if (kt + 1 < nsteps) {
            loadA(kt + 1, buf ^ 1); loadB(kt + 1, buf ^ 1); cp_commit();
            cp_wait<1>();
        } else cp_wait<0>();
        __syncthreads();
        #pragma unroll
        for (int k = 0; k < BK; k++) {
            float ra[4], rb[4];
            *(float4*)ra = *(const float4*)&As[buf][k][tr * 4];
            *(float4*)rb = *(const float4*)&Bs[buf][k][tc * 4];
            #pragma unroll
            for (int i = 0; i < 4; i++)
                #pragma unroll
                for (int j = 0; j < 4; j++) acc[i][j] += ra[i] * rb[j];
        }
        __syncthreads();
    }
    #pragma unroll
    for (int i = 0; i < 4; i++)
        #pragma unroll
        for (int j = 0; j < 4; j++)
            C[(size_t)(m0 + tr * 4 + i) * PROJD + n0 + tc * 4 + j] = acc[i][j];
}

// ---------------- prep: frames + E/F + packed B2 ----------------
__global__ void prep_k(const float* __restrict__ rot, const float* __restrict__ trans,
                       const float* __restrict__ gamma_raw) {
    __shared__ float R[9], T[3], gqS[144], gkS[144], sqqS[12], sqkS[12], wcgS[12];
    int n = blockIdx.x, tid = threadIdx.x;
    if (tid < 9) R[tid] = rot[n * 9 + tid];
    if (tid < 3) T[tid] = trans[n * 3 + tid];
    if (tid >= 16 && tid < 28) {
        int h = tid - 16;
        float x = gamma_raw[h];
        wcgS[h] = WCc * ((x > 20.f) ? x : log1pf(expf(x)));
    }
    __syncthreads();
    const float* base = &g_proj[(size_t)n * PROJD];
    for (int t = tid; t < 96; t += 128) {
        int which = t / 48, p = t % 48;
        const float* src = base + (which ? OKP : OQP) + p * 3;
        float b0 = src[0], b1 = src[1], b2 = src[2];
        float* dst = (which ? gkS : gqS) + p * 3;
        #pragma unroll
        for (int a = 0; a < 3; a++)
            dst[a] = R[a * 3 + 0] * b0 + R[a * 3 + 1] * b1 + R[a * 3 + 2] * b2 + T[a];
    }
    for (int t = tid; t < 96; t += 128) {
        int h = t >> 3, p = t & 7;
        const float* src = base + OVP + t * 3;
        float b0 = src[0], b1 = src[1], b2 = src[2];
        #pragma unroll
        for (int a = 0; a < 3; a++) {
            float v = R[a * 3 + 0] * b0 + R[a * 3 + 1] * b1 + R[a * 3 + 2] * b2 + T[a];
            g_gv[n * 288 + t * 3 + a] = v;
            g_B2[n * 576 + h * 48 + 16 + p * 3 + a] = v;
        }
    }
    for (int t = tid; t < 192; t += 128) {
        int h = t >> 4, c = t & 15;
        g_B2[n * 576 + h * 48 + c] = base[OV + t];
    }
    for (int t = tid; t < 96; t += 128) {
        int h = t / 8, c = 40 + (t % 8);
        g_B2[n * 576 + h * 48 + c] = 0.f;
    }
    __syncthreads();
    if (tid < 24) {
        int h = tid >> 1, which = tid & 1;
        const float* g = (which ? gkS : gqS) + h * 12;
        float s = 0.f;
        #pragma unroll
        for (int e = 0; e < 12; e++) s += g[e] * g[e];
        (which ? sqkS : sqqS)[h] = s;
    }
    __syncthreads();
    for (int t = tid; t < Hh * 32; t += 128) {
        int h = t >> 5, c = t & 31;
        float wcg = wcgS[h];
        float e, f;
        if (c < 16)      { e = 0.25f * base[OQ + h * 16 + c]; f = base[OK0 + h * 16 + c]; }
        else if (c < 28) { e = wcg * gqS[h * 12 + c - 16];    f = gkS[h * 12 + c - 16]; }
        else if (c == 28){ e = sqqS[h];                        f = -0.5f * wcg; }
        else if (c == 29){ e = 1.f;                            f = -0.5f * wcg * sqkS[h]; }
        else             { e = 0.f;                            f = 0.f; }
        g_E[(size_t)((h << 9) | n) * 32 + c] = e;
        g_F[(size_t)((h << 9) | n) * 32 + c] = f;
    }
}

// ---------------- logit core: 64i x 128j tile, acc 4x8 ----------------
__global__ void core_k() {
    __shared__ float As[32][64], BsT[32][128];
    int h = blockIdx.z, i0 = blockIdx.y * 64, j0 = blockIdx.x * 128;
    int tid = threadIdx.x;
    const float* Eh = &g_E[((size_t)h * Nn + i0) * 32];
    const float* Fh = &g_F[((size_t)h * Nn + j0) * 32];
    for (int t = tid; t < 512; t += 256) {
        int row = t >> 3, d4 = t & 7;
        float4 v = *(const float4*)&Eh[row * 32 + d4 * 4];
        As[d4 * 4 + 0][row] = v.x; As[d4 * 4 + 1][row] = v.y;
        As[d4 * 4 + 2][row] = v.z; As[d4 * 4 + 3][row] = v.w;
    }
    for (int t = tid; t < 1024; t += 256) {
        int row = t >> 3, d4 = t & 7;
        float4 w = *(const float4*)&Fh[row * 32 + d4 * 4];
        BsT[d4 * 4 + 0][row] = w.x; BsT[d4 * 4 + 1][row] = w.y;
        BsT[d4 * 4 + 2][row] = w.z; BsT[d4 * 4 + 3][row] = w.w;
    }
    __syncthreads();
    int tr = tid >> 4, tc = tid & 15;
    float acc[4][8];
    #pragma unroll
    for (int i = 0; i < 4; i++)
        #pragma unroll
        for (int j = 0; j < 8; j++) acc[i][j] = 0.f;
    #pragma unroll
    for (int d = 0; d < 32; d++) {
        float ra[4], rb[8];
        *(float4*)ra = *(const float4*)&As[d][tr * 4];
        *(float4*)&rb[0] = *(const float4*)&BsT[d][tc * 8];
        *(float4*)&rb[4] = *(const float4*)&BsT[d][tc * 8 + 4];
        #pragma unroll
        for (int i = 0; i < 4; i++)
            #pragma unroll
            for (int j = 0; j < 8; j++) acc[i][j] += ra[i] * rb[j];
    }
    #pragma unroll
    for (int i = 0; i < 4; i++) {
        size_t rowb = ((size_t)(i0 + tr * 4 + i) * Hh + h) * Nn + j0 + tc * 8;
        float4 v0 = make_float4(WLc * acc[i][0], WLc * acc[i][1], WLc * acc[i][2], WLc * acc[i][3]);
        float4 v1 = make_float4(WLc * acc[i][4], WLc * acc[i][5], WLc * acc[i][6], WLc * acc[i][7]);
        *(float4*)&g_logits[rowb] = v0;
        *(float4*)&g_logits[rowb + 4] = v1;
    }
}

// ---------------- FLASH2 (R13 proven form; bf16 opP store) ----------------
__global__ void __launch_bounds__(256) flash2_k(const float* __restrict__ pair,
                                                const float* __restrict__ Wb) {
    extern __shared__ float sm[];
    float* pairS = sm;                  // 8448
    float* WbT   = pairS + 8448;        // 1584
    float* lS    = WbT + 1584;          // 768
    float* comb  = lS + 768;            // 3200
    int i = blockIdx.x, js = blockIdx.y, j0 = js << 6;
    int tid = threadIdx.x;
    int w = tid >> 5, lane = tid & 31;

    for (int r = tid; r < 64 * 32; r += 256) {
        int row = r >> 5, q = r & 31;
        cp16(&pairS[row * 132 + q * 4], &pair[((size_t)i * Nn + j0 + row) * CZd + q * 4]);
    }
    cp_commit();
    for (int t = tid; t < CZd * Hh; t += 256) WbT[(t % Hh) * 132 + (t / Hh)] = Wb[t];
    if (tid < 192) {
        int h = tid >> 4, q = tid & 15;
        *(float4*)&lS[h * 64 + q * 4] =
            *(const float4*)&g_logits[((size_t)i * Hh + h) * Nn + j0 + q * 4];
    }

    float acc0[12], acc1[12];
    #pragma unroll
    for (int h = 0; h < 12; h++) { acc0[h] = 0.f; acc1[h] = 0.f; }

    cp_wait<0>();
    __syncthreads();
    {
        const float4* ap0 = (const float4*)&pairS[lane * 132 + w * 16];
        const float4* ap1 = (const float4*)&pairS[(lane + 32) * 132 + w * 16];
        #pragma unroll
        for (int z4 = 0; z4 < 4; z4++) {
            float4 p0 = ap0[z4], p1 = ap1[z4];
            #pragma unroll
            for (int h = 0; h < 12; h++) {
                float4 wv = *(const float4*)&WbT[h * 132 + w * 16 + z4 * 4];
                acc0[h] += p0.x * wv.x + p0.y * wv.y + p0.z * wv.z + p0.w * wv.w;
                acc1[h] += p1.x * wv.x + p1.y * wv.y + p1.z * wv.z + p1.w * wv.w;
            }
        }
    }
    if (w >= 4) {
        float* c = &comb[((w - 4) * 32 + lane) * 25];
        #pragma unroll
        for (int h = 0; h < 12; h++) { c[h] = acc0[h]; c[12 + h] = acc1[h]; }
    }
    __syncthreads();
    if (w < 4) {
        const float* c = &comb[(w * 32 + lane) * 25];
        #pragma unroll
        for (int h = 0; h < 12; h++) { acc0[h] += c[h]; acc1[h] += c[12 + h]; }
    }
    __syncthreads();
    if (w >= 1 && w < 4) {
        float* c = &comb[((w - 1) * 32 + lane) * 25];
        #pragma unroll
        for (int h = 0; h < 12; h++) { c[h] = acc0[h]; c[12 + h] = acc1[h]; }
    }
    __syncthreads();
    if (w == 0) {
        #pragma unroll
        for (int h = 0; h < 12; h++) {
            float s0 = acc0[h], s1 = acc1[h];
            #pragma unroll
            for (int g = 0; g < 3; g++) {
                const float* c = &comb[(g * 32 + lane) * 25];
                s0 += c[h]; s1 += c[12 + h];
            }
            lS[h * 64 + lane] += WLc * s0;
            lS[h * 64 + 32 + lane] += WLc * s1;
        }
    }
    __syncthreads();

    #pragma unroll
    for (int rep = 0; rep < 2; rep++) {
        int h = w + rep * 8;
        if (h < Hh) {
            float l0 = lS[h * 64 + lane], l1 = lS[h * 64 + 32 + lane];
            float m = fmaxf(l0, l1);
            #pragma unroll
            for (int off = 16; off; off >>= 1) m = fmaxf(m, __shfl_xor_sync(0xffffffffu, m, off));
            float e0 = __expf(l0 - m), e1 = __expf(l1 - m);
            float s = e0 + e1;
            #pragma unroll
            for (int off = 16; off; off >>= 1) s += __shfl_xor_sync(0xffffffffu, s, off);
            lS[h * 64 + lane] = e0;
            lS[h * 64 + 32 + lane] = e1;
            size_t gb = ((size_t)i * Hh + h) * Nn + j0;
            g_logits[gb + lane] = e0;
            g_logits[gb + 32 + lane] = e1;
            if (lane == 0) {
                int msb = (((i * Hh) + h) * 8 + js) * 2;
                g_ms[msb] = m;
                g_ms[msb + 1] = s;
            }
        }
    }
    __syncthreads();

    int jh = tid >> 7, rem = tid & 127, ht = rem >> 5, zz = rem & 31;
    float a3[3][4];
    #pragma unroll
    for (int b = 0; b < 3; b++)
        #pragma unroll
        for (int a = 0; a < 4; a++) a3[b][a] = 0.f;
    const float* E0 = &lS[(ht * 3 + 0) * 64 + jh * 32];
    const float* E1 = &lS[(ht * 3 + 1) * 64 + jh * 32];
    const float* E2 = &lS[(ht * 3 + 2) * 64 + jh * 32];
    const float* pb = &pairS[jh * 32 * 132];
    #pragma unroll 8
    for (int j = 0; j < 32; j++) {
        float4 p = *(const float4*)&pb[j * 132 + zz * 4];
        float v0 = E0[j], v1 = E1[j], v2 = E2[j];
        a3[0][0] += v0 * p.x; a3[0][1] += v0 * p.y; a3[0][2] += v0 * p.z; a3[0][3] += v0 * p.w;
        a3[1][0] += v1 * p.x; a3[1][1] += v1 * p.y; a3[1][2] += v1 * p.z; a3[1][3] += v1 * p.w;
        a3[2][0] += v2 * p.x; a3[2][1] += v2 * p.y; a3[2][2] += v2 * p.z; a3[2][3] += v2 * p.w;
    }
    if (jh == 1) {
        float* c = &comb[rem * 13];
        #pragma unroll
        for (int b = 0; b < 3; b++)
            #pragma unroll
            for (int a = 0; a < 4; a++) c[b * 4 + a] = a3[b][a];
    }
    __syncthreads();
    if (jh == 0) {
        const float* c = &comb[rem * 13];
        __nv_bfloat16* dst = &g_opP[((size_t)js * Nn + i) * (Hh * CZd)];
        #pragma unroll
        for (int b = 0; b < 3; b++) {
            float x0 = a3[b][0] + c[b * 4 + 0];
            float x1 = a3[b][1] + c[b * 4 + 1];
            float x2 = a3[b][2] + c[b * 4 + 2];
            float x3 = a3[b][3] + c[b * 4 + 3];
            __nv_bfloat162 p0 = __floats2bfloat162_rn(x0, x1);
            __nv_bfloat162 p1 = __floats2bfloat162_rn(x2, x3);
            *(__nv_bfloat162*)&dst[(ht * 3 + b) * CZd + zz * 4]     = p0;
            *(__nv_bfloat162*)&dst[(ht * 3 + b) * CZd + zz * 4 + 2] = p1;
        }
    }
}

// ---------------- o_v & o_pt: 4-way j-split partials, inline fct ----------------
__global__ void ov_k() {
    __shared__ float As[2][32 * 36];
    __shared__ float Bs[2][32 * 48];
    __shared__ float fS[32 * 8];
    int i0 = blockIdx.x * 32, h = blockIdx.y, jp = blockIdx.z;
    int tid = threadIdx.x;
    int tr = tid / 16, tc = tid % 16;
    if (tid < 32) {
        int row = tid;
        float mv[8], sv[8];
        float mg = -1e30f;
        #pragma unroll
        for (int k = 0; k < 8; k++) {
            int b = (((i0 + row) * Hh + h) * 8 + k) * 2;
            mv[k] = g_ms[b]; sv[k] = g_ms[b + 1];
            mg = fmaxf(mg, mv[k]);
        }
        float sg = 0.f;
        #pragma unroll
        for (int k = 0; k < 8; k++) sg += sv[k] * __expf(mv[k] - mg);
        float inv = 1.f / sg;
        #pragma unroll
        for (int k = 0; k < 8; k++) fS[row * 8 + k] = __expf(mv[k] - mg) * inv;
    }
    float acc[2][3];
    #pragma unroll
    for (int a = 0; a < 2; a++)
        #pragma unroll
        for (int b = 0; b < 3; b++) acc[a][b] = 0.f;

    auto loadA = [&](int c, int buf) {
        int j0 = (jp * 4 + c) * 32;
        int row = tid >> 3, q = tid & 7;
        cp16(&As[buf][row * 36 + q * 4],
             &g_logits[((size_t)(i0 + row) * Hh + h) * Nn + j0 + q * 4]);
    };
    auto loadB = [&](int c, int buf) {
        int j0 = (jp * 4 + c) * 32;
        for (int t = tid; t < 384; t += 256) {
            int row = t / 12, q = t % 12;
            cp16(&Bs[buf][row * 48 + q * 4], &g_B2[(size_t)(j0 + row) * 576 + h * 48 + q * 4]);
        }
    };
    loadA(0, 0); loadB(0, 0); cp_commit();
    for (int c = 0; c < 4; c++) {
        int buf = c & 1;
        if (c + 1 < 4) {
            loadA(c + 1, buf ^ 1); loadB(c + 1, buf ^ 1); cp_commit();
            cp_wait<1>();
        } else cp_wait<0>();
        __syncthreads();
        float pacc[2][3];
        #pragma unroll
        for (int a = 0; a < 2; a++)
            #pragma unroll
            for (int b = 0; b < 3; b++) pacc[a][b] = 0.f;
        #pragma unroll 8
        for (int jl = 0; jl < 32; jl++) {
            float ra[2], rb[3];
            #pragma unroll
            for (int a = 0; a < 2; a++) ra[a] = As[buf][(tr * 2 + a) * 36 + jl];
            #pragma unroll
            for (int b = 0; b < 3; b++) rb[b] = Bs[buf][jl * 48 + tc * 3 + b];
            #pragma unroll
            for (int a = 0; a < 2; a++)
                #pragma unroll
                for (int b = 0; b < 3; b++) pacc[a][b] += ra[a] * rb[b];
        }
        int js = (jp * 4 + c) >> 1;
        #pragma unroll
        for (int a = 0; a < 2; a++) {
            float f = fS[(tr * 2 + a) * 8 + js];
            #pragma unroll
            for (int b = 0; b < 3; b++) acc[a][b] += f * pacc[a][b];
        }
        __syncthreads();
    }
    float* dst = &g_ovP[((size_t)jp * Nn) * (Hh * 48)];
    #pragma unroll
    for (int a = 0; a < 2; a++) {
        int i = i0 + tr * 2 + a;
        #pragma unroll
        for (int b = 0; b < 3; b++) {
            int c = tc * 3 + b;
            dst[(size_t)i * (Hh * 48) + h * 48 + c] = acc[a][b];
        }
    }
}

// ---------------- megacombine: fct + o_pair + ov-routing + post_pt ----------------
__global__ void megacombine_k(const float* __restrict__ rot, const float* __restrict__ trans) {
    __shared__ float fctS[96];
    int i = blockIdx.x, tid = threadIdx.x;
    if (tid < 96) {
        int h = tid >> 3, js = tid & 7;
        float mv[8], sv[8];
        float mg = -1e30f;
        #pragma unroll
        for (int k = 0; k < 8; k++) {
            int b = ((i * Hh + h) * 8 + k) * 2;
            mv[k] = g_ms[b]; sv[k] = g_ms[b + 1];
            mg = fmaxf(mg, mv[k]);
        }
        float sg = 0.f;
        #pragma unroll
        for (int k = 0; k < 8; k++) sg += sv[k] * __expf(mv[k] - mg);
        fctS[tid] = __expf(mv[js] - mg) / sg;
    }
    __syncthreads();
    // o_pair from bf16 partials
    const size_t S = (size_t)Nn * Hh * CZd;
    for (int c = tid; c < Hh * CZd; c += 256) {
        int h = c >> 7;
        float s = 0.f;
        #pragma unroll
        for (int js = 0; js < 8; js++)
            s += fctS[h * 8 + js] * __bfloat162float(g_opP[js * S + (size_t)i * (Hh * CZd) + c]);
        g_concat[(size_t)i * OUTD + 576 + c] = s;
    }
    // ov-routing + post_pt
    const size_t S2 = (size_t)Nn * Hh * 48;
    const size_t ibase = (size_t)i * (Hh * 48);
    for (int t = tid; t < 192; t += 256) {
        int h = t >> 4, c = t & 15;
        size_t base = ibase + h * 48 + c;
        float s = g_ovP[base] + g_ovP[S2 + base] + g_ovP[2 * S2 + base] + g_ovP[3 * S2 + base];
        g_concat[(size_t)i * OUTD + h * Cc + c] = s;
    }
    if (tid < 96) {
        int t = tid;
        float pt[3];
        #pragma unroll
        for (int a = 0; a < 3; a++) {
            size_t base = ibase + (t >> 3) * 48 + 16 + (t & 7) * 3 + a;
            pt[a] = g_ovP[base] + g_ovP[S2 + base] + g_ovP[2 * S2 + base] + g_ovP[3 * S2 + base];
        }
        float b0 = pt[0] - trans[i * 3 + 0];
        float b1 = pt[1] - trans[i * 3 + 1];
        float b2 = pt[2] - trans[i * 3 + 2];
        float l0 = rot[i * 9 + 0] * b0 + rot[i * 9 + 3] * b1 + rot[i * 9 + 6] * b2;
        float l1 = rot[i * 9 + 1] * b0 + rot[i * 9 + 4] * b1 + rot[i * 9 + 7] * b2;
        float l2 = rot[i * 9 + 2] * b0 + rot[i * 9 + 5] * b1 + rot[i * 9 + 8] * b2;
        float* crow = &g_concat[(size_t)i * OUTD];
        crow[192 + t * 3 + 0] = l0;
        crow[192 + t * 3 + 1] = l1;
        crow[192 + t * 3 + 2] = l2;
        crow[480 + t] = sqrtf(l0 * l0 + l1 * l1 + l2 * l2 + 1e-8f);
    }
}

// ---------------- layer norms ----------------
__device__ __forceinline__ float blockSum384(float v, float* red) {
    int tid = threadIdx.x;
    red[tid] = v;
    if (tid < 128) red[384 + tid] = 0.f;
    __syncthreads();
    for (int s = 256; s > 0; s >>= 1) {
        if (tid < s) red[tid] += red[tid + s];
        __syncthreads();
    }
    float r = red[0];
    __syncthreads();
    return r;
}

__global__ void ln1_k(const float* __restrict__ single_in, const float* __restrict__ bo,
                      const float* __restrict__ g, const float* __restrict__ b) {
    __shared__ float red[512];
    int row = blockIdx.x, tid = threadIdx.x;
    float x = single_in[row * CSd + tid] + bo[tid];
    #pragma unroll
    for (int z = 0; z < 6; z++) x += g_wop[(size_t)z * Nn * CSd + row * CSd + tid];
    float mean = blockSum384(x, red) * (1.f / CSd);
    float dx = x - mean;
    float var = blockSum384(dx * dx, red) * (1.f / CSd);
    g_s1[row * CSd + tid] = dx * rsqrtf(var + 1e-5f) * g[tid] + b[tid];
}

// ---------------- ln2 + backbone update, fused ----------------
__global__ void ln2_update_k(const float* __restrict__ g, const float* __restrict__ bb,
                             const float* __restrict__ rot, const float* __restrict__ trans,
                             const float* __restrict__ Wbu, const float* __restrict__ bbu,
                             float* __restrict__ out) {
    __shared__ float red[512];
    __shared__ float yS[384];
    int row = blockIdx.x, tid = threadIdx.x;
    float x = g_s1[row * CSd + tid] + g_h3[row * CSd + tid];
    float mean = blockSum384(x, red) * (1.f / CSd);
    float dx = x - mean;
    float var = blockSum384(dx * dx, red) * (1.f / CSd);
    float y = dx * rsqrtf(var + 1e-5f) * g[tid] + bb[tid];
    out[row * CSd + tid] = y;
    yS[tid] = y;
    __syncthreads();
    if (tid >= 32) return;
    int lane = tid;
    float u[6] = {0, 0, 0, 0, 0, 0};
    for (int s = lane; s < CSd; s += 32) {
        float xv = yS[s];
        #pragma unroll
        for (int j = 0; j < 6; j++) u[j] += xv * Wbu[s * 6 + j];
    }
    #pragma unroll
    for (int j = 0; j < 6; j++)
        #pragma unroll
        for (int off = 16; off; off >>= 1) u[j] += __shfl_xor_sync(0xffffffffu, u[j], off);
    if (lane != 0) return;
    int n = row;
    #pragma unroll
    for (int j = 0; j < 6; j++) u[j] += bbu[j];
    float b = u[0], c = u[1], d = u[2];
    float inq = rsqrtf(1.f + b * b + c * c + d * d);
    float a = inq; b *= inq; c *= inq; d *= inq;
    float R[9] = {
        a*a + b*b - c*c - d*d, 2.f*(b*c - a*d),       2.f*(b*d + a*c),
        2.f*(b*c + a*d),       a*a - b*b + c*c - d*d, 2.f*(c*d - a*b),
        2.f*(b*d - a*c),       2.f*(c*d + a*b),       a*a - b*b - c*c + d*d };
    float rn[9];
    #pragma unroll
    for (int aa = 0; aa < 3; aa++)
        #pragma unroll
        for (int cc = 0; cc < 3; cc++) {
            float s2 = 0.f;
            #pragma unroll
            for (int bx = 0; bx < 3; bx++) s2 += rot[n * 9 + aa * 3 + bx] * R[bx * 3 + cc];
            rn[aa * 3 + cc] = s2;
        }
    float t0 = u[3], t1 = u[4], t2 = u[5];
    float tn[3];
    #pragma unroll
    for (int aa = 0; aa < 3; aa++)
        tn[aa] = rot[n * 9 + aa * 3 + 0] * t0 + rot[n * 9 + aa * 3 + 1] * t1 +
                 rot[n * 9 + aa * 3 + 2] * t2 + trans[n * 3 + aa];
    #pragma unroll
    for (int e = 0; e < 9; e++) { g_rotn[n * 9 + e] = rn[e]; out[Nn * CSd + n * 9 + e] = rn[e]; }
    #pragma unroll
    for (int e = 0; e < 3; e++) { g_trn[n * 3 + e] = tn[e]; out[Nn * CSd + Nn * 9 + n * 3 + e] = tn[e]; }
}

// ---------------- loss ----------------
__global__ void loss_part_k(const float* __restrict__ rt, const float* __restrict__ tt) {
    int i = blockIdx.x, tid = threadIdx.x;
    __shared__ float red[256];
    float rn[9], rte[9], tni[3], tti[3];
    #pragma unroll
    for (int e = 0; e < 9; e++) { rn[e] = g_rotn[i * 9 + e]; rte[e] = rt[i * 9 + e]; }
    #pragma unroll
    for (int e = 0; e < 3; e++) { tni[e] = g_trn[i * 3 + e]; tti[e] = tt[i * 3 + e]; }
    float s = 0.f;
    for (int j = tid; j < Nn; j += 256) {
        float db0 = g_trn[j * 3 + 0] - tni[0];
        float db1 = g_trn[j * 3 + 1] - tni[1];
        float db2 = g_trn[j * 3 + 2] - tni[2];
        float dp0 = rn[0] * db0 + rn[3] * db1 + rn[6] * db2;
        float dp1 = rn[1] * db0 + rn[4] * db1 + rn[7] * db2;
        float dp2 = rn[2] * db0 + rn[5] * db1 + rn[8] * db2;
        float eb0 = tt[j * 3 + 0] - tti[0];
        float eb1 = tt[j * 3 + 1] - tti[1];
        float eb2 = tt[j * 3 + 2] - tti[2];
        float dt0 = rte[0] * eb0 + rte[3] * eb1 + rte[6] * eb2;
        float dt1 = rte[1] * eb0 + rte[4] * eb1 + rte[7] * eb2;
        float dt2 = rte[2] * eb0 + rte[5] * eb1 + rte[8] * eb2;
        float d0 = dp0 - dt0, d1 = dp1 - dt1, d2 = dp2 - dt2;
        float dd = sqrtf(d0 * d0 + d1 * d1 + d2 * d2 + 1e-12f);
        s += fminf(dd, 10.f);
    }
    red[tid] = s; __syncthreads();
    for (int st = 128; st > 0; st >>= 1) {
        if (tid < st) red[tid] += red[tid + st];
        __syncthreads();
    }
    if (tid == 0) g_partial[i] = red[0];
}

__global__ void loss_final_k(float* __restrict__ out) {
    __shared__ float red[512];
    int tid = threadIdx.x;
    red[tid] = g_partial[tid];
    __syncthreads();
    for (int s = 256; s > 0; s >>= 1) {
        if (tid < s) red[tid] += red[tid + s];
        __syncthreads();
    }
    if (tid == 0)
        out[Nn * CSd + Nn * 9 + Nn * 3] = red[0] / ((float)Nn * (float)Nn) * 0.1f;
}

// ---------------- host ----------------
template <typename T>
static float* symaddr(T& sym) {
    void* p = nullptr;
    cudaGetSymbolAddress(&p, sym);
    return (float*)p;
}

extern "C" void kernel_launch(void* const* d_in, const int* in_sizes, int n_in,
                              void* d_out, int out_size) {
    const float* single      = (const float*)d_in[0];
    const float* pair        = (const float*)d_in[1];
    const float* rot         = (const float*)d_in[2];
    const float* trans       = (const float*)d_in[3];
    const float* rot_truth   = (const float*)d_in[4];
    const float* trans_truth = (const float*)d_in[5];
    const float* Wq  = (const float*)d_in[6];
    const float* Wk  = (const float*)d_in[7];
    const float* Wv  = (const float*)d_in[8];
    const float* Wqp = (const float*)d_in[9];
    const float* Wkp = (const float*)d_in[10];
    const float* Wvp = (const float*)d_in[11];
    const float* Wb  = (const float*)d_in[12];
    const float* Wo  = (const float*)d_in[13];
    const float* bo  = (const float*)d_in[14];
    const float* gamma_raw = (const float*)d_in[15];
    const float* ln1_g = (const float*)d_in[16];
    const float* ln1_b = (const float*)d_in[17];
    const float* ln2_g = (const float*)d_in[18];
    const float* ln2_b = (const float*)d_in[19];
    const float* W1 = (const float*)d_in[20];
    const float* b1 = (const float*)d_in[21];
    const float* W2 = (const float*)d_in[22];
    const float* b2 = (const float*)d_in[23];
    const float* W3 = (const float*)d_in[24];
    const float* b3 = (const float*)d_in[25];
    const float* Wbu = (const float*)d_in[26];
    const float* bbu = (const float*)d_in[27];
    float* out = (float*)d_out;

    float* pProj   = symaddr(g_proj);
    float* pConcat = symaddr(g_concat);
    float* pS1     = symaddr(g_s1);
    float* pH1     = symaddr(g_h1);
    float* pH2     = symaddr(g_h2);
    float* pH3     = symaddr(g_h3);

    const int FLASH2_SMEM = (8448 + 1584 + 768 + 3200) * 4;   // 56000
    cudaFuncSetAttribute(flash2_k, cudaFuncAttributeMaxDynamicSharedMemorySize, FLASH2_SMEM);

    proj_gemm_k<<<dim3(PROJD/64, Nn/64), 256>>>(single, Wq, Wk, Wv, Wqp, Wkp, Wvp, pProj);
    prep_k<<<Nn, 128>>>(rot, trans, gamma_raw);
    core_k<<<dim3(Nn/128, Nn/64, Hh), 256>>>();

    flash2_k<<<dim3(Nn, 8), 256, FLASH2_SMEM>>>(pair, Wb);
    ov_k<<<dim3(Nn/32, Hh, 4), 256>>>();
    megacombine_k<<<Nn, 256>>>(rot, trans);

    sgemm_k<64,64,16,4,4,false,false,true><<<dim3(CSd/64, Nn/64, 6), 256>>>(
        pConcat, Wo, nullptr, symaddr(g_wop), Nn, CSd, OUTD, OUTD/6);
    ln1_k<<<Nn, CSd>>>(single, bo, ln1_g, ln1_b);

    sgemm_k<32,32,16,2,2,true,true,false><<<dim3(CSd/32, Nn/32, 1), 256>>>(
        pS1, W1, b1, pH1, Nn, CSd, CSd, CSd);
    sgemm_k<32,32,16,2,2,true,true,false><<<dim3(CSd/32, Nn/32, 1), 256>>>(
        pH1, W2, b2, pH2, Nn, CSd, CSd, CSd);
    sgemm_k<32,32,16,2,2,true,false,false><<<dim3(CSd/32, Nn/32, 1), 256>>>(
        pH2, W3, b3, pH3, Nn, CSd, CSd, CSd);
    ln2_update_k<<<Nn, CSd>>>(ln2_g, ln2_b, rot, trans, Wbu, bbu, out);

    loss_part_k<<<Nn, 256>>>(rot_truth, trans_truth);
    loss_final_k<<<1, 512>>>(out);
}